// round 1
// baseline (speedup 1.0000x reference)
#include <cuda_runtime.h>

// Problem constants
static constexpr int B_ = 4;
static constexpr int C_ = 256;
static constexpr int N_ = 32768;     // 32*32*32
static constexpr int H_ = 8;
static constexpr int G_ = 4;
static constexpr int CPG = C_ / G_;  // 64
static constexpr long GRP_ELEMS = (long)CPG * N_;  // 2097152

// -------- device scratch (no allocations allowed) --------
__device__ float  d_qkv[(long)B_ * 768 * N_];     // 384 MB
__device__ float2 d_part[16 * 64];                // GN partial (sum, sumsq)
__device__ float  d_scale[B_ * C_];
__device__ float  d_shift[B_ * C_];
__device__ float  d_Wp[B_ * 768 * C_];            // per-batch GN-folded qkv weight
__device__ float  d_biasp[B_ * 768];
__device__ float  d_simpart[B_ * H_ * 16 * 1024];
__device__ float  d_sim[B_ * H_ * 1024];
__device__ float  d_W2[B_ * C_ * C_];             // per-batch fused sim+out_proj weight

// ============================================================
// K1: GroupNorm partial stats. grid (64, 16), 256 threads.
// Each (b,g) group is a contiguous 2M-float region of x.
// ============================================================
__global__ void gn_stats1(const float* __restrict__ x) {
    int bg  = blockIdx.y;
    int blk = blockIdx.x;
    const float* p = x + (long)bg * GRP_ELEMS + (long)blk * 32768;
    int tid = threadIdx.x;
    float s = 0.f, ss = 0.f;
    for (int i = tid * 4; i < 32768; i += 1024) {
        float4 v = *(const float4*)&p[i];
        s  += v.x + v.y + v.z + v.w;
        ss += v.x*v.x + v.y*v.y + v.z*v.z + v.w*v.w;
    }
    __shared__ float rs[256], rss[256];
    rs[tid] = s; rss[tid] = ss;
    __syncthreads();
    for (int st = 128; st > 0; st >>= 1) {
        if (tid < st) { rs[tid] += rs[tid+st]; rss[tid] += rss[tid+st]; }
        __syncthreads();
    }
    if (tid == 0) d_part[bg * 64 + blk] = make_float2(rs[0], rss[0]);
}

// ============================================================
// K2: finalize stats -> per-channel scale/shift. grid 16, 64 threads.
// ============================================================
__global__ void gn_stats2(const float* __restrict__ gnw, const float* __restrict__ gnb) {
    int bg = blockIdx.x;
    int tid = threadIdx.x;
    __shared__ float rs[64], rss[64];
    float2 p = d_part[bg * 64 + tid];
    rs[tid] = p.x; rss[tid] = p.y;
    __syncthreads();
    for (int st = 32; st > 0; st >>= 1) {
        if (tid < st) { rs[tid] += rs[tid+st]; rss[tid] += rss[tid+st]; }
        __syncthreads();
    }
    float inv_cnt = 1.0f / (float)GRP_ELEMS;
    float mean = rs[0] * inv_cnt;
    float var  = rss[0] * inv_cnt - mean * mean;
    float rstd = rsqrtf(var + 1e-5f);
    int b = bg >> 2, g = bg & 3;
    int c = g * CPG + tid;
    float sc = rstd * gnw[c];
    d_scale[b * C_ + c] = sc;
    d_shift[b * C_ + c] = gnb[c] - mean * sc;
}

// ============================================================
// K3: build per-batch GN-folded qkv weight + bias. grid (768,4), 256 thr.
// ============================================================
__global__ void build_wp(const float* __restrict__ W) {
    int o = blockIdx.x, b = blockIdx.y, c = threadIdx.x;
    float w = W[o * C_ + c];
    d_Wp[((long)b * 768 + o) * C_ + c] = w * d_scale[b * C_ + c];
    __shared__ float red[256];
    red[c] = w * d_shift[b * C_ + c];
    __syncthreads();
    for (int st = 128; st > 0; st >>= 1) {
        if (c < st) red[c] += red[c + st];
        __syncthreads();
    }
    if (c == 0) d_biasp[b * 768 + o] = red[0];
}

// ============================================================
// SGEMM: C[b] = A[b] (MxK) @ Bm[b] (KxN) + bias + optional residual.
// 128x128 tile, BK=8, 256 threads, 8x8 per thread.
// ============================================================
__global__ void __launch_bounds__(256, 2) sgemm128(
    const float* __restrict__ A, const float* __restrict__ Bm,
    float* __restrict__ C, const float* __restrict__ bias,
    const float* __restrict__ resid,
    int M, int N, int K,
    long sA, long sB, long sC, int sBias)
{
    __shared__ float As[8][128];
    __shared__ float Bs[8][128];
    int bz = blockIdx.z;
    A  += (long)bz * sA;
    Bm += (long)bz * sB;
    C  += (long)bz * sC;
    const float* biasp = bias + (long)bz * sBias;
    const float* rp = resid ? resid + (long)bz * sC : nullptr;

    int tid = threadIdx.x;
    int bx = blockIdx.x, by = blockIdx.y;
    int rowA = tid >> 1;
    int colA = (tid & 1) * 4;
    int rowB = tid >> 5;
    int colB = (tid & 31) * 4;

    const float* Aptr = A + (long)(by * 128 + rowA) * K + colA;
    const float* Bptr = Bm + (long)rowB * N + bx * 128 + colB;

    int tr = (tid >> 4) * 8;
    int tc = (tid & 15) * 8;

    float acc[8][8];
    #pragma unroll
    for (int i = 0; i < 8; i++)
        #pragma unroll
        for (int j = 0; j < 8; j++) acc[i][j] = 0.f;

    for (int k0 = 0; k0 < K; k0 += 8) {
        float4 a4 = *(const float4*)Aptr;
        As[colA + 0][rowA] = a4.x;
        As[colA + 1][rowA] = a4.y;
        As[colA + 2][rowA] = a4.z;
        As[colA + 3][rowA] = a4.w;
        *(float4*)&Bs[rowB][colB] = *(const float4*)Bptr;
        __syncthreads();
        Aptr += 8;
        Bptr += (long)8 * N;
        #pragma unroll
        for (int k = 0; k < 8; k++) {
            float4 ra0 = *(const float4*)&As[k][tr];
            float4 ra1 = *(const float4*)&As[k][tr + 4];
            float4 rb0 = *(const float4*)&Bs[k][tc];
            float4 rb1 = *(const float4*)&Bs[k][tc + 4];
            float ra[8] = {ra0.x, ra0.y, ra0.z, ra0.w, ra1.x, ra1.y, ra1.z, ra1.w};
            float rb[8] = {rb0.x, rb0.y, rb0.z, rb0.w, rb1.x, rb1.y, rb1.z, rb1.w};
            #pragma unroll
            for (int i = 0; i < 8; i++)
                #pragma unroll
                for (int j = 0; j < 8; j++)
                    acc[i][j] += ra[i] * rb[j];
        }
        __syncthreads();
    }

    // epilogue
    #pragma unroll
    for (int i = 0; i < 8; i++) {
        int row = by * 128 + tr + i;
        float bv = biasp[row];
        long base = (long)row * N + bx * 128 + tc;
        float4 r0 = make_float4(0.f,0.f,0.f,0.f), r1 = r0;
        if (rp) {
            r0 = *(const float4*)&rp[base];
            r1 = *(const float4*)&rp[base + 4];
        }
        float4 o0, o1;
        o0.x = acc[i][0] + bv + r0.x; o0.y = acc[i][1] + bv + r0.y;
        o0.z = acc[i][2] + bv + r0.z; o0.w = acc[i][3] + bv + r0.w;
        o1.x = acc[i][4] + bv + r1.x; o1.y = acc[i][5] + bv + r1.y;
        o1.z = acc[i][6] + bv + r1.z; o1.w = acc[i][7] + bv + r1.w;
        *(float4*)&C[base]     = o0;
        *(float4*)&C[base + 4] = o1;
    }
}

// ============================================================
// K5: softmax over N for each k-row (in place). grid 1024, 256 thr.
// ============================================================
__global__ void softmax_k() {
    int blk = blockIdx.x;
    int b = blk >> 8, r = blk & 255;
    float* row = d_qkv + ((long)b * 768 + 256 + r) * N_;
    int tid = threadIdx.x;
    __shared__ float red[256];

    float m = -1e30f;
    for (int i = tid * 4; i < N_; i += 1024) {
        float4 v = *(const float4*)&row[i];
        m = fmaxf(m, fmaxf(fmaxf(v.x, v.y), fmaxf(v.z, v.w)));
    }
    red[tid] = m; __syncthreads();
    for (int st = 128; st > 0; st >>= 1) {
        if (tid < st) red[tid] = fmaxf(red[tid], red[tid + st]);
        __syncthreads();
    }
    m = red[0];
    __syncthreads();

    float sum = 0.f;
    for (int i = tid * 4; i < N_; i += 1024) {
        float4 v = *(const float4*)&row[i];
        sum += __expf(v.x - m) + __expf(v.y - m) + __expf(v.z - m) + __expf(v.w - m);
    }
    red[tid] = sum; __syncthreads();
    for (int st = 128; st > 0; st >>= 1) {
        if (tid < st) red[tid] += red[tid + st];
        __syncthreads();
    }
    float inv = 1.0f / red[0];

    for (int i = tid * 4; i < N_; i += 1024) {
        float4 v = *(const float4*)&row[i];
        v.x = __expf(v.x - m) * inv;
        v.y = __expf(v.y - m) * inv;
        v.z = __expf(v.z - m) * inv;
        v.w = __expf(v.w - m) * inv;
        *(float4*)&row[i] = v;
    }
}

// ============================================================
// K6: sim partial: sim[b,h,d,e] = sum_n k[d,n]*v[e,n], split over n.
// grid (16 splits, 32 bh), 256 threads, 2x2 register tile.
// ============================================================
__global__ void __launch_bounds__(256) sim_partial() {
    const int PAD = 68;
    __shared__ float ks[32][PAD], vs[32][PAD];
    int sp = blockIdx.x, bh = blockIdx.y;
    int b = bh >> 3, h = bh & 7;
    const float* kp = d_qkv + ((long)b * 768 + 256 + h * 32) * N_;
    const float* vp = d_qkv + ((long)b * 768 + 512 + h * 32) * N_;
    int tid = threadIdx.x;
    int d2 = (tid >> 4) * 2;
    int e2 = (tid & 15) * 2;
    float a00 = 0.f, a01 = 0.f, a10 = 0.f, a11 = 0.f;

    int nbeg = sp * 2048;
    for (int n0 = nbeg; n0 < nbeg + 2048; n0 += 64) {
        __syncthreads();
        for (int l = tid; l < 512; l += 256) {
            int dd = l >> 4, jj = (l & 15) * 4;
            *(float4*)&ks[dd][jj] = *(const float4*)&kp[(long)dd * N_ + n0 + jj];
            *(float4*)&vs[dd][jj] = *(const float4*)&vp[(long)dd * N_ + n0 + jj];
        }
        __syncthreads();
        #pragma unroll
        for (int j = 0; j < 64; j += 4) {
            float4 x0 = *(const float4*)&ks[d2][j];
            float4 x1 = *(const float4*)&ks[d2 + 1][j];
            float4 y0 = *(const float4*)&vs[e2][j];
            float4 y1 = *(const float4*)&vs[e2 + 1][j];
            a00 += x0.x*y0.x + x0.y*y0.y + x0.z*y0.z + x0.w*y0.w;
            a01 += x0.x*y1.x + x0.y*y1.y + x0.z*y1.z + x0.w*y1.w;
            a10 += x1.x*y0.x + x1.y*y0.y + x1.z*y0.z + x1.w*y0.w;
            a11 += x1.x*y1.x + x1.y*y1.y + x1.z*y1.z + x1.w*y1.w;
        }
    }
    float* out = d_simpart + ((long)(bh * 16 + sp)) * 1024;
    out[(d2 + 0) * 32 + e2 + 0] = a00;
    out[(d2 + 0) * 32 + e2 + 1] = a01;
    out[(d2 + 1) * 32 + e2 + 0] = a10;
    out[(d2 + 1) * 32 + e2 + 1] = a11;
}

// K7: reduce sim splits. grid 32, 1024 threads.
__global__ void sim_reduce() {
    int bh = blockIdx.x, i = threadIdx.x;
    float s = 0.f;
    #pragma unroll
    for (int sp = 0; sp < 16; sp++)
        s += d_simpart[(long)(bh * 16 + sp) * 1024 + i];
    d_sim[bh * 1024 + i] = s;
}

// ============================================================
// K8: fuse sim into out_weight: W2[b,o,h*32+d] = sum_e OW[o,h*32+e]*sim[b,h,d,e]
// grid (256, 4), 256 threads.
// ============================================================
__global__ void build_w2(const float* __restrict__ OW) {
    int o = blockIdx.x, b = blockIdx.y, cp = threadIdx.x;
    int h = cp >> 5, d = cp & 31;
    const float* simp = d_sim + ((long)((b * 8 + h) * 32 + d)) * 32;
    const float* owp  = OW + o * C_ + h * 32;
    float s = 0.f;
    #pragma unroll
    for (int e = 0; e < 32; e++) s += owp[e] * simp[e];
    d_W2[((long)b * C_ + o) * C_ + cp] = s;
}

// ============================================================
// host launch
// ============================================================
extern "C" void kernel_launch(void* const* d_in, const int* in_sizes, int n_in,
                              void* d_out, int out_size) {
    const float* x    = (const float*)d_in[0];
    const float* gnw  = (const float*)d_in[1];
    const float* gnb  = (const float*)d_in[2];
    const float* qkvW = (const float*)d_in[3];
    const float* ow   = (const float*)d_in[4];
    const float* ob   = (const float*)d_in[5];
    float* out = (float*)d_out;

    float *pWp, *pQkv, *pBiasp, *pW2;
    cudaGetSymbolAddress((void**)&pWp,    d_Wp);
    cudaGetSymbolAddress((void**)&pQkv,   d_qkv);
    cudaGetSymbolAddress((void**)&pBiasp, d_biasp);
    cudaGetSymbolAddress((void**)&pW2,    d_W2);

    gn_stats1<<<dim3(64, 16), 256>>>(x);
    gn_stats2<<<16, 64>>>(gnw, gnb);
    build_wp<<<dim3(768, 4), 256>>>(qkvW);

    // qkv[b] = W'[b](768x256) @ x[b](256xN) + bias'[b]
    sgemm128<<<dim3(256, 6, 4), 256>>>(pWp, x, pQkv, pBiasp, nullptr,
                                       768, N_, 256,
                                       (long)768 * 256, (long)256 * N_, (long)768 * N_, 768);

    softmax_k<<<1024, 256>>>();
    sim_partial<<<dim3(16, 32), 256>>>();
    sim_reduce<<<32, 1024>>>();
    build_w2<<<dim3(256, 4), 256>>>(ow);

    // out[b] = W2[b](256x256) @ q[b](256xN) + out_bias + x[b]
    sgemm128<<<dim3(256, 2, 4), 256>>>(pW2, pQkv, out, ob, x,
                                       256, N_, 256,
                                       (long)256 * 256, (long)768 * N_, (long)256 * N_, 0);
}

// round 3
// speedup vs baseline: 1.8016x; 1.8016x over previous
#include <cuda_runtime.h>
#include <cuda_bf16.h>
#include <cstdint>

// Problem constants
static constexpr int B_ = 4;
static constexpr int C_ = 256;
static constexpr int N_ = 32768;     // 32*32*32
static constexpr int H_ = 8;
static constexpr int CPG = 64;       // C_/NUM_GROUPS
static constexpr long GRP_ELEMS = (long)CPG * N_;  // 2097152

// ---------------- device scratch (no allocations allowed) ----------------
__device__ float d_q[(long)B_ * C_ * N_];          // 128 MB
__device__ float d_k[(long)B_ * C_ * N_];
__device__ float d_v[(long)B_ * C_ * N_];
__device__ __nv_bfloat16 d_xThi[(long)B_ * N_ * C_];   // xT [b][n][c]
__device__ __nv_bfloat16 d_xTlo[(long)B_ * N_ * C_];
__device__ __nv_bfloat16 d_qThi[(long)B_ * N_ * C_];
__device__ __nv_bfloat16 d_qTlo[(long)B_ * N_ * C_];
__device__ __nv_bfloat16 d_Wphi[B_ * 768 * C_];
__device__ __nv_bfloat16 d_Wplo[B_ * 768 * C_];
__device__ float d_biasp[B_ * 768];
__device__ __nv_bfloat16 d_W2hi[B_ * C_ * C_];
__device__ __nv_bfloat16 d_W2lo[B_ * C_ * C_];
__device__ float2 d_part[16 * 64];
__device__ float d_scale[B_ * C_];
__device__ float d_shift[B_ * C_];
__device__ float d_simpart[B_ * H_ * 16 * 1024];
__device__ float d_sim[B_ * H_ * 1024];

// ---------------- PTX helpers ----------------
__device__ __forceinline__ uint32_t smem_u32(const void* p) {
    uint32_t a;
    asm("{ .reg .u64 t; cvta.to.shared.u64 t, %1; cvt.u32.u64 %0, t; }" : "=r"(a) : "l"(p));
    return a;
}
#define CP16(dst, src) asm volatile("cp.async.ca.shared.global [%0], [%1], 16;" :: "r"(dst), "l"(src))
#define CP_COMMIT()    asm volatile("cp.async.commit_group;")
#define CP_WAIT1()     asm volatile("cp.async.wait_group 1;")

__device__ __forceinline__ void ldm4(uint32_t* r, uint32_t addr) {
    asm volatile("ldmatrix.sync.aligned.m8n8.x4.shared.b16 {%0,%1,%2,%3}, [%4];"
        : "=r"(r[0]), "=r"(r[1]), "=r"(r[2]), "=r"(r[3]) : "r"(addr));
}
__device__ __forceinline__ void ldm2(uint32_t* r, uint32_t addr) {
    asm volatile("ldmatrix.sync.aligned.m8n8.x2.shared.b16 {%0,%1}, [%2];"
        : "=r"(r[0]), "=r"(r[1]) : "r"(addr));
}
__device__ __forceinline__ void mma_bf16(float* d, const uint32_t* a, const uint32_t* b) {
    asm volatile(
        "mma.sync.aligned.m16n8k16.row.col.f32.bf16.bf16.f32 "
        "{%0,%1,%2,%3}, {%4,%5,%6,%7}, {%8,%9}, {%0,%1,%2,%3};"
        : "+f"(d[0]), "+f"(d[1]), "+f"(d[2]), "+f"(d[3])
        : "r"(a[0]), "r"(a[1]), "r"(a[2]), "r"(a[3]), "r"(b[0]), "r"(b[1]));
}

// ============================================================
// GroupNorm stats
// ============================================================
__global__ void gn_stats1(const float* __restrict__ x) {
    int bg = blockIdx.y, blk = blockIdx.x;
    const float* p = x + (long)bg * GRP_ELEMS + (long)blk * 32768;
    int tid = threadIdx.x;
    float s = 0.f, ss = 0.f;
    for (int i = tid * 4; i < 32768; i += 1024) {
        float4 v = *(const float4*)&p[i];
        s += v.x + v.y + v.z + v.w;
        ss += v.x * v.x + v.y * v.y + v.z * v.z + v.w * v.w;
    }
    __shared__ float rs[256], rss[256];
    rs[tid] = s; rss[tid] = ss;
    __syncthreads();
    for (int st = 128; st > 0; st >>= 1) {
        if (tid < st) { rs[tid] += rs[tid + st]; rss[tid] += rss[tid + st]; }
        __syncthreads();
    }
    if (tid == 0) d_part[bg * 64 + blk] = make_float2(rs[0], rss[0]);
}

__global__ void gn_stats2(const float* __restrict__ gnw, const float* __restrict__ gnb) {
    int bg = blockIdx.x, tid = threadIdx.x;
    __shared__ float rs[64], rss[64];
    float2 p = d_part[bg * 64 + tid];
    rs[tid] = p.x; rss[tid] = p.y;
    __syncthreads();
    for (int st = 32; st > 0; st >>= 1) {
        if (tid < st) { rs[tid] += rs[tid + st]; rss[tid] += rss[tid + st]; }
        __syncthreads();
    }
    float inv = 1.0f / (float)GRP_ELEMS;
    float mean = rs[0] * inv;
    float var = rss[0] * inv - mean * mean;
    float rstd = rsqrtf(var + 1e-5f);
    int b = bg >> 2, g = bg & 3;
    int c = g * CPG + tid;
    float sc = rstd * gnw[c];
    d_scale[b * C_ + c] = sc;
    d_shift[b * C_ + c] = gnb[c] - mean * sc;
}

// ============================================================
// GN-folded qkv weight (bf16 hi/lo) + folded bias
// ============================================================
__global__ void build_wp(const float* __restrict__ W) {
    int o = blockIdx.x, b = blockIdx.y, c = threadIdx.x;
    float w = W[o * C_ + c];
    float wp = w * d_scale[b * C_ + c];
    __nv_bfloat16 h = __float2bfloat16(wp);
    long idx = ((long)b * 768 + o) * C_ + c;
    d_Wphi[idx] = h;
    d_Wplo[idx] = __float2bfloat16(wp - __bfloat162float(h));
    __shared__ float red[256];
    red[c] = w * d_shift[b * C_ + c];
    __syncthreads();
    for (int st = 128; st > 0; st >>= 1) {
        if (c < st) red[c] += red[c + st];
        __syncthreads();
    }
    if (c == 0) d_biasp[b * 768 + o] = red[0];
}

// ============================================================
// Tiled transpose + bf16 hi/lo split: src [b][256][N] -> dst [b][N][256]
// ============================================================
__global__ void tconv(const float* __restrict__ src,
                      __nv_bfloat16* __restrict__ dhi, __nv_bfloat16* __restrict__ dlo) {
    __shared__ float t[32][33];
    int n0 = blockIdx.x * 32, c0 = blockIdx.y * 32, b = blockIdx.z;
    const float* s = src + (long)b * C_ * N_;
    int tx = threadIdx.x, ty = threadIdx.y;
    #pragma unroll
    for (int i = 0; i < 4; i++) {
        int c = c0 + ty + i * 8;
        t[ty + i * 8][tx] = s[(long)c * N_ + n0 + tx];
    }
    __syncthreads();
    __nv_bfloat16* ph = dhi + (long)b * N_ * C_;
    __nv_bfloat16* pl = dlo + (long)b * N_ * C_;
    #pragma unroll
    for (int i = 0; i < 4; i++) {
        int n = n0 + ty + i * 8;
        float v = t[tx][ty + i * 8];
        __nv_bfloat16 h = __float2bfloat16(v);
        ph[(long)n * C_ + c0 + tx] = h;
        pl[(long)n * C_ + c0 + tx] = __float2bfloat16(v - __bfloat162float(h));
    }
}

// ============================================================
// bf16 split GEMM via mma.sync: D[128x128] per CTA.
// A[M][256] (row-major, hi/lo), B = xT/qT [N][256] (row-major, hi/lo).
// D = Ahi*Bhi^T + Ahi*Blo^T + Alo*Bhi^T  (fp32 accum)
// Smem: padded rows of 80B (40 bf16), conflict-free ldmatrix.
// ============================================================
static constexpr int SKROW = 40;         // bf16 elems per smem row (32 + 8 pad)
static constexpr int TILE_BYTES = 128 * SKROW * 2;   // 10240 per matrix
static constexpr int STAGE_BYTES = 4 * TILE_BYTES;   // Ahi, Alo, Bhi, Blo
static constexpr int GEMM_SMEM = 2 * STAGE_BYTES;    // 81920

__device__ __forceinline__ void load_stage(
    uint32_t sbase, const __nv_bfloat16* Ah, const __nv_bfloat16* Al,
    const __nv_bfloat16* Bh, const __nv_bfloat16* Bl, int kt, int tid)
{
    int k0 = kt * 32;
    #pragma unroll
    for (int it = 0; it < 2; it++) {
        int i = tid + it * 256;
        int row = i >> 2, c = i & 3;
        uint32_t doff = row * (SKROW * 2) + c * 16;
        long goff = (long)row * 256 + k0 + c * 8;
        CP16(sbase + doff,                  Ah + goff);
        CP16(sbase + TILE_BYTES + doff,     Al + goff);
        CP16(sbase + 2 * TILE_BYTES + doff, Bh + goff);
        CP16(sbase + 3 * TILE_BYTES + doff, Bl + goff);
    }
}

template <int MODE>
__global__ void __launch_bounds__(256, 1) gemm_mma(
    const __nv_bfloat16* __restrict__ Ahi, const __nv_bfloat16* __restrict__ Alo,
    const __nv_bfloat16* __restrict__ Bhi, const __nv_bfloat16* __restrict__ Blo,
    const float* __restrict__ bias, const float* __restrict__ resid,
    float* __restrict__ outQ, float* __restrict__ outK, float* __restrict__ outV,
    float* __restrict__ outO, int Mtotal)
{
    extern __shared__ char smem[];
    uint32_t sb = smem_u32(smem);
    int tid = threadIdx.x;
    int warp = tid >> 5, lane = tid & 31;
    int wm = (warp >> 2) * 64;      // warp m offset in tile
    int wn = (warp & 3) * 32;       // warp n offset in tile
    int nt = blockIdx.x, mt = blockIdx.y, b = blockIdx.z;

    const __nv_bfloat16* Ah = Ahi + (long)b * Mtotal * 256 + (long)mt * 128 * 256;
    const __nv_bfloat16* Al = Alo + (long)b * Mtotal * 256 + (long)mt * 128 * 256;
    const __nv_bfloat16* Bh = Bhi + (long)b * N_ * 256 + (long)nt * 128 * 256;
    const __nv_bfloat16* Bl = Blo + (long)b * N_ * 256 + (long)nt * 128 * 256;

    float acc[4][4][4];
    #pragma unroll
    for (int i = 0; i < 4; i++)
        #pragma unroll
        for (int j = 0; j < 4; j++)
            #pragma unroll
            for (int e = 0; e < 4; e++) acc[i][j][e] = 0.f;

    load_stage(sb, Ah, Al, Bh, Bl, 0, tid); CP_COMMIT();
    load_stage(sb + STAGE_BYTES, Ah, Al, Bh, Bl, 1, tid); CP_COMMIT();

    // ldmatrix lane addressing (fixed per thread)
    int quad = lane >> 3, qr = lane & 7;
    int a_row = wm + (quad & 1) * 8 + qr;       // + mf*16
    int a_colb = (quad >> 1) * 16;              // + k16*32 (bytes)
    int bl8 = lane & 15;
    int b_row = wn + (bl8 & 7);                 // + nf*8
    int b_colb = (bl8 >> 3) * 16;               // + k16*32 (bytes)

    #pragma unroll 1
    for (int kt = 0; kt < 8; kt++) {
        CP_WAIT1();
        __syncthreads();
        uint32_t base = sb + (kt & 1) * STAGE_BYTES;
        uint32_t aHi = base, aLo = base + TILE_BYTES;
        uint32_t bHi = base + 2 * TILE_BYTES, bLo = base + 3 * TILE_BYTES;

        #pragma unroll
        for (int k16 = 0; k16 < 2; k16++) {
            uint32_t acol = a_colb + k16 * 32;
            uint32_t bcol = b_colb + k16 * 32;
            uint32_t ah[4][4], al[4][4], bh[4][2], bl_[4][2];
            #pragma unroll
            for (int mf = 0; mf < 4; mf++) {
                uint32_t ro = (a_row + mf * 16) * (SKROW * 2);
                ldm4(ah[mf], aHi + ro + acol);
                ldm4(al[mf], aLo + ro + acol);
            }
            #pragma unroll
            for (int nf = 0; nf < 4; nf++) {
                uint32_t ro = (b_row + nf * 8) * (SKROW * 2);
                ldm2(bh[nf], bHi + ro + bcol);
                ldm2(bl_[nf], bLo + ro + bcol);
            }
            #pragma unroll
            for (int mf = 0; mf < 4; mf++)
                #pragma unroll
                for (int nf = 0; nf < 4; nf++) {
                    mma_bf16(acc[mf][nf], ah[mf], bh[nf]);
                    mma_bf16(acc[mf][nf], ah[mf], bl_[nf]);
                    mma_bf16(acc[mf][nf], al[mf], bh[nf]);
                }
        }
        __syncthreads();
        if (kt + 2 < 8)
            load_stage(sb + (kt & 1) * STAGE_BYTES, Ah, Al, Bh, Bl, kt + 2, tid);
        CP_COMMIT();
    }
    asm volatile("cp.async.wait_group 0;");

    // ---- epilogue: d-frag (m16n8): d0,d1 -> (r, n), (r, n+1); d2,d3 -> (r+8, ...)
    #pragma unroll
    for (int mf = 0; mf < 4; mf++) {
        int r0 = mt * 128 + wm + mf * 16 + (lane >> 2);
        #pragma unroll
        for (int half = 0; half < 2; half++) {
            int mrow = r0 + half * 8;
            float bv;
            float* dst;
            const float* rp = nullptr;
            if (MODE == 1) {
                int sec = mrow >> 8, c = mrow & 255;
                bv = bias[b * 768 + mrow];
                dst = (sec == 0 ? outQ : (sec == 1 ? outK : outV)) + ((long)b * C_ + c) * N_;
            } else {
                bv = bias[mrow];
                long base = ((long)b * C_ + mrow) * N_;
                dst = outO + base;
                rp = resid + base;
            }
            #pragma unroll
            for (int nf = 0; nf < 4; nf++) {
                int n = nt * 128 + wn + nf * 8 + 2 * (lane & 3);
                float dA = acc[mf][nf][half * 2 + 0] + bv;
                float dB = acc[mf][nf][half * 2 + 1] + bv;
                if (MODE == 2) {
                    float2 rv = *(const float2*)&rp[n];
                    dA += rv.x; dB += rv.y;
                }
                float2 o; o.x = dA; o.y = dB;
                *(float2*)&dst[n] = o;
            }
        }
    }
}

// ============================================================
// softmax over N per k-row (in place on d_k)
// ============================================================
__global__ void softmax_k() {
    int blk = blockIdx.x;
    int b = blk >> 8, r = blk & 255;
    float* row = d_k + ((long)b * C_ + r) * N_;
    int tid = threadIdx.x;
    __shared__ float red[256];
    float m = -1e30f;
    for (int i = tid * 4; i < N_; i += 1024) {
        float4 v = *(const float4*)&row[i];
        m = fmaxf(m, fmaxf(fmaxf(v.x, v.y), fmaxf(v.z, v.w)));
    }
    red[tid] = m; __syncthreads();
    for (int st = 128; st > 0; st >>= 1) {
        if (tid < st) red[tid] = fmaxf(red[tid], red[tid + st]);
        __syncthreads();
    }
    m = red[0];
    __syncthreads();
    float sum = 0.f;
    for (int i = tid * 4; i < N_; i += 1024) {
        float4 v = *(const float4*)&row[i];
        sum += __expf(v.x - m) + __expf(v.y - m) + __expf(v.z - m) + __expf(v.w - m);
    }
    red[tid] = sum; __syncthreads();
    for (int st = 128; st > 0; st >>= 1) {
        if (tid < st) red[tid] += red[tid + st];
        __syncthreads();
    }
    float inv = 1.0f / red[0];
    for (int i = tid * 4; i < N_; i += 1024) {
        float4 v = *(const float4*)&row[i];
        v.x = __expf(v.x - m) * inv;
        v.y = __expf(v.y - m) * inv;
        v.z = __expf(v.z - m) * inv;
        v.w = __expf(v.w - m) * inv;
        *(float4*)&row[i] = v;
    }
}

// ============================================================
// sim[b,h,d,e] = sum_n k[d,n]*v[e,n] (split over n, then reduce)
// ============================================================
__global__ void __launch_bounds__(256) sim_partial() {
    const int PAD = 68;
    __shared__ float ks[32][PAD], vs[32][PAD];
    int sp = blockIdx.x, bh = blockIdx.y;
    int b = bh >> 3, h = bh & 7;
    const float* kp = d_k + ((long)b * C_ + h * 32) * N_;
    const float* vp = d_v + ((long)b * C_ + h * 32) * N_;
    int tid = threadIdx.x;
    int d2 = (tid >> 4) * 2, e2 = (tid & 15) * 2;
    float a00 = 0.f, a01 = 0.f, a10 = 0.f, a11 = 0.f;
    int nbeg = sp * 2048;
    for (int n0 = nbeg; n0 < nbeg + 2048; n0 += 64) {
        __syncthreads();
        for (int l = tid; l < 512; l += 256) {
            int dd = l >> 4, jj = (l & 15) * 4;
            *(float4*)&ks[dd][jj] = *(const float4*)&kp[(long)dd * N_ + n0 + jj];
            *(float4*)&vs[dd][jj] = *(const float4*)&vp[(long)dd * N_ + n0 + jj];
        }
        __syncthreads();
        #pragma unroll
        for (int j = 0; j < 64; j += 4) {
            float4 x0 = *(const float4*)&ks[d2][j];
            float4 x1 = *(const float4*)&ks[d2 + 1][j];
            float4 y0 = *(const float4*)&vs[e2][j];
            float4 y1 = *(const float4*)&vs[e2 + 1][j];
            a00 += x0.x * y0.x + x0.y * y0.y + x0.z * y0.z + x0.w * y0.w;
            a01 += x0.x * y1.x + x0.y * y1.y + x0.z * y1.z + x0.w * y1.w;
            a10 += x1.x * y0.x + x1.y * y0.y + x1.z * y0.z + x1.w * y0.w;
            a11 += x1.x * y1.x + x1.y * y1.y + x1.z * y1.z + x1.w * y1.w;
        }
    }
    float* out = d_simpart + ((long)(bh * 16 + sp)) * 1024;
    out[(d2 + 0) * 32 + e2 + 0] = a00;
    out[(d2 + 0) * 32 + e2 + 1] = a01;
    out[(d2 + 1) * 32 + e2 + 0] = a10;
    out[(d2 + 1) * 32 + e2 + 1] = a11;
}

__global__ void sim_reduce() {
    int bh = blockIdx.x, i = threadIdx.x;
    float s = 0.f;
    #pragma unroll
    for (int sp = 0; sp < 16; sp++)
        s += d_simpart[(long)(bh * 16 + sp) * 1024 + i];
    d_sim[bh * 1024 + i] = s;
}

// ============================================================
// W2[b,o,h*32+d] = sum_e OW[o,h*32+e]*sim[b,h,d,e]  (bf16 hi/lo)
// ============================================================
__global__ void build_w2(const float* __restrict__ OW) {
    int o = blockIdx.x, b = blockIdx.y, cp = threadIdx.x;
    int h = cp >> 5, d = cp & 31;
    const float* simp = d_sim + ((long)((b * 8 + h) * 32 + d)) * 32;
    const float* owp = OW + o * C_ + h * 32;
    float s = 0.f;
    #pragma unroll
    for (int e = 0; e < 32; e++) s += owp[e] * simp[e];
    __nv_bfloat16 hh = __float2bfloat16(s);
    long idx = ((long)b * C_ + o) * C_ + cp;
    d_W2hi[idx] = hh;
    d_W2lo[idx] = __float2bfloat16(s - __bfloat162float(hh));
}

// ============================================================
// host launch
// ============================================================
extern "C" void kernel_launch(void* const* d_in, const int* in_sizes, int n_in,
                              void* d_out, int out_size) {
    const float* x    = (const float*)d_in[0];
    const float* gnw  = (const float*)d_in[1];
    const float* gnb  = (const float*)d_in[2];
    const float* qkvW = (const float*)d_in[3];
    const float* ow   = (const float*)d_in[4];
    const float* ob   = (const float*)d_in[5];
    float* out = (float*)d_out;

    float *pQ, *pK, *pV, *pBiasp;
    __nv_bfloat16 *pXh, *pXl, *pQh, *pQl, *pWph, *pWpl, *pW2h, *pW2l;
    cudaGetSymbolAddress((void**)&pQ, d_q);
    cudaGetSymbolAddress((void**)&pK, d_k);
    cudaGetSymbolAddress((void**)&pV, d_v);
    cudaGetSymbolAddress((void**)&pBiasp, d_biasp);
    cudaGetSymbolAddress((void**)&pXh, d_xThi);
    cudaGetSymbolAddress((void**)&pXl, d_xTlo);
    cudaGetSymbolAddress((void**)&pQh, d_qThi);
    cudaGetSymbolAddress((void**)&pQl, d_qTlo);
    cudaGetSymbolAddress((void**)&pWph, d_Wphi);
    cudaGetSymbolAddress((void**)&pWpl, d_Wplo);
    cudaGetSymbolAddress((void**)&pW2h, d_W2hi);
    cudaGetSymbolAddress((void**)&pW2l, d_W2lo);

    cudaFuncSetAttribute(gemm_mma<1>, cudaFuncAttributeMaxDynamicSharedMemorySize, GEMM_SMEM);
    cudaFuncSetAttribute(gemm_mma<2>, cudaFuncAttributeMaxDynamicSharedMemorySize, GEMM_SMEM);

    gn_stats1<<<dim3(64, 16), 256>>>(x);
    gn_stats2<<<16, 64>>>(gnw, gnb);
    build_wp<<<dim3(768, 4), 256>>>(qkvW);
    tconv<<<dim3(1024, 8, 4), dim3(32, 8)>>>(x, pXh, pXl);

    // qkv: D[768 x 32768] per batch = Wp @ xT^T (+biasp), split epilogue q/k/v
    gemm_mma<1><<<dim3(256, 6, 4), 256, GEMM_SMEM>>>(pWph, pWpl, pXh, pXl,
                                                     pBiasp, nullptr, pQ, pK, pV, nullptr, 768);

    softmax_k<<<1024, 256>>>();
    sim_partial<<<dim3(16, 32), 256>>>();
    sim_reduce<<<32, 1024>>>();
    build_w2<<<dim3(256, 4), 256>>>(ow);
    tconv<<<dim3(1024, 8, 4), dim3(32, 8)>>>(pQ, pQh, pQl);

    // out: D[256 x 32768] per batch = W2 @ qT^T + ob + x
    gemm_mma<2><<<dim3(256, 2, 4), 256, GEMM_SMEM>>>(pW2h, pW2l, pQh, pQl,
                                                     ob, x, nullptr, nullptr, nullptr, out, 256);
}

// round 4
// speedup vs baseline: 1.9479x; 1.0812x over previous
#include <cuda_runtime.h>
#include <cuda_bf16.h>
#include <cstdint>

// Problem constants
static constexpr int B_ = 4;
static constexpr int C_ = 256;
static constexpr int N_ = 32768;     // 32*32*32
static constexpr int H_ = 8;
static constexpr int CPG = 64;       // C_/NUM_GROUPS
static constexpr long GRP_ELEMS = (long)CPG * N_;  // 2097152

// ---------------- device scratch (no allocations allowed) ----------------
__device__ float d_k[(long)B_ * C_ * N_];          // 128 MB
__device__ float d_v[(long)B_ * C_ * N_];
__device__ __nv_bfloat16 d_xThi[(long)B_ * N_ * C_];   // xT [b][n][c]
__device__ __nv_bfloat16 d_xTlo[(long)B_ * N_ * C_];
__device__ __nv_bfloat16 d_qThi[(long)B_ * N_ * C_];
__device__ __nv_bfloat16 d_qTlo[(long)B_ * N_ * C_];
__device__ __nv_bfloat16 d_Wphi[B_ * 768 * C_];
__device__ __nv_bfloat16 d_Wplo[B_ * 768 * C_];
__device__ float d_biasp[B_ * 768];
__device__ __nv_bfloat16 d_W2hi[B_ * C_ * C_];
__device__ __nv_bfloat16 d_W2lo[B_ * C_ * C_];
__device__ float2 d_part[16 * 64];
__device__ float d_scale[B_ * C_];
__device__ float d_shift[B_ * C_];
__device__ float d_m[B_ * C_];       // k-row max
__device__ float d_s[B_ * C_];       // k-row sum exp(k-m)
__device__ float d_simpart[B_ * H_ * 16 * 1024];
__device__ float d_sim[B_ * H_ * 1024];

// ---------------- PTX helpers ----------------
__device__ __forceinline__ uint32_t smem_u32(const void* p) {
    uint32_t a;
    asm("{ .reg .u64 t; cvta.to.shared.u64 t, %1; cvt.u32.u64 %0, t; }" : "=r"(a) : "l"(p));
    return a;
}
#define CP16(dst, src) asm volatile("cp.async.ca.shared.global [%0], [%1], 16;" :: "r"(dst), "l"(src))
#define CP_COMMIT()    asm volatile("cp.async.commit_group;")
#define CP_WAIT1()     asm volatile("cp.async.wait_group 1;")

__device__ __forceinline__ void ldm4(uint32_t* r, uint32_t addr) {
    asm volatile("ldmatrix.sync.aligned.m8n8.x4.shared.b16 {%0,%1,%2,%3}, [%4];"
        : "=r"(r[0]), "=r"(r[1]), "=r"(r[2]), "=r"(r[3]) : "r"(addr));
}
__device__ __forceinline__ void ldm2(uint32_t* r, uint32_t addr) {
    asm volatile("ldmatrix.sync.aligned.m8n8.x2.shared.b16 {%0,%1}, [%2];"
        : "=r"(r[0]), "=r"(r[1]) : "r"(addr));
}
__device__ __forceinline__ void mma_bf16(float* d, const uint32_t* a, const uint32_t* b) {
    asm volatile(
        "mma.sync.aligned.m16n8k16.row.col.f32.bf16.bf16.f32 "
        "{%0,%1,%2,%3}, {%4,%5,%6,%7}, {%8,%9}, {%0,%1,%2,%3};"
        : "+f"(d[0]), "+f"(d[1]), "+f"(d[2]), "+f"(d[3])
        : "r"(a[0]), "r"(a[1]), "r"(a[2]), "r"(a[3]), "r"(b[0]), "r"(b[1]));
}

// ============================================================
// GroupNorm stats
// ============================================================
__global__ void gn_stats1(const float* __restrict__ x) {
    int bg = blockIdx.y, blk = blockIdx.x;
    const float* p = x + (long)bg * GRP_ELEMS + (long)blk * 32768;
    int tid = threadIdx.x;
    float s = 0.f, ss = 0.f;
    for (int i = tid * 4; i < 32768; i += 1024) {
        float4 v = *(const float4*)&p[i];
        s += v.x + v.y + v.z + v.w;
        ss += v.x * v.x + v.y * v.y + v.z * v.z + v.w * v.w;
    }
    __shared__ float rs[256], rss[256];
    rs[tid] = s; rss[tid] = ss;
    __syncthreads();
    for (int st = 128; st > 0; st >>= 1) {
        if (tid < st) { rs[tid] += rs[tid + st]; rss[tid] += rss[tid + st]; }
        __syncthreads();
    }
    if (tid == 0) d_part[bg * 64 + blk] = make_float2(rs[0], rss[0]);
}

__global__ void gn_stats2(const float* __restrict__ gnw, const float* __restrict__ gnb) {
    int bg = blockIdx.x, tid = threadIdx.x;
    __shared__ float rs[64], rss[64];
    float2 p = d_part[bg * 64 + tid];
    rs[tid] = p.x; rss[tid] = p.y;
    __syncthreads();
    for (int st = 32; st > 0; st >>= 1) {
        if (tid < st) { rs[tid] += rs[tid + st]; rss[tid] += rss[tid + st]; }
        __syncthreads();
    }
    float inv = 1.0f / (float)GRP_ELEMS;
    float mean = rs[0] * inv;
    float var = rss[0] * inv - mean * mean;
    float rstd = rsqrtf(var + 1e-5f);
    int b = bg >> 2, g = bg & 3;
    int c = g * CPG + tid;
    float sc = rstd * gnw[c];
    d_scale[b * C_ + c] = sc;
    d_shift[b * C_ + c] = gnb[c] - mean * sc;
}

// ============================================================
// GN-folded qkv weight (bf16 hi/lo) + folded bias
// ============================================================
__global__ void build_wp(const float* __restrict__ W) {
    int o = blockIdx.x, b = blockIdx.y, c = threadIdx.x;
    float w = W[o * C_ + c];
    float wp = w * d_scale[b * C_ + c];
    __nv_bfloat16 h = __float2bfloat16(wp);
    long idx = ((long)b * 768 + o) * C_ + c;
    d_Wphi[idx] = h;
    d_Wplo[idx] = __float2bfloat16(wp - __bfloat162float(h));
    __shared__ float red[256];
    red[c] = w * d_shift[b * C_ + c];
    __syncthreads();
    for (int st = 128; st > 0; st >>= 1) {
        if (c < st) red[c] += red[c + st];
        __syncthreads();
    }
    if (c == 0) d_biasp[b * 768 + o] = red[0];
}

// ============================================================
// Tiled transpose + bf16 hi/lo split: src [b][256][N] -> dst [b][N][256]
// ============================================================
__global__ void tconv(const float* __restrict__ src,
                      __nv_bfloat16* __restrict__ dhi, __nv_bfloat16* __restrict__ dlo) {
    __shared__ float t[32][33];
    int n0 = blockIdx.x * 32, c0 = blockIdx.y * 32, b = blockIdx.z;
    const float* s = src + (long)b * C_ * N_;
    int tx = threadIdx.x, ty = threadIdx.y;
    #pragma unroll
    for (int i = 0; i < 4; i++) {
        int c = c0 + ty + i * 8;
        t[ty + i * 8][tx] = s[(long)c * N_ + n0 + tx];
    }
    __syncthreads();
    __nv_bfloat16* ph = dhi + (long)b * N_ * C_;
    __nv_bfloat16* pl = dlo + (long)b * N_ * C_;
    #pragma unroll
    for (int i = 0; i < 4; i++) {
        int n = n0 + ty + i * 8;
        float v = t[tx][ty + i * 8];
        __nv_bfloat16 h = __float2bfloat16(v);
        ph[(long)n * C_ + c0 + tx] = h;
        pl[(long)n * C_ + c0 + tx] = __float2bfloat16(v - __bfloat162float(h));
    }
}

// ============================================================
// bf16 split GEMM via mma.sync: D[128x128] per CTA.
// grid = (mt, nt, b)  [mt fastest -> CTAs sharing B tile co-scheduled -> L2 reuse]
// MODE 1: qkv. mt 0-1 -> q: transpose epilogue writes qT bf16 hi/lo directly.
//               mt 2-5 -> k/v fp32 [c][n].
// MODE 2: out = W2 @ qT^T + ob + residual.
// ============================================================
static constexpr int SKROW = 40;         // bf16 elems per smem row (32 + 8 pad)
static constexpr int TILE_BYTES = 128 * SKROW * 2;   // 10240 per matrix
static constexpr int STAGE_BYTES = 4 * TILE_BYTES;   // Ahi, Alo, Bhi, Blo
static constexpr int GEMM_SMEM = 2 * STAGE_BYTES;    // 81920

__device__ __forceinline__ void load_stage(
    uint32_t sbase, const __nv_bfloat16* Ah, const __nv_bfloat16* Al,
    const __nv_bfloat16* Bh, const __nv_bfloat16* Bl, int kt, int tid)
{
    int k0 = kt * 32;
    #pragma unroll
    for (int it = 0; it < 2; it++) {
        int i = tid + it * 256;
        int row = i >> 2, c = i & 3;
        uint32_t doff = row * (SKROW * 2) + c * 16;
        long goff = (long)row * 256 + k0 + c * 8;
        CP16(sbase + doff,                  Ah + goff);
        CP16(sbase + TILE_BYTES + doff,     Al + goff);
        CP16(sbase + 2 * TILE_BYTES + doff, Bh + goff);
        CP16(sbase + 3 * TILE_BYTES + doff, Bl + goff);
    }
}

template <int MODE>
__global__ void __launch_bounds__(256, 1) gemm_mma(
    const __nv_bfloat16* __restrict__ Ahi, const __nv_bfloat16* __restrict__ Alo,
    const __nv_bfloat16* __restrict__ Bhi, const __nv_bfloat16* __restrict__ Blo,
    const float* __restrict__ bias, const float* __restrict__ resid,
    __nv_bfloat16* __restrict__ outQh, __nv_bfloat16* __restrict__ outQl,
    float* __restrict__ outK, float* __restrict__ outV,
    float* __restrict__ outO, int Mtotal)
{
    extern __shared__ char smem[];
    uint32_t sb = smem_u32(smem);
    int tid = threadIdx.x;
    int warp = tid >> 5, lane = tid & 31;
    int wm = (warp >> 2) * 64;      // warp m offset in tile
    int wn = (warp & 3) * 32;       // warp n offset in tile
    int mt = blockIdx.x, nt = blockIdx.y, b = blockIdx.z;

    const __nv_bfloat16* Ah = Ahi + (long)b * Mtotal * 256 + (long)mt * 128 * 256;
    const __nv_bfloat16* Al = Alo + (long)b * Mtotal * 256 + (long)mt * 128 * 256;
    const __nv_bfloat16* Bh = Bhi + (long)b * N_ * 256 + (long)nt * 128 * 256;
    const __nv_bfloat16* Bl = Blo + (long)b * N_ * 256 + (long)nt * 128 * 256;

    float acc[4][4][4];
    #pragma unroll
    for (int i = 0; i < 4; i++)
        #pragma unroll
        for (int j = 0; j < 4; j++)
            #pragma unroll
            for (int e = 0; e < 4; e++) acc[i][j][e] = 0.f;

    load_stage(sb, Ah, Al, Bh, Bl, 0, tid); CP_COMMIT();
    load_stage(sb + STAGE_BYTES, Ah, Al, Bh, Bl, 1, tid); CP_COMMIT();

    int quad = lane >> 3, qr = lane & 7;
    int a_row = wm + (quad & 1) * 8 + qr;
    int a_colb = (quad >> 1) * 16;
    int bl8 = lane & 15;
    int b_row = wn + (bl8 & 7);
    int b_colb = (bl8 >> 3) * 16;

    #pragma unroll 1
    for (int kt = 0; kt < 8; kt++) {
        CP_WAIT1();
        __syncthreads();
        uint32_t base = sb + (kt & 1) * STAGE_BYTES;
        uint32_t aHi = base, aLo = base + TILE_BYTES;
        uint32_t bHi = base + 2 * TILE_BYTES, bLo = base + 3 * TILE_BYTES;

        #pragma unroll
        for (int k16 = 0; k16 < 2; k16++) {
            uint32_t acol = a_colb + k16 * 32;
            uint32_t bcol = b_colb + k16 * 32;
            uint32_t ah[4][4], al[4][4], bh[4][2], bl_[4][2];
            #pragma unroll
            for (int mf = 0; mf < 4; mf++) {
                uint32_t ro = (a_row + mf * 16) * (SKROW * 2);
                ldm4(ah[mf], aHi + ro + acol);
                ldm4(al[mf], aLo + ro + acol);
            }
            #pragma unroll
            for (int nf = 0; nf < 4; nf++) {
                uint32_t ro = (b_row + nf * 8) * (SKROW * 2);
                ldm2(bh[nf], bHi + ro + bcol);
                ldm2(bl_[nf], bLo + ro + bcol);
            }
            #pragma unroll
            for (int mf = 0; mf < 4; mf++)
                #pragma unroll
                for (int nf = 0; nf < 4; nf++) {
                    mma_bf16(acc[mf][nf], ah[mf], bh[nf]);
                    mma_bf16(acc[mf][nf], ah[mf], bl_[nf]);
                    mma_bf16(acc[mf][nf], al[mf], bh[nf]);
                }
        }
        __syncthreads();
        if (kt + 2 < 8)
            load_stage(sb + (kt & 1) * STAGE_BYTES, Ah, Al, Bh, Bl, kt + 2, tid);
        CP_COMMIT();
    }
    asm volatile("cp.async.wait_group 0;");

    if (MODE == 1 && mt < 2) {
        // ---- q path: transpose through smem, write qT bf16 hi/lo ----
        float* smem_t = (float*)smem;   // [128][129]
        __syncthreads();
        #pragma unroll
        for (int mf = 0; mf < 4; mf++) {
            int rbase = wm + mf * 16 + (lane >> 2);
            #pragma unroll
            for (int half = 0; half < 2; half++) {
                int m = rbase + half * 8;
                float bv = bias[b * 768 + mt * 128 + m];
                #pragma unroll
                for (int nf = 0; nf < 4; nf++) {
                    int n = wn + nf * 8 + 2 * (lane & 3);
                    smem_t[m * 129 + n]     = acc[mf][nf][half * 2 + 0] + bv;
                    smem_t[m * 129 + n + 1] = acc[mf][nf][half * 2 + 1] + bv;
                }
            }
        }
        __syncthreads();
        int j = tid & 127, hf = tid >> 7;
        long gn = (long)nt * 128 + j;
        __nv_bfloat16* ph = outQh + ((long)b * N_ + gn) * 256 + mt * 128 + hf * 64;
        __nv_bfloat16* pl = outQl + ((long)b * N_ + gn) * 256 + mt * 128 + hf * 64;
        #pragma unroll
        for (int ch = 0; ch < 8; ch++) {
            __align__(16) __nv_bfloat16 hb[8];
            __align__(16) __nv_bfloat16 lb[8];
            #pragma unroll
            for (int e = 0; e < 8; e++) {
                float v = smem_t[(hf * 64 + ch * 8 + e) * 129 + j];
                __nv_bfloat16 hh = __float2bfloat16(v);
                hb[e] = hh;
                lb[e] = __float2bfloat16(v - __bfloat162float(hh));
            }
            *(uint4*)(ph + ch * 8) = *(const uint4*)hb;
            *(uint4*)(pl + ch * 8) = *(const uint4*)lb;
        }
        return;
    }

    #pragma unroll
    for (int mf = 0; mf < 4; mf++) {
        int r0 = mt * 128 + wm + mf * 16 + (lane >> 2);
        #pragma unroll
        for (int half = 0; half < 2; half++) {
            int mrow = r0 + half * 8;
            float bv;
            float* dst;
            const float* rp = nullptr;
            if (MODE == 1) {
                int sec = mrow >> 8, c = mrow & 255;   // sec 1=k, 2=v
                bv = bias[b * 768 + mrow];
                dst = (sec == 1 ? outK : outV) + ((long)b * C_ + c) * N_;
            } else {
                bv = bias[mrow];
                long base = ((long)b * C_ + mrow) * N_;
                dst = outO + base;
                rp = resid + base;
            }
            #pragma unroll
            for (int nf = 0; nf < 4; nf++) {
                int n = nt * 128 + wn + nf * 8 + 2 * (lane & 3);
                float dA = acc[mf][nf][half * 2 + 0] + bv;
                float dB = acc[mf][nf][half * 2 + 1] + bv;
                if (MODE == 2) {
                    float2 rv = *(const float2*)&rp[n];
                    dA += rv.x; dB += rv.y;
                }
                float2 o; o.x = dA; o.y = dB;
                *(float2*)&dst[n] = o;
            }
        }
    }
}

// ============================================================
// k-row online (max, sumexp) stats. grid 1024, 256 threads.
// ============================================================
__global__ void krow_stats() {
    int blk = blockIdx.x;
    int b = blk >> 8, r = blk & 255;
    const float* row = d_k + ((long)b * C_ + r) * N_;
    int tid = threadIdx.x;
    float m = -1e30f, s = 0.f;
    for (int i = tid * 4; i < N_; i += 1024) {
        float4 v = *(const float4*)&row[i];
        float mv = fmaxf(fmaxf(v.x, v.y), fmaxf(v.z, v.w));
        if (mv > m) { s *= __expf(m - mv); m = mv; }
        s += __expf(v.x - m) + __expf(v.y - m) + __expf(v.z - m) + __expf(v.w - m);
    }
    __shared__ float sm[256], ssum[256];
    sm[tid] = m; ssum[tid] = s;
    __syncthreads();
    for (int st = 128; st > 0; st >>= 1) {
        if (tid < st) {
            float m1 = sm[tid], m2 = sm[tid + st];
            float s1 = ssum[tid], s2 = ssum[tid + st];
            float M = fmaxf(m1, m2);
            ssum[tid] = s1 * __expf(m1 - M) + s2 * __expf(m2 - M);
            sm[tid] = M;
        }
        __syncthreads();
    }
    if (tid == 0) { d_m[b * C_ + r] = sm[0]; d_s[b * C_ + r] = ssum[0]; }
}

// ============================================================
// sim[b,h,d,e] = sum_n exp(k[d,n]-m[d])*v[e,n] (split over n)
// ============================================================
__global__ void __launch_bounds__(256) sim_partial() {
    const int PAD = 68;
    __shared__ float ks[32][PAD], vs[32][PAD];
    __shared__ float ms[32];
    int sp = blockIdx.x, bh = blockIdx.y;
    int b = bh >> 3, h = bh & 7;
    const float* kp = d_k + ((long)b * C_ + h * 32) * N_;
    const float* vp = d_v + ((long)b * C_ + h * 32) * N_;
    int tid = threadIdx.x;
    if (tid < 32) ms[tid] = d_m[b * C_ + h * 32 + tid];
    int d2 = (tid >> 4) * 2, e2 = (tid & 15) * 2;
    float a00 = 0.f, a01 = 0.f, a10 = 0.f, a11 = 0.f;
    int nbeg = sp * 2048;
    for (int n0 = nbeg; n0 < nbeg + 2048; n0 += 64) {
        __syncthreads();
        for (int l = tid; l < 512; l += 256) {
            int dd = l >> 4, jj = (l & 15) * 4;
            float mrow = ms[dd];
            float4 kv = *(const float4*)&kp[(long)dd * N_ + n0 + jj];
            kv.x = __expf(kv.x - mrow);
            kv.y = __expf(kv.y - mrow);
            kv.z = __expf(kv.z - mrow);
            kv.w = __expf(kv.w - mrow);
            *(float4*)&ks[dd][jj] = kv;
            *(float4*)&vs[dd][jj] = *(const float4*)&vp[(long)dd * N_ + n0 + jj];
        }
        __syncthreads();
        #pragma unroll
        for (int j = 0; j < 64; j += 4) {
            float4 x0 = *(const float4*)&ks[d2][j];
            float4 x1 = *(const float4*)&ks[d2 + 1][j];
            float4 y0 = *(const float4*)&vs[e2][j];
            float4 y1 = *(const float4*)&vs[e2 + 1][j];
            a00 += x0.x * y0.x + x0.y * y0.y + x0.z * y0.z + x0.w * y0.w;
            a01 += x0.x * y1.x + x0.y * y1.y + x0.z * y1.z + x0.w * y1.w;
            a10 += x1.x * y0.x + x1.y * y0.y + x1.z * y0.z + x1.w * y0.w;
            a11 += x1.x * y1.x + x1.y * y1.y + x1.z * y1.z + x1.w * y1.w;
        }
    }
    float* out = d_simpart + ((long)(bh * 16 + sp)) * 1024;
    out[(d2 + 0) * 32 + e2 + 0] = a00;
    out[(d2 + 0) * 32 + e2 + 1] = a01;
    out[(d2 + 1) * 32 + e2 + 0] = a10;
    out[(d2 + 1) * 32 + e2 + 1] = a11;
}

// reduce splits + divide by softmax denominator s[d]
__global__ void sim_reduce() {
    int bh = blockIdx.x, i = threadIdx.x;
    int b = bh >> 3, h = bh & 7;
    float s = 0.f;
    #pragma unroll
    for (int sp = 0; sp < 16; sp++)
        s += d_simpart[(long)(bh * 16 + sp) * 1024 + i];
    float inv = 1.0f / d_s[b * C_ + h * 32 + (i >> 5)];
    d_sim[bh * 1024 + i] = s * inv;
}

// ============================================================
// W2[b,o,h*32+d] = sum_e OW[o,h*32+e]*sim[b,h,d,e]  (bf16 hi/lo)
// ============================================================
__global__ void build_w2(const float* __restrict__ OW) {
    int o = blockIdx.x, b = blockIdx.y, cp = threadIdx.x;
    int h = cp >> 5, d = cp & 31;
    const float* simp = d_sim + ((long)((b * 8 + h) * 32 + d)) * 32;
    const float* owp = OW + o * C_ + h * 32;
    float s = 0.f;
    #pragma unroll
    for (int e = 0; e < 32; e++) s += owp[e] * simp[e];
    __nv_bfloat16 hh = __float2bfloat16(s);
    long idx = ((long)b * C_ + o) * C_ + cp;
    d_W2hi[idx] = hh;
    d_W2lo[idx] = __float2bfloat16(s - __bfloat162float(hh));
}

// ============================================================
// host launch
// ============================================================
extern "C" void kernel_launch(void* const* d_in, const int* in_sizes, int n_in,
                              void* d_out, int out_size) {
    const float* x    = (const float*)d_in[0];
    const float* gnw  = (const float*)d_in[1];
    const float* gnb  = (const float*)d_in[2];
    const float* qkvW = (const float*)d_in[3];
    const float* ow   = (const float*)d_in[4];
    const float* ob   = (const float*)d_in[5];
    float* out = (float*)d_out;

    float *pK, *pV, *pBiasp;
    __nv_bfloat16 *pXh, *pXl, *pQh, *pQl, *pWph, *pWpl, *pW2h, *pW2l;
    cudaGetSymbolAddress((void**)&pK, d_k);
    cudaGetSymbolAddress((void**)&pV, d_v);
    cudaGetSymbolAddress((void**)&pBiasp, d_biasp);
    cudaGetSymbolAddress((void**)&pXh, d_xThi);
    cudaGetSymbolAddress((void**)&pXl, d_xTlo);
    cudaGetSymbolAddress((void**)&pQh, d_qThi);
    cudaGetSymbolAddress((void**)&pQl, d_qTlo);
    cudaGetSymbolAddress((void**)&pWph, d_Wphi);
    cudaGetSymbolAddress((void**)&pWpl, d_Wplo);
    cudaGetSymbolAddress((void**)&pW2h, d_W2hi);
    cudaGetSymbolAddress((void**)&pW2l, d_W2lo);

    cudaFuncSetAttribute(gemm_mma<1>, cudaFuncAttributeMaxDynamicSharedMemorySize, GEMM_SMEM);
    cudaFuncSetAttribute(gemm_mma<2>, cudaFuncAttributeMaxDynamicSharedMemorySize, GEMM_SMEM);

    gn_stats1<<<dim3(64, 16), 256>>>(x);
    gn_stats2<<<16, 64>>>(gnw, gnb);
    build_wp<<<dim3(768, 4), 256>>>(qkvW);
    tconv<<<dim3(1024, 8, 4), dim3(32, 8)>>>(x, pXh, pXl);

    // qkv: grid (mt fastest for B L2 reuse). q -> qT bf16 direct; k,v -> fp32.
    gemm_mma<1><<<dim3(6, 256, 4), 256, GEMM_SMEM>>>(pWph, pWpl, pXh, pXl,
                                                     pBiasp, nullptr, pQh, pQl, pK, pV, nullptr, 768);

    krow_stats<<<1024, 256>>>();
    sim_partial<<<dim3(16, 32), 256>>>();
    sim_reduce<<<32, 1024>>>();
    build_w2<<<dim3(256, 4), 256>>>(ow);

    // out: W2 @ qT^T + ob + x
    gemm_mma<2><<<dim3(2, 256, 4), 256, GEMM_SMEM>>>(pW2h, pW2l, pQh, pQl,
                                                     ob, x, nullptr, nullptr, nullptr, nullptr, out, 256);
}

// round 5
// speedup vs baseline: 3.0563x; 1.5690x over previous
#include <cuda_runtime.h>
#include <cuda_fp16.h>
#include <cstdint>

// Problem constants
static constexpr int B_ = 4;
static constexpr int C_ = 256;
static constexpr int N_ = 32768;     // 32*32*32
static constexpr int H_ = 8;
static constexpr int CPG = 64;       // C_/NUM_GROUPS
static constexpr long GRP_ELEMS = (long)CPG * N_;  // 2097152

// ---------------- device scratch (no allocations allowed) ----------------
__device__ float d_k[(long)B_ * C_ * N_];          // 128 MB
__device__ float d_v[(long)B_ * C_ * N_];
__device__ __half d_xT[(long)B_ * N_ * C_];        // xT [b][n][c] fp16
__device__ __half d_qT[(long)B_ * N_ * C_];        // qT [b][n][c] fp16
__device__ __half d_Wp[B_ * 768 * C_];             // GN-folded qkv weight fp16
__device__ float d_biasp[B_ * 768];
__device__ __half d_W2[B_ * C_ * C_];              // fused sim+out_proj weight fp16
__device__ float2 d_part[16 * 64];
__device__ float d_scale[B_ * C_];
__device__ float d_shift[B_ * C_];
__device__ float d_m[B_ * C_];       // k-row max
__device__ float d_s[B_ * C_];       // k-row sum exp(k-m)
__device__ float d_simpart[B_ * H_ * 16 * 1024];
__device__ float d_sim[B_ * H_ * 1024];

// ---------------- PTX helpers ----------------
__device__ __forceinline__ uint32_t smem_u32(const void* p) {
    uint32_t a;
    asm("{ .reg .u64 t; cvta.to.shared.u64 t, %1; cvt.u32.u64 %0, t; }" : "=r"(a) : "l"(p));
    return a;
}
#define CP16(dst, src) asm volatile("cp.async.ca.shared.global [%0], [%1], 16;" :: "r"(dst), "l"(src))
#define CP_COMMIT()    asm volatile("cp.async.commit_group;")
#define CP_WAIT1()     asm volatile("cp.async.wait_group 1;")

__device__ __forceinline__ void ldm4(uint32_t* r, uint32_t addr) {
    asm volatile("ldmatrix.sync.aligned.m8n8.x4.shared.b16 {%0,%1,%2,%3}, [%4];"
        : "=r"(r[0]), "=r"(r[1]), "=r"(r[2]), "=r"(r[3]) : "r"(addr));
}
__device__ __forceinline__ void ldm2(uint32_t* r, uint32_t addr) {
    asm volatile("ldmatrix.sync.aligned.m8n8.x2.shared.b16 {%0,%1}, [%2];"
        : "=r"(r[0]), "=r"(r[1]) : "r"(addr));
}
__device__ __forceinline__ void mma_f16(float* d, const uint32_t* a, const uint32_t* b) {
    asm volatile(
        "mma.sync.aligned.m16n8k16.row.col.f32.f16.f16.f32 "
        "{%0,%1,%2,%3}, {%4,%5,%6,%7}, {%8,%9}, {%0,%1,%2,%3};"
        : "+f"(d[0]), "+f"(d[1]), "+f"(d[2]), "+f"(d[3])
        : "r"(a[0]), "r"(a[1]), "r"(a[2]), "r"(a[3]), "r"(b[0]), "r"(b[1]));
}

// ============================================================
// GroupNorm stats
// ============================================================
__global__ void gn_stats1(const float* __restrict__ x) {
    int bg = blockIdx.y, blk = blockIdx.x;
    const float* p = x + (long)bg * GRP_ELEMS + (long)blk * 32768;
    int tid = threadIdx.x;
    float s = 0.f, ss = 0.f;
    for (int i = tid * 4; i < 32768; i += 1024) {
        float4 v = *(const float4*)&p[i];
        s += v.x + v.y + v.z + v.w;
        ss += v.x * v.x + v.y * v.y + v.z * v.z + v.w * v.w;
    }
    __shared__ float rs[256], rss[256];
    rs[tid] = s; rss[tid] = ss;
    __syncthreads();
    for (int st = 128; st > 0; st >>= 1) {
        if (tid < st) { rs[tid] += rs[tid + st]; rss[tid] += rss[tid + st]; }
        __syncthreads();
    }
    if (tid == 0) d_part[bg * 64 + blk] = make_float2(rs[0], rss[0]);
}

__global__ void gn_stats2(const float* __restrict__ gnw, const float* __restrict__ gnb) {
    int bg = blockIdx.x, tid = threadIdx.x;
    __shared__ float rs[64], rss[64];
    float2 p = d_part[bg * 64 + tid];
    rs[tid] = p.x; rss[tid] = p.y;
    __syncthreads();
    for (int st = 32; st > 0; st >>= 1) {
        if (tid < st) { rs[tid] += rs[tid + st]; rss[tid] += rss[tid + st]; }
        __syncthreads();
    }
    float inv = 1.0f / (float)GRP_ELEMS;
    float mean = rs[0] * inv;
    float var = rss[0] * inv - mean * mean;
    float rstd = rsqrtf(var + 1e-5f);
    int b = bg >> 2, g = bg & 3;
    int c = g * CPG + tid;
    float sc = rstd * gnw[c];
    d_scale[b * C_ + c] = sc;
    d_shift[b * C_ + c] = gnb[c] - mean * sc;
}

// ============================================================
// GN-folded qkv weight (fp16) + folded bias
// ============================================================
__global__ void build_wp(const float* __restrict__ W) {
    int o = blockIdx.x, b = blockIdx.y, c = threadIdx.x;
    float w = W[o * C_ + c];
    float wp = w * d_scale[b * C_ + c];
    d_Wp[((long)b * 768 + o) * C_ + c] = __float2half_rn(wp);
    __shared__ float red[256];
    red[c] = w * d_shift[b * C_ + c];
    __syncthreads();
    for (int st = 128; st > 0; st >>= 1) {
        if (c < st) red[c] += red[c + st];
        __syncthreads();
    }
    if (c == 0) d_biasp[b * 768 + o] = red[0];
}

// ============================================================
// Tiled transpose + fp16 convert: src [b][256][N] -> dst [b][N][256]
// ============================================================
__global__ void tconv(const float* __restrict__ src, __half* __restrict__ dst) {
    __shared__ float t[32][33];
    int n0 = blockIdx.x * 32, c0 = blockIdx.y * 32, b = blockIdx.z;
    const float* s = src + (long)b * C_ * N_;
    int tx = threadIdx.x, ty = threadIdx.y;
    #pragma unroll
    for (int i = 0; i < 4; i++) {
        int c = c0 + ty + i * 8;
        t[ty + i * 8][tx] = s[(long)c * N_ + n0 + tx];
    }
    __syncthreads();
    __half* ph = dst + (long)b * N_ * C_;
    #pragma unroll
    for (int i = 0; i < 4; i++) {
        int n = n0 + ty + i * 8;
        ph[(long)n * C_ + c0 + tx] = __float2half_rn(t[tx][ty + i * 8]);
    }
}

// ============================================================
// fp16 GEMM via mma.sync: D[128x128] per CTA, fp32 accum.
// grid = (mt, nt, b)  [mt fastest -> B-tile L2 reuse]
// MODE 1: qkv. mt 0-1 -> q: transpose epilogue -> qT fp16 direct.
//               mt 2-5 -> k/v fp32 [c][n].
// MODE 2: out = W2 @ qT^T + ob + residual.
// ============================================================
static constexpr int SKROW = 40;         // fp16 elems per smem row (32 + 8 pad)
static constexpr int TILE_BYTES = 128 * SKROW * 2;   // 10240 per matrix
static constexpr int STAGE_BYTES = 2 * TILE_BYTES;   // A, B
static constexpr int GEMM_SMEM = 2 * STAGE_BYTES;    // 40960 (q-epilogue needs 66048)
static constexpr int GEMM_SMEM_Q = 128 * 129 * 4;    // 66048

__device__ __forceinline__ void load_stage(
    uint32_t sbase, const __half* A, const __half* Bm, int kt, int tid)
{
    int k0 = kt * 32;
    #pragma unroll
    for (int it = 0; it < 2; it++) {
        int i = tid + it * 256;
        int row = i >> 2, c = i & 3;
        uint32_t doff = row * (SKROW * 2) + c * 16;
        long goff = (long)row * 256 + k0 + c * 8;
        CP16(sbase + doff,              A + goff);
        CP16(sbase + TILE_BYTES + doff, Bm + goff);
    }
}

template <int MODE>
__global__ void __launch_bounds__(256, 2) gemm_mma(
    const __half* __restrict__ Amat, const __half* __restrict__ Bmat,
    const float* __restrict__ bias, const float* __restrict__ resid,
    __half* __restrict__ outQT,
    float* __restrict__ outK, float* __restrict__ outV,
    float* __restrict__ outO, int Mtotal)
{
    extern __shared__ char smem[];
    uint32_t sb = smem_u32(smem);
    int tid = threadIdx.x;
    int warp = tid >> 5, lane = tid & 31;
    int wm = (warp >> 2) * 64;
    int wn = (warp & 3) * 32;
    int mt = blockIdx.x, nt = blockIdx.y, b = blockIdx.z;

    const __half* A = Amat + (long)b * Mtotal * 256 + (long)mt * 128 * 256;
    const __half* Bm = Bmat + (long)b * N_ * 256 + (long)nt * 128 * 256;

    float acc[4][4][4];
    #pragma unroll
    for (int i = 0; i < 4; i++)
        #pragma unroll
        for (int j = 0; j < 4; j++)
            #pragma unroll
            for (int e = 0; e < 4; e++) acc[i][j][e] = 0.f;

    load_stage(sb, A, Bm, 0, tid); CP_COMMIT();
    load_stage(sb + STAGE_BYTES, A, Bm, 1, tid); CP_COMMIT();

    int quad = lane >> 3, qr = lane & 7;
    int a_row = wm + (quad & 1) * 8 + qr;
    int a_colb = (quad >> 1) * 16;
    int bl8 = lane & 15;
    int b_row = wn + (bl8 & 7);
    int b_colb = (bl8 >> 3) * 16;

    #pragma unroll 1
    for (int kt = 0; kt < 8; kt++) {
        CP_WAIT1();
        __syncthreads();
        uint32_t base = sb + (kt & 1) * STAGE_BYTES;
        uint32_t aS = base, bS = base + TILE_BYTES;

        #pragma unroll
        for (int k16 = 0; k16 < 2; k16++) {
            uint32_t acol = a_colb + k16 * 32;
            uint32_t bcol = b_colb + k16 * 32;
            uint32_t ah[4][4], bh[4][2];
            #pragma unroll
            for (int mf = 0; mf < 4; mf++)
                ldm4(ah[mf], aS + (a_row + mf * 16) * (SKROW * 2) + acol);
            #pragma unroll
            for (int nf = 0; nf < 4; nf++)
                ldm2(bh[nf], bS + (b_row + nf * 8) * (SKROW * 2) + bcol);
            #pragma unroll
            for (int mf = 0; mf < 4; mf++)
                #pragma unroll
                for (int nf = 0; nf < 4; nf++)
                    mma_f16(acc[mf][nf], ah[mf], bh[nf]);
        }
        __syncthreads();
        if (kt + 2 < 8)
            load_stage(sb + (kt & 1) * STAGE_BYTES, A, Bm, kt + 2, tid);
        CP_COMMIT();
    }
    asm volatile("cp.async.wait_group 0;");

    if (MODE == 1 && mt < 2) {
        // ---- q path: transpose through smem, write qT fp16 directly ----
        float* smem_t = (float*)smem;   // [128][129]
        __syncthreads();
        #pragma unroll
        for (int mf = 0; mf < 4; mf++) {
            int rbase = wm + mf * 16 + (lane >> 2);
            #pragma unroll
            for (int half = 0; half < 2; half++) {
                int m = rbase + half * 8;
                float bv = bias[b * 768 + mt * 128 + m];
                #pragma unroll
                for (int nf = 0; nf < 4; nf++) {
                    int n = wn + nf * 8 + 2 * (lane & 3);
                    smem_t[m * 129 + n]     = acc[mf][nf][half * 2 + 0] + bv;
                    smem_t[m * 129 + n + 1] = acc[mf][nf][half * 2 + 1] + bv;
                }
            }
        }
        __syncthreads();
        int j = tid & 127, hf = tid >> 7;
        long gn = (long)nt * 128 + j;
        __half* ph = outQT + ((long)b * N_ + gn) * 256 + mt * 128 + hf * 64;
        #pragma unroll
        for (int ch = 0; ch < 8; ch++) {
            __align__(16) __half hb[8];
            #pragma unroll
            for (int e = 0; e < 8; e++)
                hb[e] = __float2half_rn(smem_t[(hf * 64 + ch * 8 + e) * 129 + j]);
            *(uint4*)(ph + ch * 8) = *(const uint4*)hb;
        }
        return;
    }

    #pragma unroll
    for (int mf = 0; mf < 4; mf++) {
        int r0 = mt * 128 + wm + mf * 16 + (lane >> 2);
        #pragma unroll
        for (int half = 0; half < 2; half++) {
            int mrow = r0 + half * 8;
            float bv;
            float* dst;
            const float* rp = nullptr;
            if (MODE == 1) {
                int sec = mrow >> 8, c = mrow & 255;   // sec 1=k, 2=v
                bv = bias[b * 768 + mrow];
                dst = (sec == 1 ? outK : outV) + ((long)b * C_ + c) * N_;
            } else {
                bv = bias[mrow];
                long base = ((long)b * C_ + mrow) * N_;
                dst = outO + base;
                rp = resid + base;
            }
            #pragma unroll
            for (int nf = 0; nf < 4; nf++) {
                int n = nt * 128 + wn + nf * 8 + 2 * (lane & 3);
                float dA = acc[mf][nf][half * 2 + 0] + bv;
                float dB = acc[mf][nf][half * 2 + 1] + bv;
                if (MODE == 2) {
                    float2 rv = *(const float2*)&rp[n];
                    dA += rv.x; dB += rv.y;
                }
                float2 o; o.x = dA; o.y = dB;
                *(float2*)&dst[n] = o;
            }
        }
    }
}

// ============================================================
// k-row online (max, sumexp) stats. grid 1024, 256 threads.
// ============================================================
__global__ void krow_stats() {
    int blk = blockIdx.x;
    int b = blk >> 8, r = blk & 255;
    const float* row = d_k + ((long)b * C_ + r) * N_;
    int tid = threadIdx.x;
    float m = -1e30f, s = 0.f;
    for (int i = tid * 4; i < N_; i += 1024) {
        float4 v = *(const float4*)&row[i];
        float mv = fmaxf(fmaxf(v.x, v.y), fmaxf(v.z, v.w));
        if (mv > m) { s *= __expf(m - mv); m = mv; }
        s += __expf(v.x - m) + __expf(v.y - m) + __expf(v.z - m) + __expf(v.w - m);
    }
    __shared__ float sm[256], ssum[256];
    sm[tid] = m; ssum[tid] = s;
    __syncthreads();
    for (int st = 128; st > 0; st >>= 1) {
        if (tid < st) {
            float m1 = sm[tid], m2 = sm[tid + st];
            float s1 = ssum[tid], s2 = ssum[tid + st];
            float M = fmaxf(m1, m2);
            ssum[tid] = s1 * __expf(m1 - M) + s2 * __expf(m2 - M);
            sm[tid] = M;
        }
        __syncthreads();
    }
    if (tid == 0) { d_m[b * C_ + r] = sm[0]; d_s[b * C_ + r] = ssum[0]; }
}

// ============================================================
// sim[b,h,d,e] = sum_n exp(k[d,n]-m[d])*v[e,n] (split over n)
// ============================================================
__global__ void __launch_bounds__(256) sim_partial() {
    const int PAD = 68;
    __shared__ float ks[32][PAD], vs[32][PAD];
    __shared__ float ms[32];
    int sp = blockIdx.x, bh = blockIdx.y;
    int b = bh >> 3, h = bh & 7;
    const float* kp = d_k + ((long)b * C_ + h * 32) * N_;
    const float* vp = d_v + ((long)b * C_ + h * 32) * N_;
    int tid = threadIdx.x;
    if (tid < 32) ms[tid] = d_m[b * C_ + h * 32 + tid];
    int d2 = (tid >> 4) * 2, e2 = (tid & 15) * 2;
    float a00 = 0.f, a01 = 0.f, a10 = 0.f, a11 = 0.f;
    int nbeg = sp * 2048;
    for (int n0 = nbeg; n0 < nbeg + 2048; n0 += 64) {
        __syncthreads();
        for (int l = tid; l < 512; l += 256) {
            int dd = l >> 4, jj = (l & 15) * 4;
            float mrow = ms[dd];
            float4 kv = *(const float4*)&kp[(long)dd * N_ + n0 + jj];
            kv.x = __expf(kv.x - mrow);
            kv.y = __expf(kv.y - mrow);
            kv.z = __expf(kv.z - mrow);
            kv.w = __expf(kv.w - mrow);
            *(float4*)&ks[dd][jj] = kv;
            *(float4*)&vs[dd][jj] = *(const float4*)&vp[(long)dd * N_ + n0 + jj];
        }
        __syncthreads();
        #pragma unroll
        for (int j = 0; j < 64; j += 4) {
            float4 x0 = *(const float4*)&ks[d2][j];
            float4 x1 = *(const float4*)&ks[d2 + 1][j];
            float4 y0 = *(const float4*)&vs[e2][j];
            float4 y1 = *(const float4*)&vs[e2 + 1][j];
            a00 += x0.x * y0.x + x0.y * y0.y + x0.z * y0.z + x0.w * y0.w;
            a01 += x0.x * y1.x + x0.y * y1.y + x0.z * y1.z + x0.w * y1.w;
            a10 += x1.x * y0.x + x1.y * y0.y + x1.z * y0.z + x1.w * y0.w;
            a11 += x1.x * y1.x + x1.y * y1.y + x1.z * y1.z + x1.w * y1.w;
        }
    }
    float* out = d_simpart + ((long)(bh * 16 + sp)) * 1024;
    out[(d2 + 0) * 32 + e2 + 0] = a00;
    out[(d2 + 0) * 32 + e2 + 1] = a01;
    out[(d2 + 1) * 32 + e2 + 0] = a10;
    out[(d2 + 1) * 32 + e2 + 1] = a11;
}

// reduce splits + divide by softmax denominator s[d]
__global__ void sim_reduce() {
    int bh = blockIdx.x, i = threadIdx.x;
    int b = bh >> 3, h = bh & 7;
    float s = 0.f;
    #pragma unroll
    for (int sp = 0; sp < 16; sp++)
        s += d_simpart[(long)(bh * 16 + sp) * 1024 + i];
    float inv = 1.0f / d_s[b * C_ + h * 32 + (i >> 5)];
    d_sim[bh * 1024 + i] = s * inv;
}

// ============================================================
// W2[b,o,h*32+d] = sum_e OW[o,h*32+e]*sim[b,h,d,e]  (fp16)
// ============================================================
__global__ void build_w2(const float* __restrict__ OW) {
    int o = blockIdx.x, b = blockIdx.y, cp = threadIdx.x;
    int h = cp >> 5, d = cp & 31;
    const float* simp = d_sim + ((long)((b * 8 + h) * 32 + d)) * 32;
    const float* owp = OW + o * C_ + h * 32;
    float s = 0.f;
    #pragma unroll
    for (int e = 0; e < 32; e++) s += owp[e] * simp[e];
    d_W2[((long)b * C_ + o) * C_ + cp] = __float2half_rn(s);
}

// ============================================================
// host launch
// ============================================================
extern "C" void kernel_launch(void* const* d_in, const int* in_sizes, int n_in,
                              void* d_out, int out_size) {
    const float* x    = (const float*)d_in[0];
    const float* gnw  = (const float*)d_in[1];
    const float* gnb  = (const float*)d_in[2];
    const float* qkvW = (const float*)d_in[3];
    const float* ow   = (const float*)d_in[4];
    const float* ob   = (const float*)d_in[5];
    float* out = (float*)d_out;

    float *pK, *pV, *pBiasp;
    __half *pXT, *pQT, *pWp, *pW2;
    cudaGetSymbolAddress((void**)&pK, d_k);
    cudaGetSymbolAddress((void**)&pV, d_v);
    cudaGetSymbolAddress((void**)&pBiasp, d_biasp);
    cudaGetSymbolAddress((void**)&pXT, d_xT);
    cudaGetSymbolAddress((void**)&pQT, d_qT);
    cudaGetSymbolAddress((void**)&pWp, d_Wp);
    cudaGetSymbolAddress((void**)&pW2, d_W2);

    cudaFuncSetAttribute(gemm_mma<1>, cudaFuncAttributeMaxDynamicSharedMemorySize, GEMM_SMEM_Q);
    cudaFuncSetAttribute(gemm_mma<2>, cudaFuncAttributeMaxDynamicSharedMemorySize, GEMM_SMEM);

    gn_stats1<<<dim3(64, 16), 256>>>(x);
    gn_stats2<<<16, 64>>>(gnw, gnb);
    build_wp<<<dim3(768, 4), 256>>>(qkvW);
    tconv<<<dim3(1024, 8, 4), dim3(32, 8)>>>(x, pXT);

    // qkv: grid (mt fastest for B L2 reuse). q -> qT fp16 direct; k,v -> fp32.
    gemm_mma<1><<<dim3(6, 256, 4), 256, GEMM_SMEM_Q>>>(pWp, pXT,
                                                       pBiasp, nullptr, pQT, pK, pV, nullptr, 768);

    krow_stats<<<1024, 256>>>();
    sim_partial<<<dim3(16, 32), 256>>>();
    sim_reduce<<<32, 1024>>>();
    build_w2<<<dim3(256, 4), 256>>>(ow);

    // out: W2 @ qT^T + ob + x
    gemm_mma<2><<<dim3(2, 256, 4), 256, GEMM_SMEM>>>(pW2, pQT,
                                                     ob, x, nullptr, nullptr, nullptr, out, 256);
}

// round 6
// speedup vs baseline: 3.1089x; 1.0172x over previous
#include <cuda_runtime.h>
#include <cuda_fp16.h>
#include <cstdint>

// Problem constants
static constexpr int B_ = 4;
static constexpr int C_ = 256;
static constexpr int N_ = 32768;     // 32*32*32
static constexpr int H_ = 8;

// ---------------- device scratch (no allocations allowed) ----------------
__device__ __half d_kh[(long)B_ * C_ * N_];        // k fp16 [b][c][n]
__device__ __half d_vh[(long)B_ * C_ * N_];        // v fp16
__device__ __half d_xT[(long)B_ * N_ * C_];        // xT [b][n][c] fp16
__device__ __half d_qT[(long)B_ * N_ * C_];        // qT fp16
__device__ __half d_Wp[B_ * 768 * C_];             // GN-folded qkv weight fp16
__device__ float d_biasp[B_ * 768];
__device__ __half d_W2[B_ * C_ * C_];              // fused sim+out_proj weight fp16
__device__ float2 d_gpart[16 * 2048];              // GN partials (sum, sumsq)
__device__ float d_scale[B_ * C_];
__device__ float d_shift[B_ * C_];
__device__ float2 d_kms[B_ * C_ * 256];            // per-tile k (max, sumexp)
__device__ float d_m[B_ * C_];
__device__ float d_s[B_ * C_];
__device__ float d_simpart[B_ * H_ * 16 * 1024];
__device__ float d_sim[B_ * H_ * 1024];

// ---------------- PTX helpers ----------------
__device__ __forceinline__ uint32_t smem_u32(const void* p) {
    uint32_t a;
    asm("{ .reg .u64 t; cvta.to.shared.u64 t, %1; cvt.u32.u64 %0, t; }" : "=r"(a) : "l"(p));
    return a;
}
#define CP16(dst, src) asm volatile("cp.async.ca.shared.global [%0], [%1], 16;" :: "r"(dst), "l"(src))
#define CP_COMMIT()    asm volatile("cp.async.commit_group;")
#define CP_WAIT1()     asm volatile("cp.async.wait_group 1;")

__device__ __forceinline__ void ldm4(uint32_t* r, uint32_t addr) {
    asm volatile("ldmatrix.sync.aligned.m8n8.x4.shared.b16 {%0,%1,%2,%3}, [%4];"
        : "=r"(r[0]), "=r"(r[1]), "=r"(r[2]), "=r"(r[3]) : "r"(addr));
}
__device__ __forceinline__ void ldm2(uint32_t* r, uint32_t addr) {
    asm volatile("ldmatrix.sync.aligned.m8n8.x2.shared.b16 {%0,%1}, [%2];"
        : "=r"(r[0]), "=r"(r[1]) : "r"(addr));
}
__device__ __forceinline__ void mma_f16(float* d, const uint32_t* a, const uint32_t* b) {
    asm volatile(
        "mma.sync.aligned.m16n8k16.row.col.f32.f16.f16.f32 "
        "{%0,%1,%2,%3}, {%4,%5,%6,%7}, {%8,%9}, {%0,%1,%2,%3};"
        : "+f"(d[0]), "+f"(d[1]), "+f"(d[2]), "+f"(d[3])
        : "r"(a[0]), "r"(a[1]), "r"(a[2]), "r"(a[3]), "r"(b[0]), "r"(b[1]));
}

// ============================================================
// Fused: x transpose->fp16 xT  +  GroupNorm partial stats.
// grid (1024, 8, 4), block (32, 8).
// ============================================================
__global__ void tconv_stats(const float* __restrict__ x, __half* __restrict__ dst) {
    __shared__ float t[32][33];
    __shared__ float rs[256], rss[256];
    int n0 = blockIdx.x * 32, c0 = blockIdx.y * 32, b = blockIdx.z;
    const float* s = x + (long)b * C_ * N_;
    int tx = threadIdx.x, ty = threadIdx.y;
    int tid = ty * 32 + tx;
    float sum = 0.f, ss = 0.f;
    #pragma unroll
    for (int i = 0; i < 4; i++) {
        int c = c0 + ty + i * 8;
        float v = s[(long)c * N_ + n0 + tx];
        t[ty + i * 8][tx] = v;
        sum += v; ss += v * v;
    }
    rs[tid] = sum; rss[tid] = ss;
    __syncthreads();
    __half* ph = dst + (long)b * N_ * C_;
    #pragma unroll
    for (int i = 0; i < 4; i++) {
        int n = n0 + ty + i * 8;
        ph[(long)n * C_ + c0 + tx] = __float2half_rn(t[tx][ty + i * 8]);
    }
    for (int st = 128; st > 0; st >>= 1) {
        if (tid < st) { rs[tid] += rs[tid + st]; rss[tid] += rss[tid + st]; }
        __syncthreads();
    }
    if (tid == 0) {
        int bg = b * 4 + (blockIdx.y >> 1);
        int idx = blockIdx.x * 2 + (blockIdx.y & 1);
        d_gpart[bg * 2048 + idx] = make_float2(rs[0], rss[0]);
    }
}

// ============================================================
// finalize GN stats -> scale/shift. grid 16, 256 threads.
// ============================================================
__global__ void gn_stats2(const float* __restrict__ gnw, const float* __restrict__ gnb) {
    int bg = blockIdx.x, tid = threadIdx.x;
    __shared__ float rs[256], rss[256];
    float s = 0.f, ss = 0.f;
    for (int i = tid; i < 2048; i += 256) {
        float2 p = d_gpart[bg * 2048 + i];
        s += p.x; ss += p.y;
    }
    rs[tid] = s; rss[tid] = ss;
    __syncthreads();
    for (int st = 128; st > 0; st >>= 1) {
        if (tid < st) { rs[tid] += rs[tid + st]; rss[tid] += rss[tid + st]; }
        __syncthreads();
    }
    if (tid < 64) {
        float inv = 1.0f / (float)(64L * N_);
        float mean = rs[0] * inv;
        float var = rss[0] * inv - mean * mean;
        float rstd = rsqrtf(var + 1e-5f);
        int b = bg >> 2, g = bg & 3;
        int c = g * 64 + tid;
        float sc = rstd * gnw[c];
        d_scale[b * C_ + c] = sc;
        d_shift[b * C_ + c] = gnb[c] - mean * sc;
    }
}

// ============================================================
// GN-folded qkv weight (fp16) + folded bias
// ============================================================
__global__ void build_wp(const float* __restrict__ W) {
    int o = blockIdx.x, b = blockIdx.y, c = threadIdx.x;
    float w = W[o * C_ + c];
    d_Wp[((long)b * 768 + o) * C_ + c] = __float2half_rn(w * d_scale[b * C_ + c]);
    __shared__ float red[256];
    red[c] = w * d_shift[b * C_ + c];
    __syncthreads();
    for (int st = 128; st > 0; st >>= 1) {
        if (c < st) red[c] += red[c + st];
        __syncthreads();
    }
    if (c == 0) d_biasp[b * 768 + o] = red[0];
}

// ============================================================
// fp16 GEMM via mma.sync: D[128x128] per CTA, fp32 accum.
// grid = (mt, nt, b)  [mt fastest -> B-tile L2 reuse]
// MODE 1 (qkv): mt 0-1 -> q -> transpose epilogue -> qT fp16.
//               mt 2-3 -> k fp16 + per-tile (max,sumexp) partials.
//               mt 4-5 -> v fp16.
// MODE 2: out = W2 @ qT^T + ob + residual (fp32).
// ============================================================
static constexpr int SKROW = 40;
static constexpr int TILE_BYTES = 128 * SKROW * 2;   // 10240
static constexpr int STAGE_BYTES = 2 * TILE_BYTES;
static constexpr int GEMM_SMEM = 2 * STAGE_BYTES;    // 40960
static constexpr int GEMM_SMEM_Q = 128 * 129 * 4;    // 66048 (>= 40960 + epilogue needs)

__device__ __forceinline__ void load_stage(
    uint32_t sbase, const __half* A, const __half* Bm, int kt, int tid)
{
    int k0 = kt * 32;
    #pragma unroll
    for (int it = 0; it < 2; it++) {
        int i = tid + it * 256;
        int row = i >> 2, c = i & 3;
        uint32_t doff = row * (SKROW * 2) + c * 16;
        long goff = (long)row * 256 + k0 + c * 8;
        CP16(sbase + doff,              A + goff);
        CP16(sbase + TILE_BYTES + doff, Bm + goff);
    }
}

template <int MODE>
__global__ void __launch_bounds__(256, 2) gemm_mma(
    const __half* __restrict__ Amat, const __half* __restrict__ Bmat,
    const float* __restrict__ bias, const float* __restrict__ resid,
    __half* __restrict__ outQT,
    __half* __restrict__ outK, __half* __restrict__ outV,
    float* __restrict__ outO, int Mtotal)
{
    extern __shared__ char smem[];
    uint32_t sb = smem_u32(smem);
    int tid = threadIdx.x;
    int warp = tid >> 5, lane = tid & 31;
    int wm = (warp >> 2) * 64;
    int wn = (warp & 3) * 32;
    int mt = blockIdx.x, nt = blockIdx.y, b = blockIdx.z;

    const __half* A = Amat + (long)b * Mtotal * 256 + (long)mt * 128 * 256;
    const __half* Bm = Bmat + (long)b * N_ * 256 + (long)nt * 128 * 256;

    float acc[4][4][4];
    #pragma unroll
    for (int i = 0; i < 4; i++)
        #pragma unroll
        for (int j = 0; j < 4; j++)
            #pragma unroll
            for (int e = 0; e < 4; e++) acc[i][j][e] = 0.f;

    load_stage(sb, A, Bm, 0, tid); CP_COMMIT();
    load_stage(sb + STAGE_BYTES, A, Bm, 1, tid); CP_COMMIT();

    int quad = lane >> 3, qr = lane & 7;
    int a_row = wm + (quad & 1) * 8 + qr;
    int a_colb = (quad >> 1) * 16;
    int bl8 = lane & 15;
    int b_row = wn + (bl8 & 7);
    int b_colb = (bl8 >> 3) * 16;

    #pragma unroll 1
    for (int kt = 0; kt < 8; kt++) {
        CP_WAIT1();
        __syncthreads();
        uint32_t base = sb + (kt & 1) * STAGE_BYTES;
        uint32_t aS = base, bS = base + TILE_BYTES;
        #pragma unroll
        for (int k16 = 0; k16 < 2; k16++) {
            uint32_t acol = a_colb + k16 * 32;
            uint32_t bcol = b_colb + k16 * 32;
            uint32_t ah[4][4], bh[4][2];
            #pragma unroll
            for (int mf = 0; mf < 4; mf++)
                ldm4(ah[mf], aS + (a_row + mf * 16) * (SKROW * 2) + acol);
            #pragma unroll
            for (int nf = 0; nf < 4; nf++)
                ldm2(bh[nf], bS + (b_row + nf * 8) * (SKROW * 2) + bcol);
            #pragma unroll
            for (int mf = 0; mf < 4; mf++)
                #pragma unroll
                for (int nf = 0; nf < 4; nf++)
                    mma_f16(acc[mf][nf], ah[mf], bh[nf]);
        }
        __syncthreads();
        if (kt + 2 < 8)
            load_stage(sb + (kt & 1) * STAGE_BYTES, A, Bm, kt + 2, tid);
        CP_COMMIT();
    }
    asm volatile("cp.async.wait_group 0;");

    if (MODE == 1 && mt < 2) {
        // ---- q path: transpose through smem, write qT fp16 ----
        float* smem_t = (float*)smem;   // [128][129]
        __syncthreads();
        #pragma unroll
        for (int mf = 0; mf < 4; mf++) {
            int rbase = wm + mf * 16 + (lane >> 2);
            #pragma unroll
            for (int half = 0; half < 2; half++) {
                int m = rbase + half * 8;
                float bv = bias[b * 768 + mt * 128 + m];
                #pragma unroll
                for (int nf = 0; nf < 4; nf++) {
                    int n = wn + nf * 8 + 2 * (lane & 3);
                    smem_t[m * 129 + n]     = acc[mf][nf][half * 2 + 0] + bv;
                    smem_t[m * 129 + n + 1] = acc[mf][nf][half * 2 + 1] + bv;
                }
            }
        }
        __syncthreads();
        int j = tid & 127, hf = tid >> 7;
        long gn = (long)nt * 128 + j;
        __half* ph = outQT + ((long)b * N_ + gn) * 256 + mt * 128 + hf * 64;
        #pragma unroll
        for (int ch = 0; ch < 8; ch++) {
            __align__(16) __half hb[8];
            #pragma unroll
            for (int e = 0; e < 8; e++)
                hb[e] = __float2half_rn(smem_t[(hf * 64 + ch * 8 + e) * 129 + j]);
            *(uint4*)(ph + ch * 8) = *(const uint4*)hb;
        }
        return;
    }

    if (MODE == 1) {
        // ---- k/v path: write fp16; k also per-tile (max,sumexp) partials ----
        bool isK = (mt < 4);
        int c_base = isK ? (mt - 2) * 128 : (mt - 4) * 128;
        __half* outH = isK ? outK : outV;
        float2* sms = (float2*)smem;    // [128][4]
        __syncthreads();
        #pragma unroll
        for (int mf = 0; mf < 4; mf++) {
            #pragma unroll
            for (int half = 0; half < 2; half++) {
                int r = wm + mf * 16 + half * 8 + (lane >> 2);
                float bv = bias[b * 768 + mt * 128 + r];
                __half* dst = outH + ((long)b * C_ + c_base + r) * N_ + (long)nt * 128;
                float vv[8];
                #pragma unroll
                for (int nf = 0; nf < 4; nf++) {
                    int n = wn + nf * 8 + 2 * (lane & 3);
                    // round-trip so stats match what sim reads
                    __half h0 = __float2half_rn(acc[mf][nf][half * 2 + 0] + bv);
                    __half h1 = __float2half_rn(acc[mf][nf][half * 2 + 1] + bv);
                    *(__half2*)&dst[n] = __halves2half2(h0, h1);
                    vv[nf * 2 + 0] = __half2float(h0);
                    vv[nf * 2 + 1] = __half2float(h1);
                }
                if (isK) {
                    float m = vv[0];
                    #pragma unroll
                    for (int e = 1; e < 8; e++) m = fmaxf(m, vv[e]);
                    float s = 0.f;
                    #pragma unroll
                    for (int e = 0; e < 8; e++) s += __expf(vv[e] - m);
                    #pragma unroll
                    for (int dlt = 1; dlt <= 2; dlt <<= 1) {
                        float m2 = __shfl_xor_sync(0xffffffffu, m, dlt);
                        float s2 = __shfl_xor_sync(0xffffffffu, s, dlt);
                        float M = fmaxf(m, m2);
                        s = s * __expf(m - M) + s2 * __expf(m2 - M);
                        m = M;
                    }
                    if ((lane & 3) == 0) sms[r * 4 + (warp & 3)] = make_float2(m, s);
                }
            }
        }
        if (isK) {
            __syncthreads();
            if (tid < 128) {
                float2 p0 = sms[tid * 4 + 0], p1 = sms[tid * 4 + 1];
                float2 p2 = sms[tid * 4 + 2], p3 = sms[tid * 4 + 3];
                float M01 = fmaxf(p0.x, p1.x);
                float s01 = p0.y * __expf(p0.x - M01) + p1.y * __expf(p1.x - M01);
                float M23 = fmaxf(p2.x, p3.x);
                float s23 = p2.y * __expf(p2.x - M23) + p3.y * __expf(p3.x - M23);
                float M = fmaxf(M01, M23);
                float S = s01 * __expf(M01 - M) + s23 * __expf(M23 - M);
                d_kms[((long)b * C_ + c_base + tid) * 256 + nt] = make_float2(M, S);
            }
        }
        return;
    }

    // MODE 2 epilogue: fp32 out + bias + residual
    #pragma unroll
    for (int mf = 0; mf < 4; mf++) {
        #pragma unroll
        for (int half = 0; half < 2; half++) {
            int mrow = mt * 128 + wm + mf * 16 + half * 8 + (lane >> 2);
            float bv = bias[mrow];
            long base = ((long)b * C_ + mrow) * N_;
            float* dst = outO + base;
            const float* rp = resid + base;
            #pragma unroll
            for (int nf = 0; nf < 4; nf++) {
                int n = nt * 128 + wn + nf * 8 + 2 * (lane & 3);
                float2 rv = *(const float2*)&rp[n];
                float2 o;
                o.x = acc[mf][nf][half * 2 + 0] + bv + rv.x;
                o.y = acc[mf][nf][half * 2 + 1] + bv + rv.y;
                *(float2*)&dst[n] = o;
            }
        }
    }
}

// ============================================================
// reduce per-tile k stats -> d_m, d_s. grid 1024, 256 threads.
// ============================================================
__global__ void krow_reduce() {
    int row = blockIdx.x, tid = threadIdx.x;
    __shared__ float sm[256], ssum[256];
    float2 p = d_kms[(long)row * 256 + tid];
    sm[tid] = p.x; ssum[tid] = p.y;
    __syncthreads();
    for (int st = 128; st > 0; st >>= 1) {
        if (tid < st) {
            float m1 = sm[tid], m2 = sm[tid + st];
            float M = fmaxf(m1, m2);
            ssum[tid] = ssum[tid] * __expf(m1 - M) + ssum[tid + st] * __expf(m2 - M);
            sm[tid] = M;
        }
        __syncthreads();
    }
    if (tid == 0) { d_m[row] = sm[0]; d_s[row] = ssum[0]; }
}

// ============================================================
// sim[b,h,d,e] = sum_n exp(k[d,n]-m[d])*v[e,n] (fp16 in, split over n)
// ============================================================
__global__ void __launch_bounds__(256) sim_partial() {
    const int PAD = 68;
    __shared__ float ks[32][PAD], vs[32][PAD];
    __shared__ float ms[32];
    int sp = blockIdx.x, bh = blockIdx.y;
    int b = bh >> 3, h = bh & 7;
    const __half* kp = d_kh + ((long)b * C_ + h * 32) * N_;
    const __half* vp = d_vh + ((long)b * C_ + h * 32) * N_;
    int tid = threadIdx.x;
    if (tid < 32) ms[tid] = d_m[b * C_ + h * 32 + tid];
    int d2 = (tid >> 4) * 2, e2 = (tid & 15) * 2;
    float a00 = 0.f, a01 = 0.f, a10 = 0.f, a11 = 0.f;
    int nbeg = sp * 2048;
    for (int n0 = nbeg; n0 < nbeg + 2048; n0 += 64) {
        __syncthreads();
        for (int l = tid; l < 512; l += 256) {
            int dd = l >> 4, jj = (l & 15) * 4;
            float mrow = ms[dd];
            uint2 kraw = *(const uint2*)&kp[(long)dd * N_ + n0 + jj];
            float2 k0 = __half22float2(*(__half2*)&kraw.x);
            float2 k1 = __half22float2(*(__half2*)&kraw.y);
            float4 kv;
            kv.x = __expf(k0.x - mrow);
            kv.y = __expf(k0.y - mrow);
            kv.z = __expf(k1.x - mrow);
            kv.w = __expf(k1.y - mrow);
            *(float4*)&ks[dd][jj] = kv;
            uint2 vraw = *(const uint2*)&vp[(long)dd * N_ + n0 + jj];
            float2 v0 = __half22float2(*(__half2*)&vraw.x);
            float2 v1 = __half22float2(*(__half2*)&vraw.y);
            float4 vv; vv.x = v0.x; vv.y = v0.y; vv.z = v1.x; vv.w = v1.y;
            *(float4*)&vs[dd][jj] = vv;
        }
        __syncthreads();
        #pragma unroll
        for (int j = 0; j < 64; j += 4) {
            float4 x0 = *(const float4*)&ks[d2][j];
            float4 x1 = *(const float4*)&ks[d2 + 1][j];
            float4 y0 = *(const float4*)&vs[e2][j];
            float4 y1 = *(const float4*)&vs[e2 + 1][j];
            a00 += x0.x * y0.x + x0.y * y0.y + x0.z * y0.z + x0.w * y0.w;
            a01 += x0.x * y1.x + x0.y * y1.y + x0.z * y1.z + x0.w * y1.w;
            a10 += x1.x * y0.x + x1.y * y0.y + x1.z * y0.z + x1.w * y0.w;
            a11 += x1.x * y1.x + x1.y * y1.y + x1.z * y1.z + x1.w * y1.w;
        }
    }
    float* out = d_simpart + ((long)(bh * 16 + sp)) * 1024;
    out[(d2 + 0) * 32 + e2 + 0] = a00;
    out[(d2 + 0) * 32 + e2 + 1] = a01;
    out[(d2 + 1) * 32 + e2 + 0] = a10;
    out[(d2 + 1) * 32 + e2 + 1] = a11;
}

// reduce splits + divide by softmax denominator
__global__ void sim_reduce() {
    int bh = blockIdx.x, i = threadIdx.x;
    int b = bh >> 3, h = bh & 7;
    float s = 0.f;
    #pragma unroll
    for (int sp = 0; sp < 16; sp++)
        s += d_simpart[(long)(bh * 16 + sp) * 1024 + i];
    float inv = 1.0f / d_s[b * C_ + h * 32 + (i >> 5)];
    d_sim[bh * 1024 + i] = s * inv;
}

// ============================================================
// W2[b,o,h*32+d] = sum_e OW[o,h*32+e]*sim[b,h,d,e]  (fp16)
// ============================================================
__global__ void build_w2(const float* __restrict__ OW) {
    int o = blockIdx.x, b = blockIdx.y, cp = threadIdx.x;
    int h = cp >> 5, d = cp & 31;
    const float* simp = d_sim + ((long)((b * 8 + h) * 32 + d)) * 32;
    const float* owp = OW + o * C_ + h * 32;
    float s = 0.f;
    #pragma unroll
    for (int e = 0; e < 32; e++) s += owp[e] * simp[e];
    d_W2[((long)b * C_ + o) * C_ + cp] = __float2half_rn(s);
}

// ============================================================
// host launch
// ============================================================
extern "C" void kernel_launch(void* const* d_in, const int* in_sizes, int n_in,
                              void* d_out, int out_size) {
    const float* x    = (const float*)d_in[0];
    const float* gnw  = (const float*)d_in[1];
    const float* gnb  = (const float*)d_in[2];
    const float* qkvW = (const float*)d_in[3];
    const float* ow   = (const float*)d_in[4];
    const float* ob   = (const float*)d_in[5];
    float* out = (float*)d_out;

    float* pBiasp;
    __half *pKh, *pVh, *pXT, *pQT, *pWp, *pW2;
    cudaGetSymbolAddress((void**)&pKh, d_kh);
    cudaGetSymbolAddress((void**)&pVh, d_vh);
    cudaGetSymbolAddress((void**)&pBiasp, d_biasp);
    cudaGetSymbolAddress((void**)&pXT, d_xT);
    cudaGetSymbolAddress((void**)&pQT, d_qT);
    cudaGetSymbolAddress((void**)&pWp, d_Wp);
    cudaGetSymbolAddress((void**)&pW2, d_W2);

    cudaFuncSetAttribute(gemm_mma<1>, cudaFuncAttributeMaxDynamicSharedMemorySize, GEMM_SMEM_Q);
    cudaFuncSetAttribute(gemm_mma<2>, cudaFuncAttributeMaxDynamicSharedMemorySize, GEMM_SMEM);

    tconv_stats<<<dim3(1024, 8, 4), dim3(32, 8)>>>(x, pXT);
    gn_stats2<<<16, 256>>>(gnw, gnb);
    build_wp<<<dim3(768, 4), 256>>>(qkvW);

    // qkv: q -> qT fp16 direct; k,v -> fp16 (+k tile stats).
    gemm_mma<1><<<dim3(6, 256, 4), 256, GEMM_SMEM_Q>>>(pWp, pXT,
                                                       pBiasp, nullptr, pQT, pKh, pVh, nullptr, 768);

    krow_reduce<<<1024, 256>>>();
    sim_partial<<<dim3(16, 32), 256>>>();
    sim_reduce<<<32, 1024>>>();
    build_w2<<<dim3(256, 4), 256>>>(ow);

    // out: W2 @ qT^T + ob + x
    gemm_mma<2><<<dim3(2, 256, 4), 256, GEMM_SMEM>>>(pW2, pQT,
                                                     ob, x, nullptr, nullptr, nullptr, out, 256);
}

// round 7
// speedup vs baseline: 3.1983x; 1.0287x over previous
#include <cuda_runtime.h>
#include <cuda_fp16.h>
#include <cstdint>

// Problem constants
static constexpr int B_ = 4;
static constexpr int C_ = 256;
static constexpr int N_ = 32768;     // 32*32*32
static constexpr int H_ = 8;

// ---------------- device scratch (no allocations allowed) ----------------
__device__ __half d_kh[(long)B_ * C_ * N_];        // k fp16 [b][c][n]
__device__ __half d_vh[(long)B_ * C_ * N_];        // v fp16
__device__ __half d_xT[(long)B_ * N_ * C_];        // xT [b][n][c] fp16
__device__ __half d_qT[(long)B_ * N_ * C_];        // qT fp16
__device__ __half d_Wp[B_ * 768 * C_];             // GN-folded qkv weight fp16
__device__ float d_biasp[B_ * 768];
__device__ __half d_W2[B_ * C_ * C_];              // fused sim+out_proj weight fp16
__device__ float2 d_gpart[16 * 2048];              // GN partials (sum, sumsq)
__device__ float d_scale[B_ * C_];
__device__ float d_shift[B_ * C_];
__device__ float2 d_kms[B_ * C_ * 256];            // per-tile k (max, sumexp)
__device__ float d_m[B_ * C_];
__device__ float d_s[B_ * C_];
__device__ float d_simpart[B_ * H_ * 16 * 1024];
__device__ float d_sim[B_ * H_ * 1024];

// ---------------- PTX helpers ----------------
__device__ __forceinline__ uint32_t smem_u32(const void* p) {
    uint32_t a;
    asm("{ .reg .u64 t; cvta.to.shared.u64 t, %1; cvt.u32.u64 %0, t; }" : "=r"(a) : "l"(p));
    return a;
}
#define CP16(dst, src) asm volatile("cp.async.cg.shared.global [%0], [%1], 16;" :: "r"(dst), "l"(src))
#define CP_COMMIT()    asm volatile("cp.async.commit_group;")

__device__ __forceinline__ void ldm4(uint32_t* r, uint32_t addr) {
    asm volatile("ldmatrix.sync.aligned.m8n8.x4.shared.b16 {%0,%1,%2,%3}, [%4];"
        : "=r"(r[0]), "=r"(r[1]), "=r"(r[2]), "=r"(r[3]) : "r"(addr));
}
__device__ __forceinline__ void mma_f16(float* d, const uint32_t* a, const uint32_t* b) {
    asm volatile(
        "mma.sync.aligned.m16n8k16.row.col.f32.f16.f16.f32 "
        "{%0,%1,%2,%3}, {%4,%5,%6,%7}, {%8,%9}, {%0,%1,%2,%3};"
        : "+f"(d[0]), "+f"(d[1]), "+f"(d[2]), "+f"(d[3])
        : "r"(a[0]), "r"(a[1]), "r"(a[2]), "r"(a[3]), "r"(b[0]), "r"(b[1]));
}

// ============================================================
// Fused: x transpose->fp16 xT  +  GroupNorm partial stats.
// ============================================================
__global__ void tconv_stats(const float* __restrict__ x, __half* __restrict__ dst) {
    __shared__ float t[32][33];
    __shared__ float rs[256], rss[256];
    int n0 = blockIdx.x * 32, c0 = blockIdx.y * 32, b = blockIdx.z;
    const float* s = x + (long)b * C_ * N_;
    int tx = threadIdx.x, ty = threadIdx.y;
    int tid = ty * 32 + tx;
    float sum = 0.f, ss = 0.f;
    #pragma unroll
    for (int i = 0; i < 4; i++) {
        int c = c0 + ty + i * 8;
        float v = s[(long)c * N_ + n0 + tx];
        t[ty + i * 8][tx] = v;
        sum += v; ss += v * v;
    }
    rs[tid] = sum; rss[tid] = ss;
    __syncthreads();
    __half* ph = dst + (long)b * N_ * C_;
    #pragma unroll
    for (int i = 0; i < 4; i++) {
        int n = n0 + ty + i * 8;
        ph[(long)n * C_ + c0 + tx] = __float2half_rn(t[tx][ty + i * 8]);
    }
    for (int st = 128; st > 0; st >>= 1) {
        if (tid < st) { rs[tid] += rs[tid + st]; rss[tid] += rss[tid + st]; }
        __syncthreads();
    }
    if (tid == 0) {
        int bg = b * 4 + (blockIdx.y >> 1);
        int idx = blockIdx.x * 2 + (blockIdx.y & 1);
        d_gpart[bg * 2048 + idx] = make_float2(rs[0], rss[0]);
    }
}

// ============================================================
// finalize GN stats -> scale/shift
// ============================================================
__global__ void gn_stats2(const float* __restrict__ gnw, const float* __restrict__ gnb) {
    int bg = blockIdx.x, tid = threadIdx.x;
    __shared__ float rs[256], rss[256];
    float s = 0.f, ss = 0.f;
    for (int i = tid; i < 2048; i += 256) {
        float2 p = d_gpart[bg * 2048 + i];
        s += p.x; ss += p.y;
    }
    rs[tid] = s; rss[tid] = ss;
    __syncthreads();
    for (int st = 128; st > 0; st >>= 1) {
        if (tid < st) { rs[tid] += rs[tid + st]; rss[tid] += rss[tid + st]; }
        __syncthreads();
    }
    if (tid < 64) {
        float inv = 1.0f / (float)(64L * N_);
        float mean = rs[0] * inv;
        float var = rss[0] * inv - mean * mean;
        float rstd = rsqrtf(var + 1e-5f);
        int b = bg >> 2, g = bg & 3;
        int c = g * 64 + tid;
        float sc = rstd * gnw[c];
        d_scale[b * C_ + c] = sc;
        d_shift[b * C_ + c] = gnb[c] - mean * sc;
    }
}

// ============================================================
// GN-folded qkv weight (fp16) + folded bias
// ============================================================
__global__ void build_wp(const float* __restrict__ W) {
    int o = blockIdx.x, b = blockIdx.y, c = threadIdx.x;
    float w = W[o * C_ + c];
    d_Wp[((long)b * 768 + o) * C_ + c] = __float2half_rn(w * d_scale[b * C_ + c]);
    __shared__ float red[256];
    red[c] = w * d_shift[b * C_ + c];
    __syncthreads();
    for (int st = 128; st > 0; st >>= 1) {
        if (c < st) red[c] += red[c + st];
        __syncthreads();
    }
    if (c == 0) d_biasp[b * 768 + o] = red[0];
}

// ============================================================
// fp16 GEMM via mma.sync, 4-stage cp.async.cg pipeline.
// ============================================================
static constexpr int SKROW = 40;
static constexpr int TILE_BYTES = 128 * SKROW * 2;   // 10240
static constexpr int STAGE_BYTES = 2 * TILE_BYTES;   // 20480
static constexpr int NSTAGE = 4;
static constexpr int GEMM_SMEM = NSTAGE * STAGE_BYTES;   // 81920 (> q-epi 66048)

__device__ __forceinline__ void load_stage(
    uint32_t sbase, const __half* A, const __half* Bm, int kt, int tid)
{
    int k0 = kt * 32;
    #pragma unroll
    for (int it = 0; it < 2; it++) {
        int i = tid + it * 256;
        int row = i >> 2, c = i & 3;
        uint32_t doff = row * (SKROW * 2) + c * 16;
        long goff = (long)row * 256 + k0 + c * 8;
        CP16(sbase + doff,              A + goff);
        CP16(sbase + TILE_BYTES + doff, Bm + goff);
    }
}

template <int MODE>
__global__ void __launch_bounds__(256, 2) gemm_mma(
    const __half* __restrict__ Amat, const __half* __restrict__ Bmat,
    const float* __restrict__ bias, const float* __restrict__ resid,
    __half* __restrict__ outQT,
    __half* __restrict__ outK, __half* __restrict__ outV,
    float* __restrict__ outO, int Mtotal)
{
    extern __shared__ char smem[];
    uint32_t sb = smem_u32(smem);
    int tid = threadIdx.x;
    int warp = tid >> 5, lane = tid & 31;
    int wm = (warp >> 2) * 64;
    int wn = (warp & 3) * 32;
    int mt = blockIdx.x, nt = blockIdx.y, b = blockIdx.z;

    const __half* A = Amat + (long)b * Mtotal * 256 + (long)mt * 128 * 256;
    const __half* Bm = Bmat + (long)b * N_ * 256 + (long)nt * 128 * 256;

    float acc[4][4][4];
    #pragma unroll
    for (int i = 0; i < 4; i++)
        #pragma unroll
        for (int j = 0; j < 4; j++)
            #pragma unroll
            for (int e = 0; e < 4; e++) acc[i][j][e] = 0.f;

    // prologue: fill 3 of 4 stages
    load_stage(sb + 0 * STAGE_BYTES, A, Bm, 0, tid); CP_COMMIT();
    load_stage(sb + 1 * STAGE_BYTES, A, Bm, 1, tid); CP_COMMIT();
    load_stage(sb + 2 * STAGE_BYTES, A, Bm, 2, tid); CP_COMMIT();

    // A ldmatrix lane addressing (x4: 16x16 tile)
    int quad = lane >> 3, qr = lane & 7;
    int a_row = wm + (quad & 1) * 8 + qr;
    int a_colb = (quad >> 1) * 16;
    // B ldmatrix x4 (two nf tiles per load): lane bits b3=k-half, b4=nf-within-pair
    int b_row = wn + ((lane >> 4) & 1) * 8 + (lane & 7);
    int b_colb = ((lane >> 3) & 1) * 16;

    #pragma unroll 1
    for (int kt = 0; kt < 8; kt++) {
        asm volatile("cp.async.wait_group 2;");
        __syncthreads();
        if (kt + 3 < 8)
            load_stage(sb + ((kt + 3) & 3) * STAGE_BYTES, A, Bm, kt + 3, tid);
        CP_COMMIT();

        uint32_t base = sb + (kt & 3) * STAGE_BYTES;
        uint32_t aS = base, bS = base + TILE_BYTES;
        #pragma unroll
        for (int k16 = 0; k16 < 2; k16++) {
            uint32_t acol = a_colb + k16 * 32;
            uint32_t bcol = b_colb + k16 * 32;
            uint32_t ah[4][4], bh[4][2];
            #pragma unroll
            for (int mf = 0; mf < 4; mf++)
                ldm4(ah[mf], aS + (a_row + mf * 16) * (SKROW * 2) + acol);
            #pragma unroll
            for (int nfp = 0; nfp < 2; nfp++) {
                uint32_t r4[4];
                ldm4(r4, bS + (b_row + nfp * 16) * (SKROW * 2) + bcol);
                bh[nfp * 2 + 0][0] = r4[0]; bh[nfp * 2 + 0][1] = r4[1];
                bh[nfp * 2 + 1][0] = r4[2]; bh[nfp * 2 + 1][1] = r4[3];
            }
            #pragma unroll
            for (int mf = 0; mf < 4; mf++)
                #pragma unroll
                for (int nf = 0; nf < 4; nf++)
                    mma_f16(acc[mf][nf], ah[mf], bh[nf]);
        }
    }
    asm volatile("cp.async.wait_group 0;");

    if (MODE == 1 && mt < 2) {
        // ---- q path: transpose through smem, write qT fp16 ----
        float* smem_t = (float*)smem;   // [128][129]
        __syncthreads();
        #pragma unroll
        for (int mf = 0; mf < 4; mf++) {
            int rbase = wm + mf * 16 + (lane >> 2);
            #pragma unroll
            for (int half = 0; half < 2; half++) {
                int m = rbase + half * 8;
                float bv = bias[b * 768 + mt * 128 + m];
                #pragma unroll
                for (int nf = 0; nf < 4; nf++) {
                    int n = wn + nf * 8 + 2 * (lane & 3);
                    smem_t[m * 129 + n]     = acc[mf][nf][half * 2 + 0] + bv;
                    smem_t[m * 129 + n + 1] = acc[mf][nf][half * 2 + 1] + bv;
                }
            }
        }
        __syncthreads();
        int j = tid & 127, hf = tid >> 7;
        long gn = (long)nt * 128 + j;
        __half* ph = outQT + ((long)b * N_ + gn) * 256 + mt * 128 + hf * 64;
        #pragma unroll
        for (int ch = 0; ch < 8; ch++) {
            __align__(16) __half hb[8];
            #pragma unroll
            for (int e = 0; e < 8; e++)
                hb[e] = __float2half_rn(smem_t[(hf * 64 + ch * 8 + e) * 129 + j]);
            *(uint4*)(ph + ch * 8) = *(const uint4*)hb;
        }
        return;
    }

    if (MODE == 1) {
        // ---- k/v path: write fp16; k also per-tile (max,sumexp) partials ----
        bool isK = (mt < 4);
        int c_base = isK ? (mt - 2) * 128 : (mt - 4) * 128;
        __half* outH = isK ? outK : outV;
        float2* sms = (float2*)smem;    // [128][4]
        __syncthreads();
        #pragma unroll
        for (int mf = 0; mf < 4; mf++) {
            #pragma unroll
            for (int half = 0; half < 2; half++) {
                int r = wm + mf * 16 + half * 8 + (lane >> 2);
                float bv = bias[b * 768 + mt * 128 + r];
                __half* dst = outH + ((long)b * C_ + c_base + r) * N_ + (long)nt * 128;
                float vv[8];
                #pragma unroll
                for (int nf = 0; nf < 4; nf++) {
                    int n = wn + nf * 8 + 2 * (lane & 3);
                    __half h0 = __float2half_rn(acc[mf][nf][half * 2 + 0] + bv);
                    __half h1 = __float2half_rn(acc[mf][nf][half * 2 + 1] + bv);
                    *(__half2*)&dst[n] = __halves2half2(h0, h1);
                    vv[nf * 2 + 0] = __half2float(h0);
                    vv[nf * 2 + 1] = __half2float(h1);
                }
                if (isK) {
                    float m = vv[0];
                    #pragma unroll
                    for (int e = 1; e < 8; e++) m = fmaxf(m, vv[e]);
                    float s = 0.f;
                    #pragma unroll
                    for (int e = 0; e < 8; e++) s += __expf(vv[e] - m);
                    #pragma unroll
                    for (int dlt = 1; dlt <= 2; dlt <<= 1) {
                        float m2 = __shfl_xor_sync(0xffffffffu, m, dlt);
                        float s2 = __shfl_xor_sync(0xffffffffu, s, dlt);
                        float M = fmaxf(m, m2);
                        s = s * __expf(m - M) + s2 * __expf(m2 - M);
                        m = M;
                    }
                    if ((lane & 3) == 0) sms[r * 4 + (warp & 3)] = make_float2(m, s);
                }
            }
        }
        if (isK) {
            __syncthreads();
            if (tid < 128) {
                float2 p0 = sms[tid * 4 + 0], p1 = sms[tid * 4 + 1];
                float2 p2 = sms[tid * 4 + 2], p3 = sms[tid * 4 + 3];
                float M01 = fmaxf(p0.x, p1.x);
                float s01 = p0.y * __expf(p0.x - M01) + p1.y * __expf(p1.x - M01);
                float M23 = fmaxf(p2.x, p3.x);
                float s23 = p2.y * __expf(p2.x - M23) + p3.y * __expf(p3.x - M23);
                float M = fmaxf(M01, M23);
                float S = s01 * __expf(M01 - M) + s23 * __expf(M23 - M);
                d_kms[((long)b * C_ + c_base + tid) * 256 + nt] = make_float2(M, S);
            }
        }
        return;
    }

    // MODE 2 epilogue: fp32 out + bias + residual
    #pragma unroll
    for (int mf = 0; mf < 4; mf++) {
        #pragma unroll
        for (int half = 0; half < 2; half++) {
            int mrow = mt * 128 + wm + mf * 16 + half * 8 + (lane >> 2);
            float bv = bias[mrow];
            long base = ((long)b * C_ + mrow) * N_;
            float* dst = outO + base;
            const float* rp = resid + base;
            #pragma unroll
            for (int nf = 0; nf < 4; nf++) {
                int n = nt * 128 + wn + nf * 8 + 2 * (lane & 3);
                float2 rv = *(const float2*)&rp[n];
                float2 o;
                o.x = acc[mf][nf][half * 2 + 0] + bv + rv.x;
                o.y = acc[mf][nf][half * 2 + 1] + bv + rv.y;
                *(float2*)&dst[n] = o;
            }
        }
    }
}

// ============================================================
// reduce per-tile k stats -> d_m, d_s
// ============================================================
__global__ void krow_reduce() {
    int row = blockIdx.x, tid = threadIdx.x;
    __shared__ float sm[256], ssum[256];
    float2 p = d_kms[(long)row * 256 + tid];
    sm[tid] = p.x; ssum[tid] = p.y;
    __syncthreads();
    for (int st = 128; st > 0; st >>= 1) {
        if (tid < st) {
            float m1 = sm[tid], m2 = sm[tid + st];
            float M = fmaxf(m1, m2);
            ssum[tid] = ssum[tid] * __expf(m1 - M) + ssum[tid + st] * __expf(m2 - M);
            sm[tid] = M;
        }
        __syncthreads();
    }
    if (tid == 0) { d_m[row] = sm[0]; d_s[row] = ssum[0]; }
}

// ============================================================
// sim[b,h,d,e] = sum_n exp(k[d,n]-m[d])*v[e,n] (fp16 in, split over n)
// ============================================================
__global__ void __launch_bounds__(256) sim_partial() {
    const int PAD = 68;
    __shared__ float ks[32][PAD], vs[32][PAD];
    __shared__ float ms[32];
    int sp = blockIdx.x, bh = blockIdx.y;
    int b = bh >> 3, h = bh & 7;
    const __half* kp = d_kh + ((long)b * C_ + h * 32) * N_;
    const __half* vp = d_vh + ((long)b * C_ + h * 32) * N_;
    int tid = threadIdx.x;
    if (tid < 32) ms[tid] = d_m[b * C_ + h * 32 + tid];
    int d2 = (tid >> 4) * 2, e2 = (tid & 15) * 2;
    float a00 = 0.f, a01 = 0.f, a10 = 0.f, a11 = 0.f;
    int nbeg = sp * 2048;
    for (int n0 = nbeg; n0 < nbeg + 2048; n0 += 64) {
        __syncthreads();
        for (int l = tid; l < 512; l += 256) {
            int dd = l >> 4, jj = (l & 15) * 4;
            float mrow = ms[dd];
            uint2 kraw = *(const uint2*)&kp[(long)dd * N_ + n0 + jj];
            float2 k0 = __half22float2(*(__half2*)&kraw.x);
            float2 k1 = __half22float2(*(__half2*)&kraw.y);
            float4 kv;
            kv.x = __expf(k0.x - mrow);
            kv.y = __expf(k0.y - mrow);
            kv.z = __expf(k1.x - mrow);
            kv.w = __expf(k1.y - mrow);
            *(float4*)&ks[dd][jj] = kv;
            uint2 vraw = *(const uint2*)&vp[(long)dd * N_ + n0 + jj];
            float2 v0 = __half22float2(*(__half2*)&vraw.x);
            float2 v1 = __half22float2(*(__half2*)&vraw.y);
            float4 vv; vv.x = v0.x; vv.y = v0.y; vv.z = v1.x; vv.w = v1.y;
            *(float4*)&vs[dd][jj] = vv;
        }
        __syncthreads();
        #pragma unroll
        for (int j = 0; j < 64; j += 4) {
            float4 x0 = *(const float4*)&ks[d2][j];
            float4 x1 = *(const float4*)&ks[d2 + 1][j];
            float4 y0 = *(const float4*)&vs[e2][j];
            float4 y1 = *(const float4*)&vs[e2 + 1][j];
            a00 += x0.x * y0.x + x0.y * y0.y + x0.z * y0.z + x0.w * y0.w;
            a01 += x0.x * y1.x + x0.y * y1.y + x0.z * y1.z + x0.w * y1.w;
            a10 += x1.x * y0.x + x1.y * y0.y + x1.z * y0.z + x1.w * y0.w;
            a11 += x1.x * y1.x + x1.y * y1.y + x1.z * y1.z + x1.w * y1.w;
        }
    }
    float* out = d_simpart + ((long)(bh * 16 + sp)) * 1024;
    out[(d2 + 0) * 32 + e2 + 0] = a00;
    out[(d2 + 0) * 32 + e2 + 1] = a01;
    out[(d2 + 1) * 32 + e2 + 0] = a10;
    out[(d2 + 1) * 32 + e2 + 1] = a11;
}

// reduce splits + divide by softmax denominator
__global__ void sim_reduce() {
    int bh = blockIdx.x, i = threadIdx.x;
    int b = bh >> 3, h = bh & 7;
    float s = 0.f;
    #pragma unroll
    for (int sp = 0; sp < 16; sp++)
        s += d_simpart[(long)(bh * 16 + sp) * 1024 + i];
    float inv = 1.0f / d_s[b * C_ + h * 32 + (i >> 5)];
    d_sim[bh * 1024 + i] = s * inv;
}

// ============================================================
// W2[b,o,h*32+d] = sum_e OW[o,h*32+e]*sim[b,h,d,e]  (fp16)
// ============================================================
__global__ void build_w2(const float* __restrict__ OW) {
    int o = blockIdx.x, b = blockIdx.y, cp = threadIdx.x;
    int h = cp >> 5, d = cp & 31;
    const float* simp = d_sim + ((long)((b * 8 + h) * 32 + d)) * 32;
    const float* owp = OW + o * C_ + h * 32;
    float s = 0.f;
    #pragma unroll
    for (int e = 0; e < 32; e++) s += owp[e] * simp[e];
    d_W2[((long)b * C_ + o) * C_ + cp] = __float2half_rn(s);
}

// ============================================================
// host launch
// ============================================================
extern "C" void kernel_launch(void* const* d_in, const int* in_sizes, int n_in,
                              void* d_out, int out_size) {
    const float* x    = (const float*)d_in[0];
    const float* gnw  = (const float*)d_in[1];
    const float* gnb  = (const float*)d_in[2];
    const float* qkvW = (const float*)d_in[3];
    const float* ow   = (const float*)d_in[4];
    const float* ob   = (const float*)d_in[5];
    float* out = (float*)d_out;

    float* pBiasp;
    __half *pKh, *pVh, *pXT, *pQT, *pWp, *pW2;
    cudaGetSymbolAddress((void**)&pKh, d_kh);
    cudaGetSymbolAddress((void**)&pVh, d_vh);
    cudaGetSymbolAddress((void**)&pBiasp, d_biasp);
    cudaGetSymbolAddress((void**)&pXT, d_xT);
    cudaGetSymbolAddress((void**)&pQT, d_qT);
    cudaGetSymbolAddress((void**)&pWp, d_Wp);
    cudaGetSymbolAddress((void**)&pW2, d_W2);

    cudaFuncSetAttribute(gemm_mma<1>, cudaFuncAttributeMaxDynamicSharedMemorySize, GEMM_SMEM);
    cudaFuncSetAttribute(gemm_mma<2>, cudaFuncAttributeMaxDynamicSharedMemorySize, GEMM_SMEM);

    tconv_stats<<<dim3(1024, 8, 4), dim3(32, 8)>>>(x, pXT);
    gn_stats2<<<16, 256>>>(gnw, gnb);
    build_wp<<<dim3(768, 4), 256>>>(qkvW);

    // qkv: q -> qT fp16 direct; k,v -> fp16 (+k tile stats).
    gemm_mma<1><<<dim3(6, 256, 4), 256, GEMM_SMEM>>>(pWp, pXT,
                                                     pBiasp, nullptr, pQT, pKh, pVh, nullptr, 768);

    krow_reduce<<<1024, 256>>>();
    sim_partial<<<dim3(16, 32), 256>>>();
    sim_reduce<<<32, 1024>>>();
    build_w2<<<dim3(256, 4), 256>>>(ow);

    // out: W2 @ qT^T + ob + x
    gemm_mma<2><<<dim3(2, 256, 4), 256, GEMM_SMEM>>>(pW2, pQT,
                                                     ob, x, nullptr, nullptr, nullptr, out, 256);
}

// round 8
// speedup vs baseline: 3.4404x; 1.0757x over previous
#include <cuda_runtime.h>
#include <cuda_fp16.h>
#include <cstdint>

// Problem constants
static constexpr int B_ = 4;
static constexpr int C_ = 256;
static constexpr int N_ = 32768;     // 32*32*32
static constexpr int H_ = 8;

// ---------------- device scratch (no allocations allowed) ----------------
__device__ __half d_kh[(long)B_ * C_ * N_];        // k fp16 [b][c][n]
__device__ __half d_vh[(long)B_ * C_ * N_];        // v fp16
__device__ __half d_xT[(long)B_ * N_ * C_];        // xT [b][n][c] fp16
__device__ __half d_Wp[B_ * 768 * C_];             // GN-folded qkv weight fp16
__device__ float d_biasp[B_ * 768];
__device__ float d_W2f[B_ * C_ * C_];              // sim-fused out weight fp32
__device__ __half d_W3[B_ * C_ * C_];              // W2 @ Wq' fp16
__device__ float d_bias3[B_ * C_];
__device__ float2 d_gpart[16 * 2048];              // GN partials (sum, sumsq)
__device__ float d_scale[B_ * C_];
__device__ float d_shift[B_ * C_];
__device__ float2 d_kms[B_ * C_ * 256];            // per-tile k (max, sumexp)
__device__ float d_m[B_ * C_];
__device__ float d_s[B_ * C_];
__device__ float d_simpart[B_ * H_ * 16 * 1024];
__device__ float d_sim[B_ * H_ * 1024];

// ---------------- PTX helpers ----------------
__device__ __forceinline__ uint32_t smem_u32(const void* p) {
    uint32_t a;
    asm("{ .reg .u64 t; cvta.to.shared.u64 t, %1; cvt.u32.u64 %0, t; }" : "=r"(a) : "l"(p));
    return a;
}
#define CP16(dst, src) asm volatile("cp.async.cg.shared.global [%0], [%1], 16;" :: "r"(dst), "l"(src))
#define CP_COMMIT()    asm volatile("cp.async.commit_group;")

__device__ __forceinline__ void ldm4(uint32_t* r, uint32_t addr) {
    asm volatile("ldmatrix.sync.aligned.m8n8.x4.shared.b16 {%0,%1,%2,%3}, [%4];"
        : "=r"(r[0]), "=r"(r[1]), "=r"(r[2]), "=r"(r[3]) : "r"(addr));
}
__device__ __forceinline__ void mma_f16(float* d, const uint32_t* a, const uint32_t* b) {
    asm volatile(
        "mma.sync.aligned.m16n8k16.row.col.f32.f16.f16.f32 "
        "{%0,%1,%2,%3}, {%4,%5,%6,%7}, {%8,%9}, {%0,%1,%2,%3};"
        : "+f"(d[0]), "+f"(d[1]), "+f"(d[2]), "+f"(d[3])
        : "r"(a[0]), "r"(a[1]), "r"(a[2]), "r"(a[3]), "r"(b[0]), "r"(b[1]));
}

// ============================================================
// Fused: x transpose->fp16 xT  +  GroupNorm partial stats.
// ============================================================
__global__ void tconv_stats(const float* __restrict__ x, __half* __restrict__ dst) {
    __shared__ float t[32][33];
    __shared__ float rs[256], rss[256];
    int n0 = blockIdx.x * 32, c0 = blockIdx.y * 32, b = blockIdx.z;
    const float* s = x + (long)b * C_ * N_;
    int tx = threadIdx.x, ty = threadIdx.y;
    int tid = ty * 32 + tx;
    float sum = 0.f, ss = 0.f;
    #pragma unroll
    for (int i = 0; i < 4; i++) {
        int c = c0 + ty + i * 8;
        float v = s[(long)c * N_ + n0 + tx];
        t[ty + i * 8][tx] = v;
        sum += v; ss += v * v;
    }
    rs[tid] = sum; rss[tid] = ss;
    __syncthreads();
    __half* ph = dst + (long)b * N_ * C_;
    #pragma unroll
    for (int i = 0; i < 4; i++) {
        int n = n0 + ty + i * 8;
        ph[(long)n * C_ + c0 + tx] = __float2half_rn(t[tx][ty + i * 8]);
    }
    for (int st = 128; st > 0; st >>= 1) {
        if (tid < st) { rs[tid] += rs[tid + st]; rss[tid] += rss[tid + st]; }
        __syncthreads();
    }
    if (tid == 0) {
        int bg = b * 4 + (blockIdx.y >> 1);
        int idx = blockIdx.x * 2 + (blockIdx.y & 1);
        d_gpart[bg * 2048 + idx] = make_float2(rs[0], rss[0]);
    }
}

// ============================================================
// finalize GN stats -> scale/shift
// ============================================================
__global__ void gn_stats2(const float* __restrict__ gnw, const float* __restrict__ gnb) {
    int bg = blockIdx.x, tid = threadIdx.x;
    __shared__ float rs[256], rss[256];
    float s = 0.f, ss = 0.f;
    for (int i = tid; i < 2048; i += 256) {
        float2 p = d_gpart[bg * 2048 + i];
        s += p.x; ss += p.y;
    }
    rs[tid] = s; rss[tid] = ss;
    __syncthreads();
    for (int st = 128; st > 0; st >>= 1) {
        if (tid < st) { rs[tid] += rs[tid + st]; rss[tid] += rss[tid + st]; }
        __syncthreads();
    }
    if (tid < 64) {
        float inv = 1.0f / (float)(64L * N_);
        float mean = rs[0] * inv;
        float var = rss[0] * inv - mean * mean;
        float rstd = rsqrtf(var + 1e-5f);
        int b = bg >> 2, g = bg & 3;
        int c = g * 64 + tid;
        float sc = rstd * gnw[c];
        d_scale[b * C_ + c] = sc;
        d_shift[b * C_ + c] = gnb[c] - mean * sc;
    }
}

// ============================================================
// GN-folded qkv weight (fp16) + folded bias
// ============================================================
__global__ void build_wp(const float* __restrict__ W) {
    int o = blockIdx.x, b = blockIdx.y, c = threadIdx.x;
    float w = W[o * C_ + c];
    d_Wp[((long)b * 768 + o) * C_ + c] = __float2half_rn(w * d_scale[b * C_ + c]);
    __shared__ float red[256];
    red[c] = w * d_shift[b * C_ + c];
    __syncthreads();
    for (int st = 128; st > 0; st >>= 1) {
        if (c < st) red[c] += red[c + st];
        __syncthreads();
    }
    if (c == 0) d_biasp[b * 768 + o] = red[0];
}

// ============================================================
// fp16 GEMM via mma.sync, 4-stage cp.async.cg pipeline.
// MODE 1 (k,v): A = Wp rows 256..767, M=512. mt 0-1 -> k (+stats), 2-3 -> v.
// MODE 2 (out): A = W3 (per-batch 256x256), + bias3 + residual.
// ============================================================
static constexpr int SKROW = 40;
static constexpr int TILE_BYTES = 128 * SKROW * 2;   // 10240
static constexpr int STAGE_BYTES = 2 * TILE_BYTES;   // 20480
static constexpr int NSTAGE = 4;
static constexpr int GEMM_SMEM = NSTAGE * STAGE_BYTES;   // 81920

__device__ __forceinline__ void load_stage(
    uint32_t sbase, const __half* A, const __half* Bm, int kt, int tid)
{
    int k0 = kt * 32;
    #pragma unroll
    for (int it = 0; it < 2; it++) {
        int i = tid + it * 256;
        int row = i >> 2, c = i & 3;
        uint32_t doff = row * (SKROW * 2) + c * 16;
        long goff = (long)row * 256 + k0 + c * 8;
        CP16(sbase + doff,              A + goff);
        CP16(sbase + TILE_BYTES + doff, Bm + goff);
    }
}

template <int MODE>
__global__ void __launch_bounds__(256, 2) gemm_mma(
    const __half* __restrict__ Amat, const __half* __restrict__ Bmat,
    const float* __restrict__ bias, const float* __restrict__ resid,
    __half* __restrict__ outK, __half* __restrict__ outV,
    float* __restrict__ outO, int Mtotal)
{
    extern __shared__ char smem[];
    uint32_t sb = smem_u32(smem);
    int tid = threadIdx.x;
    int warp = tid >> 5, lane = tid & 31;
    int wm = (warp >> 2) * 64;
    int wn = (warp & 3) * 32;
    int mt = blockIdx.x, nt = blockIdx.y, b = blockIdx.z;

    const __half* A = Amat + (long)b * Mtotal * 256 + (long)mt * 128 * 256;
    const __half* Bm = Bmat + (long)b * N_ * 256 + (long)nt * 128 * 256;

    float acc[4][4][4];
    #pragma unroll
    for (int i = 0; i < 4; i++)
        #pragma unroll
        for (int j = 0; j < 4; j++)
            #pragma unroll
            for (int e = 0; e < 4; e++) acc[i][j][e] = 0.f;

    load_stage(sb + 0 * STAGE_BYTES, A, Bm, 0, tid); CP_COMMIT();
    load_stage(sb + 1 * STAGE_BYTES, A, Bm, 1, tid); CP_COMMIT();
    load_stage(sb + 2 * STAGE_BYTES, A, Bm, 2, tid); CP_COMMIT();

    int quad = lane >> 3, qr = lane & 7;
    int a_row = wm + (quad & 1) * 8 + qr;
    int a_colb = (quad >> 1) * 16;
    int b_row = wn + ((lane >> 4) & 1) * 8 + (lane & 7);
    int b_colb = ((lane >> 3) & 1) * 16;

    #pragma unroll 1
    for (int kt = 0; kt < 8; kt++) {
        asm volatile("cp.async.wait_group 2;");
        __syncthreads();
        if (kt + 3 < 8)
            load_stage(sb + ((kt + 3) & 3) * STAGE_BYTES, A, Bm, kt + 3, tid);
        CP_COMMIT();

        uint32_t base = sb + (kt & 3) * STAGE_BYTES;
        uint32_t aS = base, bS = base + TILE_BYTES;
        #pragma unroll
        for (int k16 = 0; k16 < 2; k16++) {
            uint32_t acol = a_colb + k16 * 32;
            uint32_t bcol = b_colb + k16 * 32;
            uint32_t ah[4][4], bh[4][2];
            #pragma unroll
            for (int mf = 0; mf < 4; mf++)
                ldm4(ah[mf], aS + (a_row + mf * 16) * (SKROW * 2) + acol);
            #pragma unroll
            for (int nfp = 0; nfp < 2; nfp++) {
                uint32_t r4[4];
                ldm4(r4, bS + (b_row + nfp * 16) * (SKROW * 2) + bcol);
                bh[nfp * 2 + 0][0] = r4[0]; bh[nfp * 2 + 0][1] = r4[1];
                bh[nfp * 2 + 1][0] = r4[2]; bh[nfp * 2 + 1][1] = r4[3];
            }
            #pragma unroll
            for (int mf = 0; mf < 4; mf++)
                #pragma unroll
                for (int nf = 0; nf < 4; nf++)
                    mma_f16(acc[mf][nf], ah[mf], bh[nf]);
        }
    }
    asm volatile("cp.async.wait_group 0;");

    if (MODE == 1) {
        // ---- k/v: write fp16; k also per-tile (max,sumexp) partials ----
        bool isK = (mt < 2);
        int c_base = isK ? mt * 128 : (mt - 2) * 128;
        __half* outH = isK ? outK : outV;
        float2* sms = (float2*)smem;    // [128][4]
        __syncthreads();
        #pragma unroll
        for (int mf = 0; mf < 4; mf++) {
            #pragma unroll
            for (int half = 0; half < 2; half++) {
                int r = wm + mf * 16 + half * 8 + (lane >> 2);
                float bv = bias[b * 768 + 256 + mt * 128 + r];
                __half* dst = outH + ((long)b * C_ + c_base + r) * N_ + (long)nt * 128;
                float vv[8];
                #pragma unroll
                for (int nf = 0; nf < 4; nf++) {
                    int n = wn + nf * 8 + 2 * (lane & 3);
                    __half h0 = __float2half_rn(acc[mf][nf][half * 2 + 0] + bv);
                    __half h1 = __float2half_rn(acc[mf][nf][half * 2 + 1] + bv);
                    *(__half2*)&dst[n] = __halves2half2(h0, h1);
                    vv[nf * 2 + 0] = __half2float(h0);
                    vv[nf * 2 + 1] = __half2float(h1);
                }
                if (isK) {
                    float m = vv[0];
                    #pragma unroll
                    for (int e = 1; e < 8; e++) m = fmaxf(m, vv[e]);
                    float s = 0.f;
                    #pragma unroll
                    for (int e = 0; e < 8; e++) s += __expf(vv[e] - m);
                    #pragma unroll
                    for (int dlt = 1; dlt <= 2; dlt <<= 1) {
                        float m2 = __shfl_xor_sync(0xffffffffu, m, dlt);
                        float s2 = __shfl_xor_sync(0xffffffffu, s, dlt);
                        float M = fmaxf(m, m2);
                        s = s * __expf(m - M) + s2 * __expf(m2 - M);
                        m = M;
                    }
                    if ((lane & 3) == 0) sms[r * 4 + (warp & 3)] = make_float2(m, s);
                }
            }
        }
        if (isK) {
            __syncthreads();
            if (tid < 128) {
                float2 p0 = sms[tid * 4 + 0], p1 = sms[tid * 4 + 1];
                float2 p2 = sms[tid * 4 + 2], p3 = sms[tid * 4 + 3];
                float M01 = fmaxf(p0.x, p1.x);
                float s01 = p0.y * __expf(p0.x - M01) + p1.y * __expf(p1.x - M01);
                float M23 = fmaxf(p2.x, p3.x);
                float s23 = p2.y * __expf(p2.x - M23) + p3.y * __expf(p3.x - M23);
                float M = fmaxf(M01, M23);
                float S = s01 * __expf(M01 - M) + s23 * __expf(M23 - M);
                d_kms[((long)b * C_ + c_base + tid) * 256 + nt] = make_float2(M, S);
            }
        }
        return;
    }

    // MODE 2 epilogue: fp32 out + per-batch bias3 + residual
    #pragma unroll
    for (int mf = 0; mf < 4; mf++) {
        #pragma unroll
        for (int half = 0; half < 2; half++) {
            int mrow = mt * 128 + wm + mf * 16 + half * 8 + (lane >> 2);
            float bv = bias[b * C_ + mrow];
            long base = ((long)b * C_ + mrow) * N_;
            float* dst = outO + base;
            const float* rp = resid + base;
            #pragma unroll
            for (int nf = 0; nf < 4; nf++) {
                int n = nt * 128 + wn + nf * 8 + 2 * (lane & 3);
                float2 rv = *(const float2*)&rp[n];
                float2 o;
                o.x = acc[mf][nf][half * 2 + 0] + bv + rv.x;
                o.y = acc[mf][nf][half * 2 + 1] + bv + rv.y;
                *(float2*)&dst[n] = o;
            }
        }
    }
}

// ============================================================
// reduce per-tile k stats -> d_m, d_s
// ============================================================
__global__ void krow_reduce() {
    int row = blockIdx.x, tid = threadIdx.x;
    __shared__ float sm[256], ssum[256];
    float2 p = d_kms[(long)row * 256 + tid];
    sm[tid] = p.x; ssum[tid] = p.y;
    __syncthreads();
    for (int st = 128; st > 0; st >>= 1) {
        if (tid < st) {
            float m1 = sm[tid], m2 = sm[tid + st];
            float M = fmaxf(m1, m2);
            ssum[tid] = ssum[tid] * __expf(m1 - M) + ssum[tid + st] * __expf(m2 - M);
            sm[tid] = M;
        }
        __syncthreads();
    }
    if (tid == 0) { d_m[row] = sm[0]; d_s[row] = ssum[0]; }
}

// ============================================================
// sim[b,h,d,e] = sum_n exp(k[d,n]-m[d])*v[e,n] (fp16 in, split over n)
// ============================================================
__global__ void __launch_bounds__(256) sim_partial() {
    const int PAD = 68;
    __shared__ float ks[32][PAD], vs[32][PAD];
    __shared__ float ms[32];
    int sp = blockIdx.x, bh = blockIdx.y;
    int b = bh >> 3, h = bh & 7;
    const __half* kp = d_kh + ((long)b * C_ + h * 32) * N_;
    const __half* vp = d_vh + ((long)b * C_ + h * 32) * N_;
    int tid = threadIdx.x;
    if (tid < 32) ms[tid] = d_m[b * C_ + h * 32 + tid];
    int d2 = (tid >> 4) * 2, e2 = (tid & 15) * 2;
    float a00 = 0.f, a01 = 0.f, a10 = 0.f, a11 = 0.f;
    int nbeg = sp * 2048;
    for (int n0 = nbeg; n0 < nbeg + 2048; n0 += 64) {
        __syncthreads();
        for (int l = tid; l < 512; l += 256) {
            int dd = l >> 4, jj = (l & 15) * 4;
            float mrow = ms[dd];
            uint2 kraw = *(const uint2*)&kp[(long)dd * N_ + n0 + jj];
            float2 k0 = __half22float2(*(__half2*)&kraw.x);
            float2 k1 = __half22float2(*(__half2*)&kraw.y);
            float4 kv;
            kv.x = __expf(k0.x - mrow);
            kv.y = __expf(k0.y - mrow);
            kv.z = __expf(k1.x - mrow);
            kv.w = __expf(k1.y - mrow);
            *(float4*)&ks[dd][jj] = kv;
            uint2 vraw = *(const uint2*)&vp[(long)dd * N_ + n0 + jj];
            float2 v0 = __half22float2(*(__half2*)&vraw.x);
            float2 v1 = __half22float2(*(__half2*)&vraw.y);
            float4 vv; vv.x = v0.x; vv.y = v0.y; vv.z = v1.x; vv.w = v1.y;
            *(float4*)&vs[dd][jj] = vv;
        }
        __syncthreads();
        #pragma unroll
        for (int j = 0; j < 64; j += 4) {
            float4 x0 = *(const float4*)&ks[d2][j];
            float4 x1 = *(const float4*)&ks[d2 + 1][j];
            float4 y0 = *(const float4*)&vs[e2][j];
            float4 y1 = *(const float4*)&vs[e2 + 1][j];
            a00 += x0.x * y0.x + x0.y * y0.y + x0.z * y0.z + x0.w * y0.w;
            a01 += x0.x * y1.x + x0.y * y1.y + x0.z * y1.z + x0.w * y1.w;
            a10 += x1.x * y0.x + x1.y * y0.y + x1.z * y0.z + x1.w * y0.w;
            a11 += x1.x * y1.x + x1.y * y1.y + x1.z * y1.z + x1.w * y1.w;
        }
    }
    float* out = d_simpart + ((long)(bh * 16 + sp)) * 1024;
    out[(d2 + 0) * 32 + e2 + 0] = a00;
    out[(d2 + 0) * 32 + e2 + 1] = a01;
    out[(d2 + 1) * 32 + e2 + 0] = a10;
    out[(d2 + 1) * 32 + e2 + 1] = a11;
}

// reduce splits + divide by softmax denominator
__global__ void sim_reduce() {
    int bh = blockIdx.x, i = threadIdx.x;
    int b = bh >> 3, h = bh & 7;
    float s = 0.f;
    #pragma unroll
    for (int sp = 0; sp < 16; sp++)
        s += d_simpart[(long)(bh * 16 + sp) * 1024 + i];
    float inv = 1.0f / d_s[b * C_ + h * 32 + (i >> 5)];
    d_sim[bh * 1024 + i] = s * inv;
}

// ============================================================
// W2f[b,o,h*32+d] = sum_e OW[o,h*32+e]*sim[b,h,d,e]  (fp32)
// ============================================================
__global__ void build_w2(const float* __restrict__ OW) {
    int o = blockIdx.x, b = blockIdx.y, cp = threadIdx.x;
    int h = cp >> 5, d = cp & 31;
    const float* simp = d_sim + ((long)((b * 8 + h) * 32 + d)) * 32;
    const float* owp = OW + o * C_ + h * 32;
    float s = 0.f;
    #pragma unroll
    for (int e = 0; e < 32; e++) s += owp[e] * simp[e];
    d_W2f[((long)b * C_ + o) * C_ + cp] = s;
}

// ============================================================
// W3[b] = W2f[b] @ Wq'[b] (fp16 out), bias3[b] = ob + W2f[b] @ bq'
// grid (256, 4), 256 threads.
// ============================================================
__global__ void build_w3(const float* __restrict__ ob) {
    int o = blockIdx.x, b = blockIdx.y, c = threadIdx.x;
    __shared__ float w2row[256];
    __shared__ float red[256];
    const float* w2p = d_W2f + ((long)b * C_ + o) * C_;
    w2row[c] = w2p[c];
    red[c] = w2row[c] * d_biasp[b * 768 + c];   // bq' rows 0-255
    __syncthreads();
    float acc = 0.f;
    const __half* wq = d_Wp + (long)b * 768 * C_;   // rows 0-255 = Wq'
    #pragma unroll 8
    for (int e = 0; e < 256; e++)
        acc += w2row[e] * __half2float(wq[(long)e * C_ + c]);
    d_W3[((long)b * C_ + o) * C_ + c] = __float2half_rn(acc);
    for (int st = 128; st > 0; st >>= 1) {
        if (c < st) red[c] += red[c + st];
        __syncthreads();
    }
    if (c == 0) d_bias3[b * C_ + o] = ob[o] + red[0];
}

// ============================================================
// host launch
// ============================================================
extern "C" void kernel_launch(void* const* d_in, const int* in_sizes, int n_in,
                              void* d_out, int out_size) {
    const float* x    = (const float*)d_in[0];
    const float* gnw  = (const float*)d_in[1];
    const float* gnb  = (const float*)d_in[2];
    const float* qkvW = (const float*)d_in[3];
    const float* ow   = (const float*)d_in[4];
    const float* ob   = (const float*)d_in[5];
    float* out = (float*)d_out;

    float *pBiasp, *pBias3;
    __half *pKh, *pVh, *pXT, *pWp, *pW3;
    cudaGetSymbolAddress((void**)&pKh, d_kh);
    cudaGetSymbolAddress((void**)&pVh, d_vh);
    cudaGetSymbolAddress((void**)&pBiasp, d_biasp);
    cudaGetSymbolAddress((void**)&pBias3, d_bias3);
    cudaGetSymbolAddress((void**)&pXT, d_xT);
    cudaGetSymbolAddress((void**)&pWp, d_Wp);
    cudaGetSymbolAddress((void**)&pW3, d_W3);

    cudaFuncSetAttribute(gemm_mma<1>, cudaFuncAttributeMaxDynamicSharedMemorySize, GEMM_SMEM);
    cudaFuncSetAttribute(gemm_mma<2>, cudaFuncAttributeMaxDynamicSharedMemorySize, GEMM_SMEM);

    tconv_stats<<<dim3(1024, 8, 4), dim3(32, 8)>>>(x, pXT);
    gn_stats2<<<16, 256>>>(gnw, gnb);
    build_wp<<<dim3(768, 4), 256>>>(qkvW);

    // k,v GEMM: A = Wp rows 256..767 (M=512). k -> stats, v plain.
    gemm_mma<1><<<dim3(4, 256, 4), 256, GEMM_SMEM>>>(pWp + (long)256 * C_, pXT,
                                                     pBiasp, nullptr, pKh, pVh, nullptr, 768);

    krow_reduce<<<1024, 256>>>();
    sim_partial<<<dim3(16, 32), 256>>>();
    sim_reduce<<<32, 1024>>>();
    build_w2<<<dim3(256, 4), 256>>>(ow);
    build_w3<<<dim3(256, 4), 256>>>(ob);

    // out = W3 @ xT^T + bias3 + x
    gemm_mma<2><<<dim3(2, 256, 4), 256, GEMM_SMEM>>>(pW3, pXT,
                                                     pBias3, x, nullptr, nullptr, out, 256);
}

// round 9
// speedup vs baseline: 4.9405x; 1.4360x over previous
#include <cuda_runtime.h>
#include <cuda_fp16.h>
#include <cstdint>

// Problem constants
static constexpr int B_ = 4;
static constexpr int C_ = 256;
static constexpr int N_ = 32768;     // 32*32*32
static constexpr int H_ = 8;
static constexpr int SIMS = 32;      // sim K-splits

// ---------------- device scratch (no allocations allowed) ----------------
__device__ __half d_kh[(long)B_ * C_ * N_];        // k fp16 [b][c][n]
__device__ __half d_vh[(long)B_ * C_ * N_];        // v fp16
__device__ __half d_xT[(long)B_ * N_ * C_];        // xT [b][n][c] fp16
__device__ __half d_Wp[B_ * 768 * C_];             // GN-folded qkv weight fp16
__device__ float d_biasp[B_ * 768];
__device__ float d_W2f[B_ * C_ * C_];              // sim-fused out weight fp32
__device__ __half d_W3[B_ * C_ * C_];              // W2 @ Wq' fp16
__device__ float d_bias3[B_ * C_];
__device__ float2 d_gpart[16 * 1024];              // GN partials (sum, sumsq)
__device__ float d_scale[B_ * C_];
__device__ float d_shift[B_ * C_];
__device__ float2 d_kms[B_ * C_ * 256];            // per-tile k (max, sumexp)
__device__ float d_m[B_ * C_];
__device__ float d_s[B_ * C_];
__device__ float d_simpart[(long)B_ * H_ * SIMS * 1024];
__device__ float d_sim[B_ * H_ * 1024];

// ---------------- PTX helpers ----------------
__device__ __forceinline__ uint32_t smem_u32(const void* p) {
    uint32_t a;
    asm("{ .reg .u64 t; cvta.to.shared.u64 t, %1; cvt.u32.u64 %0, t; }" : "=r"(a) : "l"(p));
    return a;
}
#define CP16(dst, src) asm volatile("cp.async.cg.shared.global [%0], [%1], 16;" :: "r"(dst), "l"(src))
#define CP_COMMIT()    asm volatile("cp.async.commit_group;")

__device__ __forceinline__ void ldm4(uint32_t* r, uint32_t addr) {
    asm volatile("ldmatrix.sync.aligned.m8n8.x4.shared.b16 {%0,%1,%2,%3}, [%4];"
        : "=r"(r[0]), "=r"(r[1]), "=r"(r[2]), "=r"(r[3]) : "r"(addr));
}
__device__ __forceinline__ void mma_f16(float* d, const uint32_t* a, const uint32_t* b) {
    asm volatile(
        "mma.sync.aligned.m16n8k16.row.col.f32.f16.f16.f32 "
        "{%0,%1,%2,%3}, {%4,%5,%6,%7}, {%8,%9}, {%0,%1,%2,%3};"
        : "+f"(d[0]), "+f"(d[1]), "+f"(d[2]), "+f"(d[3])
        : "r"(a[0]), "r"(a[1]), "r"(a[2]), "r"(a[3]), "r"(b[0]), "r"(b[1]));
}

// ============================================================
// Fused: x transpose->fp16 xT + GN partial stats.
// grid (1024, 4, 4), block (32,8). 64c x 32n tiles; half2 stores.
// ============================================================
__global__ void tconv_stats(const float* __restrict__ x, __half* __restrict__ dst) {
    __shared__ float t[64][33];
    __shared__ float rs[256], rss[256];
    int n0 = blockIdx.x * 32, c0 = blockIdx.y * 64, b = blockIdx.z;
    const float* s = x + (long)b * C_ * N_;
    int tx = threadIdx.x, ty = threadIdx.y;
    int tid = ty * 32 + tx;
    float sum = 0.f, ss = 0.f;
    #pragma unroll
    for (int i = 0; i < 8; i++) {
        int cl = ty + i * 8;
        float v = s[(long)(c0 + cl) * N_ + n0 + tx];
        t[cl][tx] = v;
        sum += v; ss += v * v;
    }
    rs[tid] = sum; rss[tid] = ss;
    __syncthreads();
    __half* ph = dst + (long)b * N_ * C_;
    #pragma unroll
    for (int i = 0; i < 4; i++) {
        int nl = ty + i * 8;
        __half2 h = __floats2half2_rn(t[2 * tx][nl], t[2 * tx + 1][nl]);
        *(__half2*)&ph[(long)(n0 + nl) * C_ + c0 + 2 * tx] = h;
    }
    for (int st = 128; st > 0; st >>= 1) {
        if (tid < st) { rs[tid] += rs[tid + st]; rss[tid] += rss[tid + st]; }
        __syncthreads();
    }
    if (tid == 0)
        d_gpart[(b * 4 + blockIdx.y) * 1024 + blockIdx.x] = make_float2(rs[0], rss[0]);
}

// ============================================================
// finalize GN stats -> scale/shift
// ============================================================
__global__ void gn_stats2(const float* __restrict__ gnw, const float* __restrict__ gnb) {
    int bg = blockIdx.x, tid = threadIdx.x;
    __shared__ float rs[256], rss[256];
    float s = 0.f, ss = 0.f;
    for (int i = tid; i < 1024; i += 256) {
        float2 p = d_gpart[bg * 1024 + i];
        s += p.x; ss += p.y;
    }
    rs[tid] = s; rss[tid] = ss;
    __syncthreads();
    for (int st = 128; st > 0; st >>= 1) {
        if (tid < st) { rs[tid] += rs[tid + st]; rss[tid] += rss[tid + st]; }
        __syncthreads();
    }
    if (tid < 64) {
        float inv = 1.0f / (float)(64L * N_);
        float mean = rs[0] * inv;
        float var = rss[0] * inv - mean * mean;
        float rstd = rsqrtf(var + 1e-5f);
        int b = bg >> 2, g = bg & 3;
        int c = g * 64 + tid;
        float sc = rstd * gnw[c];
        d_scale[b * C_ + c] = sc;
        d_shift[b * C_ + c] = gnb[c] - mean * sc;
    }
}

// ============================================================
// GN-folded qkv weight (fp16) + folded bias
// ============================================================
__global__ void build_wp(const float* __restrict__ W) {
    int o = blockIdx.x, b = blockIdx.y, c = threadIdx.x;
    float w = W[o * C_ + c];
    d_Wp[((long)b * 768 + o) * C_ + c] = __float2half_rn(w * d_scale[b * C_ + c]);
    __shared__ float red[256];
    red[c] = w * d_shift[b * C_ + c];
    __syncthreads();
    for (int st = 128; st > 0; st >>= 1) {
        if (c < st) red[c] += red[c + st];
        __syncthreads();
    }
    if (c == 0) d_biasp[b * 768 + o] = red[0];
}

// ============================================================
// fp16 GEMM via mma.sync, 4-stage cp.async.cg pipeline.
// MODE 1 (k,v): A = Wp rows 256..767, M=512. mt 0-1 -> k (+stats), 2-3 -> v.
// MODE 2 (out): A = W3 (per-batch 256x256), + bias3 + residual.
// ============================================================
static constexpr int SKROW = 40;
static constexpr int TILE_BYTES = 128 * SKROW * 2;   // 10240
static constexpr int STAGE_BYTES = 2 * TILE_BYTES;   // 20480
static constexpr int NSTAGE = 4;
static constexpr int GEMM_SMEM = NSTAGE * STAGE_BYTES;   // 81920

__device__ __forceinline__ void load_stage(
    uint32_t sbase, const __half* A, const __half* Bm, int kt, int tid)
{
    int k0 = kt * 32;
    #pragma unroll
    for (int it = 0; it < 2; it++) {
        int i = tid + it * 256;
        int row = i >> 2, c = i & 3;
        uint32_t doff = row * (SKROW * 2) + c * 16;
        long goff = (long)row * 256 + k0 + c * 8;
        CP16(sbase + doff,              A + goff);
        CP16(sbase + TILE_BYTES + doff, Bm + goff);
    }
}

template <int MODE>
__global__ void __launch_bounds__(256, 2) gemm_mma(
    const __half* __restrict__ Amat, const __half* __restrict__ Bmat,
    const float* __restrict__ bias, const float* __restrict__ resid,
    __half* __restrict__ outK, __half* __restrict__ outV,
    float* __restrict__ outO, int Mtotal)
{
    extern __shared__ char smem[];
    uint32_t sb = smem_u32(smem);
    int tid = threadIdx.x;
    int warp = tid >> 5, lane = tid & 31;
    int wm = (warp >> 2) * 64;
    int wn = (warp & 3) * 32;
    int mt = blockIdx.x, nt = blockIdx.y, b = blockIdx.z;

    const __half* A = Amat + (long)b * Mtotal * 256 + (long)mt * 128 * 256;
    const __half* Bm = Bmat + (long)b * N_ * 256 + (long)nt * 128 * 256;

    float acc[4][4][4];
    #pragma unroll
    for (int i = 0; i < 4; i++)
        #pragma unroll
        for (int j = 0; j < 4; j++)
            #pragma unroll
            for (int e = 0; e < 4; e++) acc[i][j][e] = 0.f;

    load_stage(sb + 0 * STAGE_BYTES, A, Bm, 0, tid); CP_COMMIT();
    load_stage(sb + 1 * STAGE_BYTES, A, Bm, 1, tid); CP_COMMIT();
    load_stage(sb + 2 * STAGE_BYTES, A, Bm, 2, tid); CP_COMMIT();

    int quad = lane >> 3, qr = lane & 7;
    int a_row = wm + (quad & 1) * 8 + qr;
    int a_colb = (quad >> 1) * 16;
    int b_row = wn + ((lane >> 4) & 1) * 8 + (lane & 7);
    int b_colb = ((lane >> 3) & 1) * 16;

    #pragma unroll 1
    for (int kt = 0; kt < 8; kt++) {
        asm volatile("cp.async.wait_group 2;");
        __syncthreads();
        if (kt + 3 < 8)
            load_stage(sb + ((kt + 3) & 3) * STAGE_BYTES, A, Bm, kt + 3, tid);
        CP_COMMIT();

        uint32_t base = sb + (kt & 3) * STAGE_BYTES;
        uint32_t aS = base, bS = base + TILE_BYTES;
        #pragma unroll
        for (int k16 = 0; k16 < 2; k16++) {
            uint32_t acol = a_colb + k16 * 32;
            uint32_t bcol = b_colb + k16 * 32;
            uint32_t ah[4][4], bh[4][2];
            #pragma unroll
            for (int mf = 0; mf < 4; mf++)
                ldm4(ah[mf], aS + (a_row + mf * 16) * (SKROW * 2) + acol);
            #pragma unroll
            for (int nfp = 0; nfp < 2; nfp++) {
                uint32_t r4[4];
                ldm4(r4, bS + (b_row + nfp * 16) * (SKROW * 2) + bcol);
                bh[nfp * 2 + 0][0] = r4[0]; bh[nfp * 2 + 0][1] = r4[1];
                bh[nfp * 2 + 1][0] = r4[2]; bh[nfp * 2 + 1][1] = r4[3];
            }
            #pragma unroll
            for (int mf = 0; mf < 4; mf++)
                #pragma unroll
                for (int nf = 0; nf < 4; nf++)
                    mma_f16(acc[mf][nf], ah[mf], bh[nf]);
        }
    }
    asm volatile("cp.async.wait_group 0;");

    if (MODE == 1) {
        bool isK = (mt < 2);
        int c_base = isK ? mt * 128 : (mt - 2) * 128;
        __half* outH = isK ? outK : outV;
        float2* sms = (float2*)smem;    // [128][4]
        __syncthreads();
        #pragma unroll
        for (int mf = 0; mf < 4; mf++) {
            #pragma unroll
            for (int half = 0; half < 2; half++) {
                int r = wm + mf * 16 + half * 8 + (lane >> 2);
                float bv = bias[b * 768 + 256 + mt * 128 + r];
                __half* dst = outH + ((long)b * C_ + c_base + r) * N_ + (long)nt * 128;
                float vv[8];
                #pragma unroll
                for (int nf = 0; nf < 4; nf++) {
                    int n = wn + nf * 8 + 2 * (lane & 3);
                    __half h0 = __float2half_rn(acc[mf][nf][half * 2 + 0] + bv);
                    __half h1 = __float2half_rn(acc[mf][nf][half * 2 + 1] + bv);
                    *(__half2*)&dst[n] = __halves2half2(h0, h1);
                    vv[nf * 2 + 0] = __half2float(h0);
                    vv[nf * 2 + 1] = __half2float(h1);
                }
                if (isK) {
                    float m = vv[0];
                    #pragma unroll
                    for (int e = 1; e < 8; e++) m = fmaxf(m, vv[e]);
                    float s = 0.f;
                    #pragma unroll
                    for (int e = 0; e < 8; e++) s += __expf(vv[e] - m);
                    #pragma unroll
                    for (int dlt = 1; dlt <= 2; dlt <<= 1) {
                        float m2 = __shfl_xor_sync(0xffffffffu, m, dlt);
                        float s2 = __shfl_xor_sync(0xffffffffu, s, dlt);
                        float M = fmaxf(m, m2);
                        s = s * __expf(m - M) + s2 * __expf(m2 - M);
                        m = M;
                    }
                    if ((lane & 3) == 0) sms[r * 4 + (warp & 3)] = make_float2(m, s);
                }
            }
        }
        if (isK) {
            __syncthreads();
            if (tid < 128) {
                float2 p0 = sms[tid * 4 + 0], p1 = sms[tid * 4 + 1];
                float2 p2 = sms[tid * 4 + 2], p3 = sms[tid * 4 + 3];
                float M01 = fmaxf(p0.x, p1.x);
                float s01 = p0.y * __expf(p0.x - M01) + p1.y * __expf(p1.x - M01);
                float M23 = fmaxf(p2.x, p3.x);
                float s23 = p2.y * __expf(p2.x - M23) + p3.y * __expf(p3.x - M23);
                float M = fmaxf(M01, M23);
                float S = s01 * __expf(M01 - M) + s23 * __expf(M23 - M);
                d_kms[((long)b * C_ + c_base + tid) * 256 + nt] = make_float2(M, S);
            }
        }
        return;
    }

    // MODE 2 epilogue: fp32 out + per-batch bias3 + residual
    #pragma unroll
    for (int mf = 0; mf < 4; mf++) {
        #pragma unroll
        for (int half = 0; half < 2; half++) {
            int mrow = mt * 128 + wm + mf * 16 + half * 8 + (lane >> 2);
            float bv = bias[b * C_ + mrow];
            long base = ((long)b * C_ + mrow) * N_;
            float* dst = outO + base;
            const float* rp = resid + base;
            #pragma unroll
            for (int nf = 0; nf < 4; nf++) {
                int n = nt * 128 + wn + nf * 8 + 2 * (lane & 3);
                float2 rv = *(const float2*)&rp[n];
                float2 o;
                o.x = acc[mf][nf][half * 2 + 0] + bv + rv.x;
                o.y = acc[mf][nf][half * 2 + 1] + bv + rv.y;
                *(float2*)&dst[n] = o;
            }
        }
    }
}

// ============================================================
// reduce per-tile k stats -> d_m, d_s
// ============================================================
__global__ void krow_reduce() {
    int row = blockIdx.x, tid = threadIdx.x;
    __shared__ float sm[256], ssum[256];
    float2 p = d_kms[(long)row * 256 + tid];
    sm[tid] = p.x; ssum[tid] = p.y;
    __syncthreads();
    for (int st = 128; st > 0; st >>= 1) {
        if (tid < st) {
            float m1 = sm[tid], m2 = sm[tid + st];
            float M = fmaxf(m1, m2);
            ssum[tid] = ssum[tid] * __expf(m1 - M) + ssum[tid + st] * __expf(m2 - M);
            sm[tid] = M;
        }
        __syncthreads();
    }
    if (tid == 0) { d_m[row] = sm[0]; d_s[row] = ssum[0]; }
}

// ============================================================
// sim via HMMA: simpart[bh,sp] = exp(k-m) @ v^T over 1024 spatial cols.
// grid (SIMS=32, 32 bh), block 256 (8 warps). Double-buffered cp.async,
// row-wise exp transform (conflict-free), per-warp 16-col K-slices.
// ============================================================
__global__ void __launch_bounds__(256) sim_hmma() {
    __shared__ __align__(16) char S[43520];
    __shared__ float ms[32];
    char* kraw0 = S;            // 2 x 8704
    char* vraw0 = S + 17408;    // 2 x 8704
    char* kx    = S + 34816;    // 8704
    int sp = blockIdx.x, bh = blockIdx.y;
    int b = bh >> 3, h = bh & 7;
    const __half* kp = d_kh + ((long)b * C_ + h * 32) * N_;
    const __half* vp = d_vh + ((long)b * C_ + h * 32) * N_;
    int tid = threadIdx.x, lane = tid & 31, w = tid >> 5;
    if (tid < 32) ms[tid] = d_m[b * C_ + h * 32 + tid];

    float acc[2][4][4];
    #pragma unroll
    for (int i = 0; i < 2; i++)
        #pragma unroll
        for (int j = 0; j < 4; j++)
            #pragma unroll
            for (int e = 0; e < 4; e++) acc[i][j][e] = 0.f;

    int quad = lane >> 3, qr = lane & 7;
    int a_row = (quad & 1) * 8 + qr;
    int a_cb = (quad >> 1) * 16;
    int b_row = ((lane >> 4) & 1) * 8 + (lane & 7);
    int b_cb = ((lane >> 3) & 1) * 16;
    int nbeg = sp * 1024;

    // stage loader: 32 rows x 128 halves for k and v
    auto load = [&](int st) {
        int buf = st & 1;
        uint32_t kb = smem_u32(kraw0 + buf * 8704);
        uint32_t vb = smem_u32(vraw0 + buf * 8704);
        int n0 = nbeg + st * 128;
        #pragma unroll
        for (int it = 0; it < 2; it++) {
            int idx = tid + it * 256;
            int row = idx >> 4, seg = idx & 15;
            long g = (long)row * N_ + n0 + seg * 8;
            CP16(kb + row * 272 + seg * 16, kp + g);
            CP16(vb + row * 272 + seg * 16, vp + g);
        }
        CP_COMMIT();
    };

    load(0);
    #pragma unroll 1
    for (int st = 0; st < 8; st++) {
        if (st + 1 < 8) { load(st + 1); asm volatile("cp.async.wait_group 1;"); }
        else            { asm volatile("cp.async.wait_group 0;"); }
        __syncthreads();
        // exp transform: warp w handles rows [4w, 4w+4), lanes sweep cols
        {
            char* kbuf = kraw0 + (st & 1) * 8704;
            #pragma unroll
            for (int rr = 0; rr < 4; rr++) {
                int row = w * 4 + rr;
                float mr = ms[row];
                const __half2* src = (const __half2*)(kbuf + row * 272);
                __half2* dst = (__half2*)(kx + row * 272);
                #pragma unroll
                for (int j = 0; j < 2; j++) {
                    int ci = lane + j * 32;
                    float2 f = __half22float2(src[ci]);
                    f.x = __expf(f.x - mr);
                    f.y = __expf(f.y - mr);
                    dst[ci] = __float22half2_rn(f);
                }
            }
        }
        __syncthreads();
        // mma: warp w owns 16-col slice
        {
            uint32_t kxu = smem_u32(kx);
            uint32_t vbu = smem_u32(vraw0 + (st & 1) * 8704);
            uint32_t colb = w * 32;
            uint32_t af[2][4], bf[4][2];
            #pragma unroll
            for (int mf = 0; mf < 2; mf++)
                ldm4(af[mf], kxu + (a_row + mf * 16) * 272 + colb + a_cb);
            #pragma unroll
            for (int nfp = 0; nfp < 2; nfp++) {
                uint32_t r4[4];
                ldm4(r4, vbu + (b_row + nfp * 16) * 272 + colb + b_cb);
                bf[nfp * 2 + 0][0] = r4[0]; bf[nfp * 2 + 0][1] = r4[1];
                bf[nfp * 2 + 1][0] = r4[2]; bf[nfp * 2 + 1][1] = r4[3];
            }
            #pragma unroll
            for (int mf = 0; mf < 2; mf++)
                #pragma unroll
                for (int nf = 0; nf < 4; nf++)
                    mma_f16(acc[mf][nf], af[mf], bf[nf]);
        }
        __syncthreads();
    }

    // cross-warp reduction (overlay on kraw/vraw region)
    float* red = (float*)S;
    float* my = red + w * 1024;
    #pragma unroll
    for (int mf = 0; mf < 2; mf++) {
        int r = mf * 16 + (lane >> 2);
        #pragma unroll
        for (int nf = 0; nf < 4; nf++) {
            int c = nf * 8 + 2 * (lane & 3);
            my[r * 32 + c]           = acc[mf][nf][0];
            my[r * 32 + c + 1]       = acc[mf][nf][1];
            my[(r + 8) * 32 + c]     = acc[mf][nf][2];
            my[(r + 8) * 32 + c + 1] = acc[mf][nf][3];
        }
    }
    __syncthreads();
    float* out = d_simpart + ((long)(bh * SIMS + sp)) * 1024;
    for (int i = tid; i < 1024; i += 256) {
        float s = 0.f;
        #pragma unroll
        for (int ww = 0; ww < 8; ww++) s += red[ww * 1024 + i];
        out[i] = s;
    }
}

// reduce splits + divide by softmax denominator
__global__ void sim_reduce() {
    int bh = blockIdx.x, i = threadIdx.x;
    int b = bh >> 3, h = bh & 7;
    float s = 0.f;
    #pragma unroll
    for (int sp = 0; sp < SIMS; sp++)
        s += d_simpart[(long)(bh * SIMS + sp) * 1024 + i];
    float inv = 1.0f / d_s[b * C_ + h * 32 + (i >> 5)];
    d_sim[bh * 1024 + i] = s * inv;
}

// ============================================================
// W2f[b,o,h*32+d] = sum_e OW[o,h*32+e]*sim[b,h,d,e]  (fp32)
// ============================================================
__global__ void build_w2(const float* __restrict__ OW) {
    int o = blockIdx.x, b = blockIdx.y, cp = threadIdx.x;
    int h = cp >> 5, d = cp & 31;
    const float* simp = d_sim + ((long)((b * 8 + h) * 32 + d)) * 32;
    const float* owp = OW + o * C_ + h * 32;
    float s = 0.f;
    #pragma unroll
    for (int e = 0; e < 32; e++) s += owp[e] * simp[e];
    d_W2f[((long)b * C_ + o) * C_ + cp] = s;
}

// ============================================================
// W3[b] = W2f[b] @ Wq'[b] (fp16 out), bias3[b] = ob + W2f[b] @ bq'
// ============================================================
__global__ void build_w3(const float* __restrict__ ob) {
    int o = blockIdx.x, b = blockIdx.y, c = threadIdx.x;
    __shared__ float w2row[256];
    __shared__ float red[256];
    const float* w2p = d_W2f + ((long)b * C_ + o) * C_;
    w2row[c] = w2p[c];
    red[c] = w2row[c] * d_biasp[b * 768 + c];
    __syncthreads();
    float acc = 0.f;
    const __half* wq = d_Wp + (long)b * 768 * C_;
    #pragma unroll 8
    for (int e = 0; e < 256; e++)
        acc += w2row[e] * __half2float(wq[(long)e * C_ + c]);
    d_W3[((long)b * C_ + o) * C_ + c] = __float2half_rn(acc);
    for (int st = 128; st > 0; st >>= 1) {
        if (c < st) red[c] += red[c + st];
        __syncthreads();
    }
    if (c == 0) d_bias3[b * C_ + o] = ob[o] + red[0];
}

// ============================================================
// host launch
// ============================================================
extern "C" void kernel_launch(void* const* d_in, const int* in_sizes, int n_in,
                              void* d_out, int out_size) {
    const float* x    = (const float*)d_in[0];
    const float* gnw  = (const float*)d_in[1];
    const float* gnb  = (const float*)d_in[2];
    const float* qkvW = (const float*)d_in[3];
    const float* ow   = (const float*)d_in[4];
    const float* ob   = (const float*)d_in[5];
    float* out = (float*)d_out;

    float *pBiasp, *pBias3;
    __half *pKh, *pVh, *pXT, *pWp, *pW3;
    cudaGetSymbolAddress((void**)&pKh, d_kh);
    cudaGetSymbolAddress((void**)&pVh, d_vh);
    cudaGetSymbolAddress((void**)&pBiasp, d_biasp);
    cudaGetSymbolAddress((void**)&pBias3, d_bias3);
    cudaGetSymbolAddress((void**)&pXT, d_xT);
    cudaGetSymbolAddress((void**)&pWp, d_Wp);
    cudaGetSymbolAddress((void**)&pW3, d_W3);

    cudaFuncSetAttribute(gemm_mma<1>, cudaFuncAttributeMaxDynamicSharedMemorySize, GEMM_SMEM);
    cudaFuncSetAttribute(gemm_mma<2>, cudaFuncAttributeMaxDynamicSharedMemorySize, GEMM_SMEM);

    tconv_stats<<<dim3(1024, 4, 4), dim3(32, 8)>>>(x, pXT);
    gn_stats2<<<16, 256>>>(gnw, gnb);
    build_wp<<<dim3(768, 4), 256>>>(qkvW);

    // k,v GEMM: A = Wp rows 256..767 (M=512). k -> stats, v plain.
    gemm_mma<1><<<dim3(4, 256, 4), 256, GEMM_SMEM>>>(pWp + (long)256 * C_, pXT,
                                                     pBiasp, nullptr, pKh, pVh, nullptr, 768);

    krow_reduce<<<1024, 256>>>();
    sim_hmma<<<dim3(SIMS, 32), 256>>>();
    sim_reduce<<<32, 1024>>>();
    build_w2<<<dim3(256, 4), 256>>>(ow);
    build_w3<<<dim3(256, 4), 256>>>(ob);

    // out = W3 @ xT^T + bias3 + x
    gemm_mma<2><<<dim3(2, 256, 4), 256, GEMM_SMEM>>>(pW3, pXT,
                                                     pBias3, x, nullptr, nullptr, out, 256);
}

// round 11
// speedup vs baseline: 5.1149x; 1.0353x over previous
#include <cuda_runtime.h>
#include <cuda_fp16.h>
#include <cstdint>

// Problem constants
static constexpr int B_ = 4;
static constexpr int C_ = 256;
static constexpr int N_ = 32768;     // 32*32*32
static constexpr int H_ = 8;
static constexpr int SIMS = 32;      // sim K-splits

// ---------------- device scratch (no allocations allowed) ----------------
__device__ __half d_kh[(long)B_ * C_ * N_];        // k fp16 [b][c][n]
__device__ __half d_vh[(long)B_ * C_ * N_];        // v fp16
__device__ __half d_xT[(long)B_ * N_ * C_];        // xT [b][n][c] fp16
__device__ __half d_Wp[B_ * 768 * C_];             // GN-folded qkv weight fp16
__device__ float d_biasp[B_ * 768];
__device__ float d_W2f[B_ * C_ * C_];              // sim-fused out weight fp32
__device__ __half d_W3[B_ * C_ * C_];              // W2 @ Wq' fp16
__device__ float d_bias3[B_ * C_];
__device__ float2 d_gpart[16 * 1024];              // GN partials (sum, sumsq)
__device__ float d_scale[B_ * C_];
__device__ float d_shift[B_ * C_];
__device__ float2 d_kms[B_ * C_ * 256];            // per-tile k (max, sumexp)
__device__ float d_m[B_ * C_];
__device__ float d_s[B_ * C_];
__device__ float d_simpart[(long)B_ * H_ * SIMS * 1024];
__device__ float d_sim[B_ * H_ * 1024];

// ---------------- PTX helpers ----------------
__device__ __forceinline__ uint32_t smem_u32(const void* p) {
    uint32_t a;
    asm("{ .reg .u64 t; cvta.to.shared.u64 t, %1; cvt.u32.u64 %0, t; }" : "=r"(a) : "l"(p));
    return a;
}
#define CP16(dst, src) asm volatile("cp.async.cg.shared.global [%0], [%1], 16;" :: "r"(dst), "l"(src))
#define CP_COMMIT()    asm volatile("cp.async.commit_group;")

__device__ __forceinline__ void ldm4(uint32_t* r, uint32_t addr) {
    asm volatile("ldmatrix.sync.aligned.m8n8.x4.shared.b16 {%0,%1,%2,%3}, [%4];"
        : "=r"(r[0]), "=r"(r[1]), "=r"(r[2]), "=r"(r[3]) : "r"(addr));
}
__device__ __forceinline__ void mma_f16(float* d, const uint32_t* a, const uint32_t* b) {
    asm volatile(
        "mma.sync.aligned.m16n8k16.row.col.f32.f16.f16.f32 "
        "{%0,%1,%2,%3}, {%4,%5,%6,%7}, {%8,%9}, {%0,%1,%2,%3};"
        : "+f"(d[0]), "+f"(d[1]), "+f"(d[2]), "+f"(d[3])
        : "r"(a[0]), "r"(a[1]), "r"(a[2]), "r"(a[3]), "r"(b[0]), "r"(b[1]));
}

// ============================================================
// Fused: x transpose->fp16 xT + GN partial stats.
// grid (1024, 4, 4), block (32,8). 64c x 32n tiles; half2 stores.
// ============================================================
__global__ void tconv_stats(const float* __restrict__ x, __half* __restrict__ dst) {
    __shared__ float t[64][33];
    __shared__ float rs[256], rss[256];
    int n0 = blockIdx.x * 32, c0 = blockIdx.y * 64, b = blockIdx.z;
    const float* s = x + (long)b * C_ * N_;
    int tx = threadIdx.x, ty = threadIdx.y;
    int tid = ty * 32 + tx;
    float sum = 0.f, ss = 0.f;
    #pragma unroll
    for (int i = 0; i < 8; i++) {
        int cl = ty + i * 8;
        float v = s[(long)(c0 + cl) * N_ + n0 + tx];
        t[cl][tx] = v;
        sum += v; ss += v * v;
    }
    rs[tid] = sum; rss[tid] = ss;
    __syncthreads();
    __half* ph = dst + (long)b * N_ * C_;
    #pragma unroll
    for (int i = 0; i < 4; i++) {
        int nl = ty + i * 8;
        __half2 h = __floats2half2_rn(t[2 * tx][nl], t[2 * tx + 1][nl]);
        *(__half2*)&ph[(long)(n0 + nl) * C_ + c0 + 2 * tx] = h;
    }
    for (int st = 128; st > 0; st >>= 1) {
        if (tid < st) { rs[tid] += rs[tid + st]; rss[tid] += rss[tid + st]; }
        __syncthreads();
    }
    if (tid == 0)
        d_gpart[(b * 4 + blockIdx.y) * 1024 + blockIdx.x] = make_float2(rs[0], rss[0]);
}

// ============================================================
// finalize GN stats -> scale/shift
// ============================================================
__global__ void gn_stats2(const float* __restrict__ gnw, const float* __restrict__ gnb) {
    int bg = blockIdx.x, tid = threadIdx.x;
    __shared__ float rs[256], rss[256];
    float s = 0.f, ss = 0.f;
    for (int i = tid; i < 1024; i += 256) {
        float2 p = d_gpart[bg * 1024 + i];
        s += p.x; ss += p.y;
    }
    rs[tid] = s; rss[tid] = ss;
    __syncthreads();
    for (int st = 128; st > 0; st >>= 1) {
        if (tid < st) { rs[tid] += rs[tid + st]; rss[tid] += rss[tid + st]; }
        __syncthreads();
    }
    if (tid < 64) {
        float inv = 1.0f / (float)(64L * N_);
        float mean = rs[0] * inv;
        float var = rss[0] * inv - mean * mean;
        float rstd = rsqrtf(var + 1e-5f);
        int b = bg >> 2, g = bg & 3;
        int c = g * 64 + tid;
        float sc = rstd * gnw[c];
        d_scale[b * C_ + c] = sc;
        d_shift[b * C_ + c] = gnb[c] - mean * sc;
    }
}

// ============================================================
// GN-folded qkv weight (fp16) + folded bias
// ============================================================
__global__ void build_wp(const float* __restrict__ W) {
    int o = blockIdx.x, b = blockIdx.y, c = threadIdx.x;
    float w = W[o * C_ + c];
    d_Wp[((long)b * 768 + o) * C_ + c] = __float2half_rn(w * d_scale[b * C_ + c]);
    __shared__ float red[256];
    red[c] = w * d_shift[b * C_ + c];
    __syncthreads();
    for (int st = 128; st > 0; st >>= 1) {
        if (c < st) red[c] += red[c + st];
        __syncthreads();
    }
    if (c == 0) d_biasp[b * 768 + o] = red[0];
}

// ============================================================
// fp16 GEMM via mma.sync. BK=64, 3-stage cp.async.cg pipeline.
// MODE 1 (k,v): A = Wp rows 256..767, M=512. mt 0-1 -> k (+stats), 2-3 -> v.
// MODE 2 (out): A = W3 (per-batch 256x256), + bias3 + residual.
// ============================================================
static constexpr int SKROW = 72;                     // 64 + 8 pad halves
static constexpr int TILE_BYTES = 128 * SKROW * 2;   // 18432
static constexpr int STAGE_BYTES = 2 * TILE_BYTES;   // 36864
static constexpr int NSTAGE = 3;
static constexpr int GEMM_SMEM = NSTAGE * STAGE_BYTES;   // 110592

__device__ __forceinline__ void load_stage(
    uint32_t sbase, const __half* A, const __half* Bm, int kt, int tid)
{
    int k0 = kt * 64;
    #pragma unroll
    for (int it = 0; it < 4; it++) {
        int i = tid + it * 256;
        int row = i >> 3, seg = i & 7;
        uint32_t doff = row * (SKROW * 2) + seg * 16;
        long goff = (long)row * 256 + k0 + seg * 8;
        CP16(sbase + doff,              A + goff);
        CP16(sbase + TILE_BYTES + doff, Bm + goff);
    }
}

template <int MODE>
__global__ void __launch_bounds__(256, 2) gemm_mma(
    const __half* __restrict__ Amat, const __half* __restrict__ Bmat,
    const float* __restrict__ bias, const float* __restrict__ resid,
    __half* __restrict__ outK, __half* __restrict__ outV,
    float* __restrict__ outO, int Mtotal)
{
    extern __shared__ char smem[];
    uint32_t sb = smem_u32(smem);
    int tid = threadIdx.x;
    int warp = tid >> 5, lane = tid & 31;
    int wm = (warp >> 2) * 64;
    int wn = (warp & 3) * 32;
    int mt = blockIdx.x, nt = blockIdx.y, b = blockIdx.z;

    const __half* A = Amat + (long)b * Mtotal * 256 + (long)mt * 128 * 256;
    const __half* Bm = Bmat + (long)b * N_ * 256 + (long)nt * 128 * 256;

    float acc[4][4][4];
    #pragma unroll
    for (int i = 0; i < 4; i++)
        #pragma unroll
        for (int j = 0; j < 4; j++)
            #pragma unroll
            for (int e = 0; e < 4; e++) acc[i][j][e] = 0.f;

    load_stage(sb + 0 * STAGE_BYTES, A, Bm, 0, tid); CP_COMMIT();
    load_stage(sb + 1 * STAGE_BYTES, A, Bm, 1, tid); CP_COMMIT();

    int quad = lane >> 3, qr = lane & 7;
    int a_row = wm + (quad & 1) * 8 + qr;
    int a_colb = (quad >> 1) * 16;
    int b_row = wn + ((lane >> 4) & 1) * 8 + (lane & 7);
    int b_colb = ((lane >> 3) & 1) * 16;

    #pragma unroll 1
    for (int kt = 0; kt < 4; kt++) {
        if (kt + 1 < 4) { asm volatile("cp.async.wait_group 1;"); }
        else            { asm volatile("cp.async.wait_group 0;"); }
        __syncthreads();
        if (kt + 2 < 4) {
            load_stage(sb + ((kt + 2) % 3) * STAGE_BYTES, A, Bm, kt + 2, tid);
            CP_COMMIT();
        }

        uint32_t base = sb + (kt % 3) * STAGE_BYTES;
        uint32_t aS = base, bS = base + TILE_BYTES;
        #pragma unroll
        for (int k16 = 0; k16 < 4; k16++) {
            uint32_t acol = a_colb + k16 * 32;
            uint32_t bcol = b_colb + k16 * 32;
            uint32_t ah[4][4], bh[4][2];
            #pragma unroll
            for (int mf = 0; mf < 4; mf++)
                ldm4(ah[mf], aS + (a_row + mf * 16) * (SKROW * 2) + acol);
            #pragma unroll
            for (int nfp = 0; nfp < 2; nfp++) {
                uint32_t r4[4];
                ldm4(r4, bS + (b_row + nfp * 16) * (SKROW * 2) + bcol);
                bh[nfp * 2 + 0][0] = r4[0]; bh[nfp * 2 + 0][1] = r4[1];
                bh[nfp * 2 + 1][0] = r4[2]; bh[nfp * 2 + 1][1] = r4[3];
            }
            #pragma unroll
            for (int mf = 0; mf < 4; mf++)
                #pragma unroll
                for (int nf = 0; nf < 4; nf++)
                    mma_f16(acc[mf][nf], ah[mf], bh[nf]);
        }
    }

    if (MODE == 1) {
        bool isK = (mt < 2);
        int c_base = isK ? mt * 128 : (mt - 2) * 128;
        __half* outH = isK ? outK : outV;
        float2* sms = (float2*)smem;    // [128][4]
        __syncthreads();
        #pragma unroll
        for (int mf = 0; mf < 4; mf++) {
            #pragma unroll
            for (int half = 0; half < 2; half++) {
                int r = wm + mf * 16 + half * 8 + (lane >> 2);
                float bv = bias[b * 768 + 256 + mt * 128 + r];
                __half* dst = outH + ((long)b * C_ + c_base + r) * N_ + (long)nt * 128;
                float vv[8];
                #pragma unroll
                for (int nf = 0; nf < 4; nf++) {
                    int n = wn + nf * 8 + 2 * (lane & 3);
                    __half h0 = __float2half_rn(acc[mf][nf][half * 2 + 0] + bv);
                    __half h1 = __float2half_rn(acc[mf][nf][half * 2 + 1] + bv);
                    *(__half2*)&dst[n] = __halves2half2(h0, h1);
                    vv[nf * 2 + 0] = __half2float(h0);
                    vv[nf * 2 + 1] = __half2float(h1);
                }
                if (isK) {
                    float m = vv[0];
                    #pragma unroll
                    for (int e = 1; e < 8; e++) m = fmaxf(m, vv[e]);
                    float s = 0.f;
                    #pragma unroll
                    for (int e = 0; e < 8; e++) s += __expf(vv[e] - m);
                    #pragma unroll
                    for (int dlt = 1; dlt <= 2; dlt <<= 1) {
                        float m2 = __shfl_xor_sync(0xffffffffu, m, dlt);
                        float s2 = __shfl_xor_sync(0xffffffffu, s, dlt);
                        float M = fmaxf(m, m2);
                        s = s * __expf(m - M) + s2 * __expf(m2 - M);
                        m = M;
                    }
                    if ((lane & 3) == 0) sms[r * 4 + (warp & 3)] = make_float2(m, s);
                }
            }
        }
        if (isK) {
            __syncthreads();
            if (tid < 128) {
                float2 p0 = sms[tid * 4 + 0], p1 = sms[tid * 4 + 1];
                float2 p2 = sms[tid * 4 + 2], p3 = sms[tid * 4 + 3];
                float M01 = fmaxf(p0.x, p1.x);
                float s01 = p0.y * __expf(p0.x - M01) + p1.y * __expf(p1.x - M01);
                float M23 = fmaxf(p2.x, p3.x);
                float s23 = p2.y * __expf(p2.x - M23) + p3.y * __expf(p3.x - M23);
                float M = fmaxf(M01, M23);
                float S = s01 * __expf(M01 - M) + s23 * __expf(M23 - M);
                d_kms[((long)b * C_ + c_base + tid) * 256 + nt] = make_float2(M, S);
            }
        }
        return;
    }

    // MODE 2 epilogue: fp32 out + per-batch bias3 + residual
    #pragma unroll
    for (int mf = 0; mf < 4; mf++) {
        #pragma unroll
        for (int half = 0; half < 2; half++) {
            int mrow = mt * 128 + wm + mf * 16 + half * 8 + (lane >> 2);
            float bv = bias[b * C_ + mrow];
            long base = ((long)b * C_ + mrow) * N_;
            float* dst = outO + base;
            const float* rp = resid + base;
            #pragma unroll
            for (int nf = 0; nf < 4; nf++) {
                int n = nt * 128 + wn + nf * 8 + 2 * (lane & 3);
                float2 rv = *(const float2*)&rp[n];
                float2 o;
                o.x = acc[mf][nf][half * 2 + 0] + bv + rv.x;
                o.y = acc[mf][nf][half * 2 + 1] + bv + rv.y;
                *(float2*)&dst[n] = o;
            }
        }
    }
}

// ============================================================
// reduce per-tile k stats -> d_m, d_s
// ============================================================
__global__ void krow_reduce() {
    int row = blockIdx.x, tid = threadIdx.x;
    __shared__ float sm[256], ssum[256];
    float2 p = d_kms[(long)row * 256 + tid];
    sm[tid] = p.x; ssum[tid] = p.y;
    __syncthreads();
    for (int st = 128; st > 0; st >>= 1) {
        if (tid < st) {
            float m1 = sm[tid], m2 = sm[tid + st];
            float M = fmaxf(m1, m2);
            ssum[tid] = ssum[tid] * __expf(m1 - M) + ssum[tid + st] * __expf(m2 - M);
            sm[tid] = M;
        }
        __syncthreads();
    }
    if (tid == 0) { d_m[row] = sm[0]; d_s[row] = ssum[0]; }
}

// ============================================================
// sim via HMMA: simpart[bh,sp] = exp(k-m) @ v^T over 1024 spatial cols.
// ============================================================
__global__ void __launch_bounds__(256) sim_hmma() {
    __shared__ __align__(16) char S[43520];
    __shared__ float ms[32];
    char* kraw0 = S;            // 2 x 8704
    char* vraw0 = S + 17408;    // 2 x 8704
    char* kx    = S + 34816;    // 8704
    int sp = blockIdx.x, bh = blockIdx.y;
    int b = bh >> 3, h = bh & 7;
    const __half* kp = d_kh + ((long)b * C_ + h * 32) * N_;
    const __half* vp = d_vh + ((long)b * C_ + h * 32) * N_;
    int tid = threadIdx.x, lane = tid & 31, w = tid >> 5;
    if (tid < 32) ms[tid] = d_m[b * C_ + h * 32 + tid];

    float acc[2][4][4];
    #pragma unroll
    for (int i = 0; i < 2; i++)
        #pragma unroll
        for (int j = 0; j < 4; j++)
            #pragma unroll
            for (int e = 0; e < 4; e++) acc[i][j][e] = 0.f;

    int quad = lane >> 3, qr = lane & 7;
    int a_row = (quad & 1) * 8 + qr;
    int a_cb = (quad >> 1) * 16;
    int b_row = ((lane >> 4) & 1) * 8 + (lane & 7);
    int b_cb = ((lane >> 3) & 1) * 16;
    int nbeg = sp * 1024;

    auto load = [&](int st) {
        int buf = st & 1;
        uint32_t kb = smem_u32(kraw0 + buf * 8704);
        uint32_t vb = smem_u32(vraw0 + buf * 8704);
        int n0 = nbeg + st * 128;
        #pragma unroll
        for (int it = 0; it < 2; it++) {
            int idx = tid + it * 256;
            int row = idx >> 4, seg = idx & 15;
            long g = (long)row * N_ + n0 + seg * 8;
            CP16(kb + row * 272 + seg * 16, kp + g);
            CP16(vb + row * 272 + seg * 16, vp + g);
        }
        CP_COMMIT();
    };

    load(0);
    #pragma unroll 1
    for (int st = 0; st < 8; st++) {
        if (st + 1 < 8) { load(st + 1); asm volatile("cp.async.wait_group 1;"); }
        else            { asm volatile("cp.async.wait_group 0;"); }
        __syncthreads();
        {
            char* kbuf = kraw0 + (st & 1) * 8704;
            #pragma unroll
            for (int rr = 0; rr < 4; rr++) {
                int row = w * 4 + rr;
                float mr = ms[row];
                const __half2* src = (const __half2*)(kbuf + row * 272);
                __half2* dst = (__half2*)(kx + row * 272);
                #pragma unroll
                for (int j = 0; j < 2; j++) {
                    int ci = lane + j * 32;
                    float2 f = __half22float2(src[ci]);
                    f.x = __expf(f.x - mr);
                    f.y = __expf(f.y - mr);
                    dst[ci] = __float22half2_rn(f);
                }
            }
        }
        __syncthreads();
        {
            uint32_t kxu = smem_u32(kx);
            uint32_t vbu = smem_u32(vraw0 + (st & 1) * 8704);
            uint32_t colb = w * 32;
            uint32_t af[2][4], bf[4][2];
            #pragma unroll
            for (int mf = 0; mf < 2; mf++)
                ldm4(af[mf], kxu + (a_row + mf * 16) * 272 + colb + a_cb);
            #pragma unroll
            for (int nfp = 0; nfp < 2; nfp++) {
                uint32_t r4[4];
                ldm4(r4, vbu + (b_row + nfp * 16) * 272 + colb + b_cb);
                bf[nfp * 2 + 0][0] = r4[0]; bf[nfp * 2 + 0][1] = r4[1];
                bf[nfp * 2 + 1][0] = r4[2]; bf[nfp * 2 + 1][1] = r4[3];
            }
            #pragma unroll
            for (int mf = 0; mf < 2; mf++)
                #pragma unroll
                for (int nf = 0; nf < 4; nf++)
                    mma_f16(acc[mf][nf], af[mf], bf[nf]);
        }
        __syncthreads();
    }

    float* red = (float*)S;
    float* my = red + w * 1024;
    #pragma unroll
    for (int mf = 0; mf < 2; mf++) {
        int r = mf * 16 + (lane >> 2);
        #pragma unroll
        for (int nf = 0; nf < 4; nf++) {
            int c = nf * 8 + 2 * (lane & 3);
            my[r * 32 + c]           = acc[mf][nf][0];
            my[r * 32 + c + 1]       = acc[mf][nf][1];
            my[(r + 8) * 32 + c]     = acc[mf][nf][2];
            my[(r + 8) * 32 + c + 1] = acc[mf][nf][3];
        }
    }
    __syncthreads();
    float* out = d_simpart + ((long)(bh * SIMS + sp)) * 1024;
    for (int i = tid; i < 1024; i += 256) {
        float s = 0.f;
        #pragma unroll
        for (int ww = 0; ww < 8; ww++) s += red[ww * 1024 + i];
        out[i] = s;
    }
}

// reduce splits + divide by softmax denominator
__global__ void sim_reduce() {
    int bh = blockIdx.x, i = threadIdx.x;
    int b = bh >> 3, h = bh & 7;
    float s = 0.f;
    #pragma unroll
    for (int sp = 0; sp < SIMS; sp++)
        s += d_simpart[(long)(bh * SIMS + sp) * 1024 + i];
    float inv = 1.0f / d_s[b * C_ + h * 32 + (i >> 5)];
    d_sim[bh * 1024 + i] = s * inv;
}

// ============================================================
// W2f[b,o,h*32+d] = sum_e OW[o,h*32+e]*sim[b,h,d,e]  (fp32)
// ============================================================
__global__ void build_w2(const float* __restrict__ OW) {
    int o = blockIdx.x, b = blockIdx.y, cp = threadIdx.x;
    int h = cp >> 5, d = cp & 31;
    const float* simp = d_sim + ((long)((b * 8 + h) * 32 + d)) * 32;
    const float* owp = OW + o * C_ + h * 32;
    float s = 0.f;
    #pragma unroll
    for (int e = 0; e < 32; e++) s += owp[e] * simp[e];
    d_W2f[((long)b * C_ + o) * C_ + cp] = s;
}

// ============================================================
// W3[b] = W2f[b] @ Wq'[b] (fp16 out), bias3[b] = ob + W2f[b] @ bq'
// ============================================================
__global__ void build_w3(const float* __restrict__ ob) {
    int o = blockIdx.x, b = blockIdx.y, c = threadIdx.x;
    __shared__ float w2row[256];
    __shared__ float red[256];
    const float* w2p = d_W2f + ((long)b * C_ + o) * C_;
    w2row[c] = w2p[c];
    red[c] = w2row[c] * d_biasp[b * 768 + c];
    __syncthreads();
    float acc = 0.f;
    const __half* wq = d_Wp + (long)b * 768 * C_;
    #pragma unroll 8
    for (int e = 0; e < 256; e++)
        acc += w2row[e] * __half2float(wq[(long)e * C_ + c]);
    d_W3[((long)b * C_ + o) * C_ + c] = __float2half_rn(acc);
    for (int st = 128; st > 0; st >>= 1) {
        if (c < st) red[c] += red[c + st];
        __syncthreads();
    }
    if (c == 0) d_bias3[b * C_ + o] = ob[o] + red[0];
}

// ============================================================
// host launch
// ============================================================
extern "C" void kernel_launch(void* const* d_in, const int* in_sizes, int n_in,
                              void* d_out, int out_size) {
    const float* x    = (const float*)d_in[0];
    const float* gnw  = (const float*)d_in[1];
    const float* gnb  = (const float*)d_in[2];
    const float* qkvW = (const float*)d_in[3];
    const float* ow   = (const float*)d_in[4];
    const float* ob   = (const float*)d_in[5];
    float* out = (float*)d_out;

    float *pBiasp, *pBias3;
    __half *pKh, *pVh, *pXT, *pWp, *pW3;
    cudaGetSymbolAddress((void**)&pKh, d_kh);
    cudaGetSymbolAddress((void**)&pVh, d_vh);
    cudaGetSymbolAddress((void**)&pBiasp, d_biasp);
    cudaGetSymbolAddress((void**)&pBias3, d_bias3);
    cudaGetSymbolAddress((void**)&pXT, d_xT);
    cudaGetSymbolAddress((void**)&pWp, d_Wp);
    cudaGetSymbolAddress((void**)&pW3, d_W3);

    cudaFuncSetAttribute(gemm_mma<1>, cudaFuncAttributeMaxDynamicSharedMemorySize, GEMM_SMEM);
    cudaFuncSetAttribute(gemm_mma<2>, cudaFuncAttributeMaxDynamicSharedMemorySize, GEMM_SMEM);

    tconv_stats<<<dim3(1024, 4, 4), dim3(32, 8)>>>(x, pXT);
    gn_stats2<<<16, 256>>>(gnw, gnb);
    build_wp<<<dim3(768, 4), 256>>>(qkvW);

    // k,v GEMM: A = Wp rows 256..767 (M=512). k -> stats, v plain.
    gemm_mma<1><<<dim3(4, 256, 4), 256, GEMM_SMEM>>>(pWp + (long)256 * C_, pXT,
                                                     pBiasp, nullptr, pKh, pVh, nullptr, 768);

    krow_reduce<<<1024, 256>>>();
    sim_hmma<<<dim3(SIMS, 32), 256>>>();
    sim_reduce<<<32, 1024>>>();
    build_w2<<<dim3(256, 4), 256>>>(ow);
    build_w3<<<dim3(256, 4), 256>>>(ob);

    // out = W3 @ xT^T + bias3 + x
    gemm_mma<2><<<dim3(2, 256, 4), 256, GEMM_SMEM>>>(pW3, pXT,
                                                     pBias3, x, nullptr, nullptr, out, 256);
}